// round 6
// baseline (speedup 1.0000x reference)
#include <cuda_runtime.h>
#include <cuda_bf16.h>
#include <math.h>
#include <stdint.h>

// ---------------- problem constants ----------------
#define S_LEN   2048
#define BATCH   2
#define T_TOK   (BATCH * S_LEN)
#define HIDDEN  2048
#define QLORA   1536
#define KVLORA  512
#define NHEADS  16
#define NOPE    128
#define ROPE_D  64
#define QHD     192
#define VHD     128
#define KVW     576

typedef __nv_bfloat16 bf16;
typedef __nv_bfloat162 bf162;

// ---------------- scratch ----------------
__device__ float g_qa [T_TOK * QLORA];
__device__ float g_ckv[T_TOK * KVW];

__device__ bf16 g_Xh[T_TOK * HIDDEN],       g_Xl[T_TOK * HIDDEN];
__device__ bf16 g_wqa_h[QLORA * HIDDEN],    g_wqa_l[QLORA * HIDDEN];
__device__ bf16 g_wqb_h[NHEADS*QHD*QLORA],  g_wqb_l[NHEADS*QHD*QLORA];
__device__ bf16 g_wkva_h[KVW * HIDDEN],     g_wkva_l[KVW * HIDDEN];
__device__ bf16 g_wkvb_h[NHEADS*256*KVLORA],g_wkvb_l[NHEADS*256*KVLORA];
__device__ bf16 g_wo_h[HIDDEN*NHEADS*VHD],  g_wo_l[HIDDEN*NHEADS*VHD];
__device__ bf16 g_qan_h[T_TOK * QLORA],     g_qan_l[T_TOK * QLORA];
__device__ bf16 g_ckvn_h[T_TOK * KVLORA],   g_ckvn_l[T_TOK * KVLORA];
__device__ bf16 g_qh[T_TOK * NHEADS * QHD], g_ql[T_TOK * NHEADS * QHD];
__device__ bf16 g_kvh[T_TOK * NHEADS * 256],g_kvl[T_TOK * NHEADS * 256];
__device__ bf16 g_kpeh[T_TOK * ROPE_D],     g_kpel[T_TOK * ROPE_D];
__device__ bf16 g_ctxh[T_TOK * NHEADS*VHD], g_ctxl[T_TOK * NHEADS*VHD];

// ---------------- common helpers ----------------
__device__ __forceinline__ uint32_t smem_u32(const void* p) {
    uint32_t a;
    asm("{ .reg .u64 t; cvta.to.shared.u64 t, %1; cvt.u32.u64 %0, t; }" : "=r"(a) : "l"(p));
    return a;
}
__device__ __forceinline__ void ldm4(uint32_t* r, uint32_t addr) {
    asm volatile("ldmatrix.sync.aligned.m8n8.x4.shared.b16 {%0,%1,%2,%3}, [%4];"
                 : "=r"(r[0]), "=r"(r[1]), "=r"(r[2]), "=r"(r[3]) : "r"(addr));
}
__device__ __forceinline__ void ldm4t(uint32_t* r, uint32_t addr) {
    asm volatile("ldmatrix.sync.aligned.m8n8.x4.trans.shared.b16 {%0,%1,%2,%3}, [%4];"
                 : "=r"(r[0]), "=r"(r[1]), "=r"(r[2]), "=r"(r[3]) : "r"(addr));
}
__device__ __forceinline__ void mma16816(float* d, const uint32_t* a, const uint32_t* b) {
    asm volatile("mma.sync.aligned.m16n8k16.row.col.f32.bf16.bf16.f32 "
                 "{%0,%1,%2,%3}, {%4,%5,%6,%7}, {%8,%9}, {%0,%1,%2,%3};"
                 : "+f"(d[0]), "+f"(d[1]), "+f"(d[2]), "+f"(d[3])
                 : "r"(a[0]), "r"(a[1]), "r"(a[2]), "r"(a[3]), "r"(b[0]), "r"(b[1]));
}
__device__ __forceinline__ void cpa16(uint32_t dst, const void* src, uint32_t sz) {
    asm volatile("cp.async.cg.shared.global [%0], [%1], 16, %2;"
                 :: "r"(dst), "l"(src), "r"(sz) : "memory");
}
__device__ __forceinline__ void split1(float v, bf16& h, bf16& l) {
    h = __float2bfloat16_rn(v);
    l = __float2bfloat16_rn(v - __bfloat162float(h));
}

// ---------------- convert fp32 -> (hi, lo) bf16 ----------------
__global__ void cvt_kernel(const float* __restrict__ x, bf16* __restrict__ h,
                           bf16* __restrict__ l, int n4) {
    int i = blockIdx.x * blockDim.x + threadIdx.x;
    if (i >= n4) return;
    float4 v = ((const float4*)x)[i];
    bf16 h0,h1,h2,h3,l0,l1,l2,l3;
    split1(v.x,h0,l0); split1(v.y,h1,l1); split1(v.z,h2,l2); split1(v.w,h3,l3);
    bf162 hp0, hp1, lp0, lp1;
    hp0.x=h0; hp0.y=h1; hp1.x=h2; hp1.y=h3;
    lp0.x=l0; lp0.y=l1; lp1.x=l2; lp1.y=l3;
    uint2 hh, ll;
    hh.x=*(uint32_t*)&hp0; hh.y=*(uint32_t*)&hp1;
    ll.x=*(uint32_t*)&lp0; ll.y=*(uint32_t*)&lp1;
    ((uint2*)h)[i] = hh;
    ((uint2*)l)[i] = ll;
}

// ============================================================================
// bf16 split GEMM (128x128 CTA, 2 CTAs/SM) — for wq_a / wkv_a.
// ============================================================================
#define SMSTR 48
#define TILEB (128 * SMSTR)
#define STAGEB (4 * TILEB)
#define NSTAGE 4
#define GEMM_SMEM (NSTAGE * STAGEB)

__global__ __launch_bounds__(256, 2) void bf_gemm(
    const bf16* __restrict__ Ah, const bf16* __restrict__ Al,
    const bf16* __restrict__ Bh, const bf16* __restrict__ Bl,
    float* __restrict__ C, bf16* __restrict__ Ch, bf16* __restrict__ Cl,
    int M, int N, int K)
{
    extern __shared__ char sm[];
    const int tid = threadIdx.x;
    const int wid = tid >> 5;
    const int lane = tid & 31;
    const int m0 = blockIdx.y * 128;
    const int n0 = blockIdx.x * 128;
    const int nvalid = (N - n0 < 128) ? (N - n0) : 128;

    const uint32_t sbase = smem_u32(sm);
    const int wr = wid >> 2, wc = wid & 3;
    const uint32_t a_row = wr * 64 + (lane & 15);
    const uint32_t a_colb = (lane >> 4) * 16;
    const uint32_t b_row = wc * 32 + (lane & 7) + ((lane >> 4) << 3);
    const uint32_t b_colb = ((lane >> 3) & 1) * 16;

    float acc[4][4][4];
#pragma unroll
    for (int i = 0; i < 4; ++i)
#pragma unroll
        for (int j = 0; j < 4; ++j)
#pragma unroll
            for (int e = 0; e < 4; ++e) acc[i][j][e] = 0.f;

    const int nch = K >> 4;

    auto issue_chunk = [&](int c) {
        const int k0 = c << 4;
        const uint32_t stb = sbase + (c & (NSTAGE - 1)) * STAGEB;
#pragma unroll
        for (int i = 0; i < 4; ++i) {
            int u = tid + i * 256;
            int tile = u >> 8;
            int row = (u & 255) >> 1;
            int c16 = u & 1;
            uint32_t dst = stb + tile * TILEB + row * SMSTR + c16 * 16;
            const bf16* src;
            uint32_t sz = 16;
            if (tile == 0)      src = Ah + (size_t)(m0 + row) * K + k0 + c16 * 8;
            else if (tile == 1) src = Al + (size_t)(m0 + row) * K + k0 + c16 * 8;
            else {
                const bf16* base = (tile == 2) ? Bh : Bl;
                src = base + (size_t)(n0 + row) * K + k0 + c16 * 8;
                if (row >= nvalid) sz = 0;
            }
            cpa16(dst, src, sz);
        }
        asm volatile("cp.async.commit_group;" ::: "memory");
    };

    issue_chunk(0);
    if (nch > 1) issue_chunk(1); else asm volatile("cp.async.commit_group;" ::: "memory");
    if (nch > 2) issue_chunk(2); else asm volatile("cp.async.commit_group;" ::: "memory");

    for (int c = 0; c < nch; ++c) {
        asm volatile("cp.async.wait_group 2;" ::: "memory");
        __syncthreads();
        if (c + 3 < nch) issue_chunk(c + 3);
        else asm volatile("cp.async.commit_group;" ::: "memory");

        const uint32_t stb = sbase + (c & (NSTAGE - 1)) * STAGEB;
        uint32_t ah[4][4], bh[2][4];
#pragma unroll
        for (int i = 0; i < 4; ++i)
            ldm4(ah[i], stb + (a_row + i * 16) * SMSTR + a_colb);
#pragma unroll
        for (int jp = 0; jp < 2; ++jp)
            ldm4(bh[jp], stb + 2 * TILEB + (b_row + jp * 16) * SMSTR + b_colb);
#pragma unroll
        for (int i = 0; i < 4; ++i)
#pragma unroll
            for (int j = 0; j < 4; ++j)
                mma16816(acc[i][j], ah[i], &bh[j >> 1][(j & 1) * 2]);
        {
            uint32_t al[4][4];
#pragma unroll
            for (int i = 0; i < 4; ++i)
                ldm4(al[i], stb + TILEB + (a_row + i * 16) * SMSTR + a_colb);
#pragma unroll
            for (int i = 0; i < 4; ++i)
#pragma unroll
                for (int j = 0; j < 4; ++j)
                    mma16816(acc[i][j], al[i], &bh[j >> 1][(j & 1) * 2]);
        }
        {
            uint32_t bl[2][4];
#pragma unroll
            for (int jp = 0; jp < 2; ++jp)
                ldm4(bl[jp], stb + 3 * TILEB + (b_row + jp * 16) * SMSTR + b_colb);
#pragma unroll
            for (int i = 0; i < 4; ++i)
#pragma unroll
                for (int j = 0; j < 4; ++j)
                    mma16816(acc[i][j], ah[i], &bl[j >> 1][(j & 1) * 2]);
        }
    }

    const int gid = lane >> 2, tig = lane & 3;
#pragma unroll
    for (int i = 0; i < 4; ++i) {
#pragma unroll
        for (int rr = 0; rr < 2; ++rr) {
            int row = m0 + wr * 64 + i * 16 + gid + rr * 8;
#pragma unroll
            for (int j = 0; j < 4; ++j) {
                int col = n0 + wc * 32 + j * 8 + tig * 2;
                if (col < N) {
                    float v0 = acc[i][j][rr * 2], v1 = acc[i][j][rr * 2 + 1];
                    if (C) *(float2*)(C + (size_t)row * N + col) = make_float2(v0, v1);
                    if (Ch) {
                        bf162 hp, lp;
                        bf16 h0,l0,h1,l1;
                        split1(v0,h0,l0); split1(v1,h1,l1);
                        hp.x=h0; hp.y=h1; lp.x=l0; lp.y=l1;
                        *(uint32_t*)(Ch + (size_t)row * N + col) = *(uint32_t*)&hp;
                        *(uint32_t*)(Cl + (size_t)row * N + col) = *(uint32_t*)&lp;
                    }
                }
            }
        }
    }
}

// ============================================================================
// bf16 split GEMM BIG: 256x128 CTA tile, 8 warps (64x64 each), 1 CTA/SM.
// Requires M%256==0, N%128==0, K%16==0 (true for wq_b, wkv_b, wo).
// ============================================================================
#define BG_TILEA (256 * SMSTR)               // 12288
#define BG_TILEB (128 * SMSTR)               // 6144
#define BG_STAGE (2 * BG_TILEA + 2 * BG_TILEB)  // 36864
#define BG_NSTG 4
#define BG_SMEM (BG_NSTG * BG_STAGE)         // 147456

__global__ __launch_bounds__(256) void bf_gemm_big(
    const bf16* __restrict__ Ah, const bf16* __restrict__ Al,
    const bf16* __restrict__ Bh, const bf16* __restrict__ Bl,
    float* __restrict__ C, bf16* __restrict__ Ch, bf16* __restrict__ Cl,
    int M, int N, int K)
{
    extern __shared__ char sm[];
    const int tid = threadIdx.x;
    const int wid = tid >> 5;
    const int lane = tid & 31;
    const int m0 = blockIdx.y * 256;
    const int n0 = blockIdx.x * 128;

    const uint32_t sbase = smem_u32(sm);
    const int wr = wid >> 1, wc = wid & 1;                  // 4x2 warps
    const uint32_t a_row = wr * 64 + (lane & 15);
    const uint32_t a_colb = (lane >> 4) * 16;
    const uint32_t b_row = wc * 64 + (lane & 7) + ((lane >> 4) << 3);
    const uint32_t b_colb = ((lane >> 3) & 1) * 16;

    float acc[4][8][4];
#pragma unroll
    for (int i = 0; i < 4; ++i)
#pragma unroll
        for (int j = 0; j < 8; ++j)
#pragma unroll
            for (int e = 0; e < 4; ++e) acc[i][j][e] = 0.f;

    const int nch = K >> 4;

    // copy: 1536 16B units per chunk, 6 per thread
    auto issue_chunk = [&](int c) {
        const int k0 = c << 4;
        const uint32_t stb = sbase + (c & (BG_NSTG - 1)) * BG_STAGE;
#pragma unroll
        for (int i = 0; i < 6; ++i) {
            int u = tid + i * 256;
            uint32_t dst;
            const bf16* src;
            if (u < 1024) {               // A: h then l, 256 rows x 2 c16
                int part = u >> 9;        // 0=h, 1=l
                int row = (u & 511) >> 1;
                int c16 = u & 1;
                dst = stb + part * BG_TILEA + row * SMSTR + c16 * 16;
                src = (part ? Al : Ah) + (size_t)(m0 + row) * K + k0 + c16 * 8;
            } else {                      // B
                int v = u - 1024;
                int part = v >> 8;
                int row = (v & 255) >> 1;
                int c16 = v & 1;
                dst = stb + 2 * BG_TILEA + part * BG_TILEB + row * SMSTR + c16 * 16;
                src = (part ? Bl : Bh) + (size_t)(n0 + row) * K + k0 + c16 * 8;
            }
            cpa16(dst, src, 16);
        }
        asm volatile("cp.async.commit_group;" ::: "memory");
    };

    issue_chunk(0);
    if (nch > 1) issue_chunk(1); else asm volatile("cp.async.commit_group;" ::: "memory");
    if (nch > 2) issue_chunk(2); else asm volatile("cp.async.commit_group;" ::: "memory");

    for (int c = 0; c < nch; ++c) {
        asm volatile("cp.async.wait_group 2;" ::: "memory");
        __syncthreads();
        if (c + 3 < nch) issue_chunk(c + 3);
        else asm volatile("cp.async.commit_group;" ::: "memory");

        const uint32_t stb = sbase + (c & (BG_NSTG - 1)) * BG_STAGE;
        uint32_t ah[4][4], bh[4][4];
#pragma unroll
        for (int i = 0; i < 4; ++i)
            ldm4(ah[i], stb + (a_row + i * 16) * SMSTR + a_colb);
#pragma unroll
        for (int jp = 0; jp < 4; ++jp)
            ldm4(bh[jp], stb + 2 * BG_TILEA + (b_row + jp * 16) * SMSTR + b_colb);
#pragma unroll
        for (int i = 0; i < 4; ++i)
#pragma unroll
            for (int j = 0; j < 8; ++j)
                mma16816(acc[i][j], ah[i], &bh[j >> 1][(j & 1) * 2]);
        {
            uint32_t al[4][4];
#pragma unroll
            for (int i = 0; i < 4; ++i)
                ldm4(al[i], stb + BG_TILEA + (a_row + i * 16) * SMSTR + a_colb);
#pragma unroll
            for (int i = 0; i < 4; ++i)
#pragma unroll
                for (int j = 0; j < 8; ++j)
                    mma16816(acc[i][j], al[i], &bh[j >> 1][(j & 1) * 2]);
        }
        {
            uint32_t bl[4][4];
#pragma unroll
            for (int jp = 0; jp < 4; ++jp)
                ldm4(bl[jp], stb + 2 * BG_TILEA + BG_TILEB + (b_row + jp * 16) * SMSTR + b_colb);
#pragma unroll
            for (int i = 0; i < 4; ++i)
#pragma unroll
                for (int j = 0; j < 8; ++j)
                    mma16816(acc[i][j], ah[i], &bl[j >> 1][(j & 1) * 2]);
        }
    }

    const int gid = lane >> 2, tig = lane & 3;
#pragma unroll
    for (int i = 0; i < 4; ++i) {
#pragma unroll
        for (int rr = 0; rr < 2; ++rr) {
            int row = m0 + wr * 64 + i * 16 + gid + rr * 8;
#pragma unroll
            for (int j = 0; j < 8; ++j) {
                int col = n0 + wc * 64 + j * 8 + tig * 2;
                float v0 = acc[i][j][rr * 2], v1 = acc[i][j][rr * 2 + 1];
                if (C) *(float2*)(C + (size_t)row * N + col) = make_float2(v0, v1);
                if (Ch) {
                    bf162 hp, lp;
                    bf16 h0,l0,h1,l1;
                    split1(v0,h0,l0); split1(v1,h1,l1);
                    hp.x=h0; hp.y=h1; lp.x=l0; lp.y=l1;
                    *(uint32_t*)(Ch + (size_t)row * N + col) = *(uint32_t*)&hp;
                    *(uint32_t*)(Cl + (size_t)row * N + col) = *(uint32_t*)&lp;
                }
            }
        }
    }
}

// ---------------- RMSNorm -> bf16 hi/lo ----------------
__global__ void rmsnorm_kernel(const float* __restrict__ x, const float* __restrict__ w,
                               bf16* __restrict__ yh, bf16* __restrict__ yl,
                               int D, int in_stride) {
    const int row = blockIdx.x;
    const float* xr = x + (size_t)row * in_stride;
    float ss = 0.f;
    for (int d = threadIdx.x; d < D; d += blockDim.x) { float v = xr[d]; ss += v * v; }
    __shared__ float red[32];
#pragma unroll
    for (int o = 16; o; o >>= 1) ss += __shfl_xor_sync(0xffffffffu, ss, o);
    if ((threadIdx.x & 31) == 0) red[threadIdx.x >> 5] = ss;
    __syncthreads();
    if (threadIdx.x < 32) {
        float v = (threadIdx.x < (blockDim.x >> 5)) ? red[threadIdx.x] : 0.f;
#pragma unroll
        for (int o = 16; o; o >>= 1) v += __shfl_xor_sync(0xffffffffu, v, o);
        if (threadIdx.x == 0) red[0] = v;
    }
    __syncthreads();
    float scale = rsqrtf(red[0] / (float)D + 1e-6f);
    for (int d = threadIdx.x; d < D; d += blockDim.x) {
        float v = w[d] * xr[d] * scale;
        bf16 h, l; split1(v, h, l);
        yh[(size_t)row * D + d] = h;
        yl[(size_t)row * D + d] = l;
    }
}

// ---------------- YaRN ----------------
__device__ __forceinline__ void yarn_cs(int pos, int j, float& c, float& s) {
    float ex   = __expf(-(float)(2 * j) * (9.210340371976184f / 64.f));
    float fi   = ex * 0.025f;
    float ramp = ((float)j - 10.f) * (1.f / 13.f);
    ramp = fminf(fmaxf(ramp, 0.f), 1.f);
    float invf = fi * ramp + ex * (1.f - ramp);
    float ang  = (float)pos * invf;
    c = cosf(ang); s = sinf(ang);
}

__global__ void rope_k_kernel(const float* __restrict__ ckv, const int* __restrict__ pos_ids,
                              bf16* __restrict__ kh, bf16* __restrict__ kl) {
    const int t = blockIdx.x;
    const int j = threadIdx.x;
    const int pos = pos_ids[t];
    const float* x = ckv + (size_t)t * KVW + KVLORA;
    float c, s; yarn_cs(pos, j, c, s);
    float x0 = x[2 * j], x1 = x[2 * j + 1];
    float r0 = x0 * c - x1 * s, r1 = x1 * c + x0 * s;
    bf16 h, l;
    split1(r0, h, l); kh[t * ROPE_D + j] = h;      kl[t * ROPE_D + j] = l;
    split1(r1, h, l); kh[t * ROPE_D + 32 + j] = h; kl[t * ROPE_D + 32 + j] = l;
}

__global__ void rope_q_kernel(bf16* __restrict__ qh, bf16* __restrict__ ql,
                              const int* __restrict__ pos_ids) {
    const int t = blockIdx.x >> 4;
    const int h = blockIdx.x & 15;
    const int j = threadIdx.x;
    const int pos = pos_ids[t];
    bf16* xh = qh + (size_t)t * (NHEADS * QHD) + h * QHD + NOPE;
    bf16* xl = ql + (size_t)t * (NHEADS * QHD) + h * QHD + NOPE;
    float c, s; yarn_cs(pos, j, c, s);
    float x0 = __bfloat162float(xh[2*j])   + __bfloat162float(xl[2*j]);
    float x1 = __bfloat162float(xh[2*j+1]) + __bfloat162float(xl[2*j+1]);
    float r0 = x0 * c - x1 * s, r1 = x1 * c + x0 * s;
    __syncwarp();
    bf16 hh, ll;
    split1(r0, hh, ll); xh[j] = hh;      xl[j] = ll;
    split1(r1, hh, ll); xh[32 + j] = hh; xl[32 + j] = ll;
}

// ============================================================================
// Flash attention, split-bf16 HMMA. BM=128, BN=64, 8 warps.
// ============================================================================
#define FL_KSTR 400
#define FL_VSTR 272
#define FL_PSTR 144
#define FL_KVSTG (64 * FL_KSTR * 2 + 64 * FL_VSTR * 2)
#define FL_VOFF  (64 * FL_KSTR * 2)
#define FL_PH  (2 * FL_KVSTG)
#define FL_PL  (FL_PH + 128 * FL_PSTR)
#define FL_SMEM (FL_PL + 128 * FL_PSTR)
#define FL_QSTR 400

__global__ __launch_bounds__(256, 1) void flash_mma(
    const bf16* __restrict__ qh, const bf16* __restrict__ ql,
    const bf16* __restrict__ kvh, const bf16* __restrict__ kvl,
    const bf16* __restrict__ kpeh, const bf16* __restrict__ kpel,
    bf16* __restrict__ ctxh, bf16* __restrict__ ctxl)
{
    extern __shared__ char sm[];
    const uint32_t sb = smem_u32(sm);
    const int qt = (int)gridDim.x - 1 - (int)blockIdx.x;
    const int hh = blockIdx.y, b = blockIdx.z;
    const int tid = threadIdx.x, wid = tid >> 5, lane = tid & 31;
    const int gid = lane >> 2, tig = lane & 3;
    const int t0 = b * S_LEN;

    const uint32_t a_row = wid * 16 + (lane & 15);
    const uint32_t a_colb = (lane >> 4) * 16;
    const uint32_t k_roff = (lane & 7) + ((lane >> 4) << 3);
    const uint32_t k_colb = ((lane >> 3) & 1) * 16;
    const uint32_t v_koff = (lane & 7) + ((lane >> 3) & 1) * 8;
    const uint32_t v_noff = (lane >> 4) * 8;

    for (int idx = tid; idx < 128 * 24; idx += 256) {
        int r = idx / 24, u = idx % 24;
        size_t g = (size_t)(t0 + qt * 128 + r) * (NHEADS * QHD) + hh * QHD + u * 8;
        *(uint4*)(sm + r * FL_QSTR + u * 16) = *(const uint4*)(qh + g);
        *(uint4*)(sm + 51200 + r * FL_QSTR + u * 16) = *(const uint4*)(ql + g);
    }
    __syncthreads();
    uint32_t qfh[12][4], qfl[12][4];
#pragma unroll
    for (int ks = 0; ks < 12; ++ks) {
        ldm4(qfh[ks], sb + a_row * FL_QSTR + a_colb + ks * 32);
        ldm4(qfl[ks], sb + 51200 + a_row * FL_QSTR + a_colb + ks * 32);
    }
    __syncthreads();

    auto issue_kv = [&](int kt) {
        const uint32_t stb = sb + (kt & 1) * FL_KVSTG;
        for (int idx = tid; idx < 64 * 24; idx += 256) {
            int r = idx / 24, u = idx % 24;
            int t = t0 + kt * 64 + r;
            const bf16 *srch, *srcl;
            if (u < 16) {
                size_t g = (size_t)t * (NHEADS * 256) + hh * 256 + u * 8;
                srch = kvh + g; srcl = kvl + g;
            } else {
                size_t g = (size_t)t * ROPE_D + (u - 16) * 8;
                srch = kpeh + g; srcl = kpel + g;
            }
            uint32_t off = r * FL_KSTR + u * 16;
            cpa16(stb + off, srch, 16);
            cpa16(stb + 64 * FL_KSTR + off, srcl, 16);
        }
        for (int idx = tid; idx < 64 * 16; idx += 256) {
            int r = idx >> 4, u = idx & 15;
            size_t g = (size_t)(t0 + kt * 64 + r) * (NHEADS * 256) + hh * 256 + 128 + u * 8;
            uint32_t off = FL_VOFF + r * FL_VSTR + u * 16;
            cpa16(stb + off, kvh + g, 16);
            cpa16(stb + 64 * FL_VSTR + off, kvl + g, 16);
        }
        asm volatile("cp.async.commit_group;" ::: "memory");
    };

    float m_i[2], l_i[2], O[16][4];
    m_i[0] = m_i[1] = -1e30f; l_i[0] = l_i[1] = 0.f;
#pragma unroll
    for (int nf = 0; nf < 16; ++nf)
#pragma unroll
        for (int e = 0; e < 4; ++e) O[nf][e] = 0.f;

    const float mm = 0.1f * logf(40.f) + 1.f;
    const float sc = mm * mm * rsqrtf(192.f);

    const int nkt = 2 * qt + 2;
    issue_kv(0);

    for (int kt = 0; kt < nkt; ++kt) {
        if (kt + 1 < nkt) {
            issue_kv(kt + 1);
            asm volatile("cp.async.wait_group 1;" ::: "memory");
        } else {
            asm volatile("cp.async.wait_group 0;" ::: "memory");
        }
        __syncthreads();
        const uint32_t stb = sb + (kt & 1) * FL_KVSTG;

        float s[8][4];
#pragma unroll
        for (int nf = 0; nf < 8; ++nf)
#pragma unroll
            for (int e = 0; e < 4; ++e) s[nf][e] = 0.f;

#pragma unroll
        for (int ks = 0; ks < 12; ++ks) {
#pragma unroll
            for (int jb = 0; jb < 4; ++jb) {
                uint32_t bh4[4], bl4[4];
                uint32_t brow = jb * 16 + k_roff;
                ldm4(bh4, stb + brow * FL_KSTR + k_colb + ks * 32);
                mma16816(s[2*jb],   qfh[ks], &bh4[0]);
                mma16816(s[2*jb+1], qfh[ks], &bh4[2]);
                mma16816(s[2*jb],   qfl[ks], &bh4[0]);
                mma16816(s[2*jb+1], qfl[ks], &bh4[2]);
                ldm4(bl4, stb + 64 * FL_KSTR + brow * FL_KSTR + k_colb + ks * 32);
                mma16816(s[2*jb],   qfh[ks], &bl4[0]);
                mma16816(s[2*jb+1], qfh[ks], &bl4[2]);
            }
        }

#pragma unroll
        for (int rr = 0; rr < 2; ++rr) {
            int grow = qt * 128 + wid * 16 + gid + rr * 8;
            float tmax = -1e30f;
#pragma unroll
            for (int nf = 0; nf < 8; ++nf) {
#pragma unroll
                for (int e = 0; e < 2; ++e) {
                    int gcol = kt * 64 + nf * 8 + tig * 2 + e;
                    float v = s[nf][rr * 2 + e] * sc;
                    if (gcol > grow) v = -1e30f;
                    s[nf][rr * 2 + e] = v;
                    tmax = fmaxf(tmax, v);
                }
            }
            tmax = fmaxf(tmax, __shfl_xor_sync(0xffffffffu, tmax, 1));
            tmax = fmaxf(tmax, __shfl_xor_sync(0xffffffffu, tmax, 2));
            float nm = fmaxf(m_i[rr], tmax);
            float fac = __expf(m_i[rr] - nm);
            float psum = 0.f;
#pragma unroll
            for (int nf = 0; nf < 8; ++nf) {
#pragma unroll
                for (int e = 0; e < 2; ++e) {
                    float p = __expf(s[nf][rr * 2 + e] - nm);
                    s[nf][rr * 2 + e] = p;
                    psum += p;
                }
            }
            psum += __shfl_xor_sync(0xffffffffu, psum, 1);
            psum += __shfl_xor_sync(0xffffffffu, psum, 2);
            l_i[rr] = l_i[rr] * fac + psum;
            m_i[rr] = nm;
#pragma unroll
            for (int nf = 0; nf < 16; ++nf) {
                O[nf][rr * 2] *= fac;
                O[nf][rr * 2 + 1] *= fac;
            }
        }

#pragma unroll
        for (int rr = 0; rr < 2; ++rr) {
            uint32_t prow = wid * 16 + gid + rr * 8;
#pragma unroll
            for (int nf = 0; nf < 8; ++nf) {
                float p0 = s[nf][rr * 2], p1 = s[nf][rr * 2 + 1];
                bf16 h0,l0,h1,l1;
                split1(p0, h0, l0); split1(p1, h1, l1);
                bf162 hp, lp; hp.x=h0; hp.y=h1; lp.x=l0; lp.y=l1;
                uint32_t off = prow * FL_PSTR + (nf * 8 + tig * 2) * 2;
                *(uint32_t*)(sm + FL_PH + off) = *(uint32_t*)&hp;
                *(uint32_t*)(sm + FL_PL + off) = *(uint32_t*)&lp;
            }
        }
        __syncwarp();

#pragma unroll
        for (int ks = 0; ks < 4; ++ks) {
            uint32_t aph[4], apl[4];
            ldm4(aph, sb + FL_PH + a_row * FL_PSTR + a_colb + ks * 32);
            ldm4(apl, sb + FL_PL + a_row * FL_PSTR + a_colb + ks * 32);
            uint32_t vrow = ks * 16 + v_koff;
#pragma unroll
            for (int nb = 0; nb < 8; ++nb) {
                uint32_t bvh[4], bvl[4];
                uint32_t vcol = (nb * 16 + v_noff) * 2;
                ldm4t(bvh, stb + FL_VOFF + vrow * FL_VSTR + vcol);
                mma16816(O[2*nb],   aph, &bvh[0]);
                mma16816(O[2*nb+1], aph, &bvh[2]);
                mma16816(O[2*nb],   apl, &bvh[0]);
                mma16816(O[2*nb+1], apl, &bvh[2]);
                ldm4t(bvl, stb + FL_VOFF + 64 * FL_VSTR + vrow * FL_VSTR + vcol);
                mma16816(O[2*nb],   aph, &bvl[0]);
                mma16816(O[2*nb+1], aph, &bvl[2]);
            }
        }
        __syncthreads();
    }

#pragma unroll
    for (int rr = 0; rr < 2; ++rr) {
        float inv = 1.f / l_i[rr];
        int row = t0 + qt * 128 + wid * 16 + gid + rr * 8;
#pragma unroll
        for (int nf = 0; nf < 16; ++nf) {
            int col = nf * 8 + tig * 2;
            float v0 = O[nf][rr * 2] * inv, v1 = O[nf][rr * 2 + 1] * inv;
            bf16 h0,l0,h1,l1;
            split1(v0, h0, l0); split1(v1, h1, l1);
            bf162 hp, lp; hp.x=h0; hp.y=h1; lp.x=l0; lp.y=l1;
            size_t g = (size_t)row * (NHEADS * VHD) + hh * VHD + col;
            *(uint32_t*)(ctxh + g) = *(uint32_t*)&hp;
            *(uint32_t*)(ctxl + g) = *(uint32_t*)&lp;
        }
    }
}

// ---------------- launch ----------------
static inline void cvt(const float* x, bf16* h, bf16* l, int n) {
    int n4 = n >> 2;
    cvt_kernel<<<(n4 + 255) / 256, 256>>>(x, h, l, n4);
}

extern "C" void kernel_launch(void* const* d_in, const int* in_sizes, int n_in,
                              void* d_out, int out_size) {
    (void)in_sizes; (void)n_in; (void)out_size;
    const float* X     = (const float*)d_in[0];
    const int*   pos   = (const int*)  d_in[1];
    const float* wq_a  = (const float*)d_in[2];
    const float* qln   = (const float*)d_in[3];
    const float* wq_b  = (const float*)d_in[4];
    const float* wkv_a = (const float*)d_in[5];
    const float* kvln  = (const float*)d_in[6];
    const float* wkv_b = (const float*)d_in[7];
    const float* wo    = (const float*)d_in[8];
    float* out = (float*)d_out;

    float *qa, *ckv;
    bf16 *Xh,*Xl,*wqah,*wqal,*wqbh,*wqbl,*wkvah,*wkval,*wkvbh,*wkvbl,*woh,*wol;
    bf16 *qanh,*qanl,*ckvnh,*ckvnl,*qhb,*qlb,*kvh,*kvl,*kpeh,*kpel,*ctxh,*ctxl;
    cudaGetSymbolAddress((void**)&qa, g_qa);
    cudaGetSymbolAddress((void**)&ckv, g_ckv);
    cudaGetSymbolAddress((void**)&Xh, g_Xh);     cudaGetSymbolAddress((void**)&Xl, g_Xl);
    cudaGetSymbolAddress((void**)&wqah, g_wqa_h); cudaGetSymbolAddress((void**)&wqal, g_wqa_l);
    cudaGetSymbolAddress((void**)&wqbh, g_wqb_h); cudaGetSymbolAddress((void**)&wqbl, g_wqb_l);
    cudaGetSymbolAddress((void**)&wkvah, g_wkva_h); cudaGetSymbolAddress((void**)&wkval, g_wkva_l);
    cudaGetSymbolAddress((void**)&wkvbh, g_wkvb_h); cudaGetSymbolAddress((void**)&wkvbl, g_wkvb_l);
    cudaGetSymbolAddress((void**)&woh, g_wo_h);  cudaGetSymbolAddress((void**)&wol, g_wo_l);
    cudaGetSymbolAddress((void**)&qanh, g_qan_h); cudaGetSymbolAddress((void**)&qanl, g_qan_l);
    cudaGetSymbolAddress((void**)&ckvnh, g_ckvn_h); cudaGetSymbolAddress((void**)&ckvnl, g_ckvn_l);
    cudaGetSymbolAddress((void**)&qhb, g_qh);    cudaGetSymbolAddress((void**)&qlb, g_ql);
    cudaGetSymbolAddress((void**)&kvh, g_kvh);   cudaGetSymbolAddress((void**)&kvl, g_kvl);
    cudaGetSymbolAddress((void**)&kpeh, g_kpeh); cudaGetSymbolAddress((void**)&kpel, g_kpel);
    cudaGetSymbolAddress((void**)&ctxh, g_ctxh); cudaGetSymbolAddress((void**)&ctxl, g_ctxl);

    cudaFuncSetAttribute(bf_gemm, cudaFuncAttributeMaxDynamicSharedMemorySize, GEMM_SMEM);
    cudaFuncSetAttribute(bf_gemm_big, cudaFuncAttributeMaxDynamicSharedMemorySize, BG_SMEM);
    cudaFuncSetAttribute(flash_mma, cudaFuncAttributeMaxDynamicSharedMemorySize, FL_SMEM);

    const dim3 blk(256);
    const int mt = T_TOK / 128;    // 32
    const int mtb = T_TOK / 256;   // 16

    cvt(X, Xh, Xl, T_TOK * HIDDEN);
    cvt(wq_a, wqah, wqal, QLORA * HIDDEN);
    cvt(wq_b, wqbh, wqbl, NHEADS * QHD * QLORA);
    cvt(wkv_a, wkvah, wkval, KVW * HIDDEN);
    cvt(wkv_b, wkvbh, wkvbl, NHEADS * 256 * KVLORA);
    cvt(wo, woh, wol, HIDDEN * NHEADS * VHD);

    // q path
    bf_gemm<<<dim3(QLORA / 128, mt), blk, GEMM_SMEM>>>(Xh, Xl, wqah, wqal, qa, nullptr, nullptr,
                                                       T_TOK, QLORA, HIDDEN);
    rmsnorm_kernel<<<T_TOK, 256>>>(qa, qln, qanh, qanl, QLORA, QLORA);
    bf_gemm_big<<<dim3((NHEADS * QHD) / 128, mtb), blk, BG_SMEM>>>(qanh, qanl, wqbh, wqbl,
                                                                   nullptr, qhb, qlb,
                                                                   T_TOK, NHEADS * QHD, QLORA);

    // kv path
    bf_gemm<<<dim3((KVW + 127) / 128, mt), blk, GEMM_SMEM>>>(Xh, Xl, wkvah, wkval, ckv,
                                                             nullptr, nullptr, T_TOK, KVW, HIDDEN);
    rmsnorm_kernel<<<T_TOK, 256>>>(ckv, kvln, ckvnh, ckvnl, KVLORA, KVW);
    rope_k_kernel<<<T_TOK, 32>>>(ckv, pos, kpeh, kpel);
    bf_gemm_big<<<dim3((NHEADS * 256) / 128, mtb), blk, BG_SMEM>>>(ckvnh, ckvnl, wkvbh, wkvbl,
                                                                   nullptr, kvh, kvl,
                                                                   T_TOK, NHEADS * 256, KVLORA);

    rope_q_kernel<<<T_TOK * NHEADS, 32>>>(qhb, qlb, pos);

    flash_mma<<<dim3(S_LEN / 128, NHEADS, BATCH), blk, FL_SMEM>>>(qhb, qlb, kvh, kvl,
                                                                  kpeh, kpel, ctxh, ctxl);

    bf_gemm_big<<<dim3(HIDDEN / 128, mtb), blk, BG_SMEM>>>(ctxh, ctxl, woh, wol, out,
                                                           nullptr, nullptr,
                                                           T_TOK, HIDDEN, NHEADS * VHD);
}

// round 7
// speedup vs baseline: 1.7590x; 1.7590x over previous
#include <cuda_runtime.h>
#include <cuda_bf16.h>
#include <math.h>
#include <stdint.h>

// ---------------- problem constants ----------------
#define S_LEN   2048
#define BATCH   2
#define T_TOK   (BATCH * S_LEN)
#define HIDDEN  2048
#define QLORA   1536
#define KVLORA  512
#define NHEADS  16
#define NOPE    128
#define ROPE_D  64
#define QHD     192
#define VHD     128
#define KVW     576

typedef __nv_bfloat16 bf16;
typedef __nv_bfloat162 bf162;

// ---------------- scratch ----------------
__device__ float g_qa [T_TOK * QLORA];
__device__ float g_ckv[T_TOK * KVW];

__device__ bf16 g_Xh[T_TOK * HIDDEN],       g_Xl[T_TOK * HIDDEN];
__device__ bf16 g_wqa_h[QLORA * HIDDEN],    g_wqa_l[QLORA * HIDDEN];
__device__ bf16 g_wqb_h[NHEADS*QHD*QLORA],  g_wqb_l[NHEADS*QHD*QLORA];
__device__ bf16 g_wkva_h[KVW * HIDDEN],     g_wkva_l[KVW * HIDDEN];
__device__ bf16 g_wkvb_h[NHEADS*256*KVLORA],g_wkvb_l[NHEADS*256*KVLORA];
__device__ bf16 g_wo_h[HIDDEN*NHEADS*VHD],  g_wo_l[HIDDEN*NHEADS*VHD];
__device__ bf16 g_qan_h[T_TOK * QLORA],     g_qan_l[T_TOK * QLORA];
__device__ bf16 g_ckvn_h[T_TOK * KVLORA],   g_ckvn_l[T_TOK * KVLORA];
__device__ bf16 g_qh[T_TOK * NHEADS * QHD], g_ql[T_TOK * NHEADS * QHD];
__device__ bf16 g_kvh[T_TOK * NHEADS * 256],g_kvl[T_TOK * NHEADS * 256];
__device__ bf16 g_kpeh[T_TOK * ROPE_D],     g_kpel[T_TOK * ROPE_D];
__device__ bf16 g_ctxh[T_TOK * NHEADS*VHD], g_ctxl[T_TOK * NHEADS*VHD];

// ---------------- common helpers ----------------
__device__ __forceinline__ uint32_t smem_u32(const void* p) {
    uint32_t a;
    asm("{ .reg .u64 t; cvta.to.shared.u64 t, %1; cvt.u32.u64 %0, t; }" : "=r"(a) : "l"(p));
    return a;
}
__device__ __forceinline__ void ldm4(uint32_t* r, uint32_t addr) {
    asm volatile("ldmatrix.sync.aligned.m8n8.x4.shared.b16 {%0,%1,%2,%3}, [%4];"
                 : "=r"(r[0]), "=r"(r[1]), "=r"(r[2]), "=r"(r[3]) : "r"(addr));
}
__device__ __forceinline__ void ldm4t(uint32_t* r, uint32_t addr) {
    asm volatile("ldmatrix.sync.aligned.m8n8.x4.trans.shared.b16 {%0,%1,%2,%3}, [%4];"
                 : "=r"(r[0]), "=r"(r[1]), "=r"(r[2]), "=r"(r[3]) : "r"(addr));
}
__device__ __forceinline__ void mma16816(float* d, const uint32_t* a, const uint32_t* b) {
    asm volatile("mma.sync.aligned.m16n8k16.row.col.f32.bf16.bf16.f32 "
                 "{%0,%1,%2,%3}, {%4,%5,%6,%7}, {%8,%9}, {%0,%1,%2,%3};"
                 : "+f"(d[0]), "+f"(d[1]), "+f"(d[2]), "+f"(d[3])
                 : "r"(a[0]), "r"(a[1]), "r"(a[2]), "r"(a[3]), "r"(b[0]), "r"(b[1]));
}
__device__ __forceinline__ void cpa16(uint32_t dst, const void* src, uint32_t sz) {
    asm volatile("cp.async.cg.shared.global [%0], [%1], 16, %2;"
                 :: "r"(dst), "l"(src), "r"(sz) : "memory");
}
__device__ __forceinline__ void split1(float v, bf16& h, bf16& l) {
    h = __float2bfloat16_rn(v);
    l = __float2bfloat16_rn(v - __bfloat162float(h));
}

// ---------------- merged convert fp32 -> (hi, lo) bf16, 6 regions ----------------
struct Cvt6P {
    const float* x[6];
    bf16* h[6];
    bf16* l[6];
    int off[7];     // prefix sums in float4 units
};
__global__ void cvt6_kernel(Cvt6P P) {
    int i = blockIdx.x * blockDim.x + threadIdx.x;
    if (i >= P.off[6]) return;
    int r = 0;
#pragma unroll
    for (int k = 1; k < 6; ++k) if (i >= P.off[k]) r = k;
    int j = i - P.off[r];
    float4 v = ((const float4*)P.x[r])[j];
    bf16 h0,h1,h2,h3,l0,l1,l2,l3;
    split1(v.x,h0,l0); split1(v.y,h1,l1); split1(v.z,h2,l2); split1(v.w,h3,l3);
    bf162 hp0, hp1, lp0, lp1;
    hp0.x=h0; hp0.y=h1; hp1.x=h2; hp1.y=h3;
    lp0.x=l0; lp0.y=l1; lp1.x=l2; lp1.y=l3;
    uint2 hh, ll;
    hh.x=*(uint32_t*)&hp0; hh.y=*(uint32_t*)&hp1;
    ll.x=*(uint32_t*)&lp0; ll.y=*(uint32_t*)&lp1;
    ((uint2*)P.h[r])[j] = hh;
    ((uint2*)P.l[r])[j] = ll;
}

// ============================================================================
// bf16 split GEMM (128x128 CTA, 2 CTAs/SM), dual-problem launch.
// BK=16, 4-stage cp.async, one sync per chunk. 8 warps (64x32 warp tile).
// ============================================================================
#define SMSTR 48
#define TILEB (128 * SMSTR)
#define STAGEB (4 * TILEB)
#define NSTAGE 4
#define GEMM_SMEM (NSTAGE * STAGEB)

struct GemmP {
    const bf16 *Ah, *Al, *Bh, *Bl;
    float* C;
    bf16 *Ch, *Cl;
    int N, K;
};

__global__ __launch_bounds__(256, 2) void bf_gemm_dual(GemmP P0, GemmP P1, int xsplit) {
    extern __shared__ char sm[];
    const bool first = ((int)blockIdx.x < xsplit);
    const GemmP p = first ? P0 : P1;
    const int n0 = (first ? blockIdx.x : (blockIdx.x - xsplit)) * 128;
    const int K = p.K, N = p.N;

    const int tid = threadIdx.x;
    const int wid = tid >> 5;
    const int lane = tid & 31;
    const int m0 = blockIdx.y * 128;
    const int nvalid = (N - n0 < 128) ? (N - n0) : 128;

    const uint32_t sbase = smem_u32(sm);
    const int wr = wid >> 2, wc = wid & 3;
    const uint32_t a_row = wr * 64 + (lane & 15);
    const uint32_t a_colb = (lane >> 4) * 16;
    const uint32_t b_row = wc * 32 + (lane & 7) + ((lane >> 4) << 3);
    const uint32_t b_colb = ((lane >> 3) & 1) * 16;

    float acc[4][4][4];
#pragma unroll
    for (int i = 0; i < 4; ++i)
#pragma unroll
        for (int j = 0; j < 4; ++j)
#pragma unroll
            for (int e = 0; e < 4; ++e) acc[i][j][e] = 0.f;

    const int nch = K >> 4;

    auto issue_chunk = [&](int c) {
        const int k0 = c << 4;
        const uint32_t stb = sbase + (c & (NSTAGE - 1)) * STAGEB;
#pragma unroll
        for (int i = 0; i < 4; ++i) {
            int u = tid + i * 256;
            int tile = u >> 8;
            int row = (u & 255) >> 1;
            int c16 = u & 1;
            uint32_t dst = stb + tile * TILEB + row * SMSTR + c16 * 16;
            const bf16* src;
            uint32_t sz = 16;
            if (tile == 0)      src = p.Ah + (size_t)(m0 + row) * K + k0 + c16 * 8;
            else if (tile == 1) src = p.Al + (size_t)(m0 + row) * K + k0 + c16 * 8;
            else {
                const bf16* base = (tile == 2) ? p.Bh : p.Bl;
                src = base + (size_t)(n0 + row) * K + k0 + c16 * 8;
                if (row >= nvalid) sz = 0;
            }
            cpa16(dst, src, sz);
        }
        asm volatile("cp.async.commit_group;" ::: "memory");
    };

    issue_chunk(0);
    if (nch > 1) issue_chunk(1); else asm volatile("cp.async.commit_group;" ::: "memory");
    if (nch > 2) issue_chunk(2); else asm volatile("cp.async.commit_group;" ::: "memory");

    for (int c = 0; c < nch; ++c) {
        asm volatile("cp.async.wait_group 2;" ::: "memory");
        __syncthreads();
        if (c + 3 < nch) issue_chunk(c + 3);
        else asm volatile("cp.async.commit_group;" ::: "memory");

        const uint32_t stb = sbase + (c & (NSTAGE - 1)) * STAGEB;
        uint32_t ah[4][4], bh[2][4];
#pragma unroll
        for (int i = 0; i < 4; ++i)
            ldm4(ah[i], stb + (a_row + i * 16) * SMSTR + a_colb);
#pragma unroll
        for (int jp = 0; jp < 2; ++jp)
            ldm4(bh[jp], stb + 2 * TILEB + (b_row + jp * 16) * SMSTR + b_colb);
#pragma unroll
        for (int i = 0; i < 4; ++i)
#pragma unroll
            for (int j = 0; j < 4; ++j)
                mma16816(acc[i][j], ah[i], &bh[j >> 1][(j & 1) * 2]);
        {
            uint32_t al[4][4];
#pragma unroll
            for (int i = 0; i < 4; ++i)
                ldm4(al[i], stb + TILEB + (a_row + i * 16) * SMSTR + a_colb);
#pragma unroll
            for (int i = 0; i < 4; ++i)
#pragma unroll
                for (int j = 0; j < 4; ++j)
                    mma16816(acc[i][j], al[i], &bh[j >> 1][(j & 1) * 2]);
        }
        {
            uint32_t bl[2][4];
#pragma unroll
            for (int jp = 0; jp < 2; ++jp)
                ldm4(bl[jp], stb + 3 * TILEB + (b_row + jp * 16) * SMSTR + b_colb);
#pragma unroll
            for (int i = 0; i < 4; ++i)
#pragma unroll
                for (int j = 0; j < 4; ++j)
                    mma16816(acc[i][j], ah[i], &bl[j >> 1][(j & 1) * 2]);
        }
    }

    const int gid = lane >> 2, tig = lane & 3;
#pragma unroll
    for (int i = 0; i < 4; ++i) {
#pragma unroll
        for (int rr = 0; rr < 2; ++rr) {
            int row = m0 + wr * 64 + i * 16 + gid + rr * 8;
#pragma unroll
            for (int j = 0; j < 4; ++j) {
                int col = n0 + wc * 32 + j * 8 + tig * 2;
                if (col < N) {
                    float v0 = acc[i][j][rr * 2], v1 = acc[i][j][rr * 2 + 1];
                    if (p.C) *(float2*)(p.C + (size_t)row * N + col) = make_float2(v0, v1);
                    if (p.Ch) {
                        bf162 hp, lp;
                        bf16 h0,l0,h1,l1;
                        split1(v0,h0,l0); split1(v1,h1,l1);
                        hp.x=h0; hp.y=h1; lp.x=l0; lp.y=l1;
                        *(uint32_t*)(p.Ch + (size_t)row * N + col) = *(uint32_t*)&hp;
                        *(uint32_t*)(p.Cl + (size_t)row * N + col) = *(uint32_t*)&lp;
                    }
                }
            }
        }
    }
}

// ---------------- dual RMSNorm -> bf16 hi/lo ----------------
struct RmsP {
    const float* x; const float* w;
    bf16 *yh, *yl;
    int D, in_stride;
};
__global__ void rmsnorm_dual(RmsP P0, RmsP P1) {
    const RmsP p = (blockIdx.y == 0) ? P0 : P1;
    const int row = blockIdx.x;
    const float* xr = p.x + (size_t)row * p.in_stride;
    float ss = 0.f;
    for (int d = threadIdx.x; d < p.D; d += blockDim.x) { float v = xr[d]; ss += v * v; }
    __shared__ float red[32];
#pragma unroll
    for (int o = 16; o; o >>= 1) ss += __shfl_xor_sync(0xffffffffu, ss, o);
    if ((threadIdx.x & 31) == 0) red[threadIdx.x >> 5] = ss;
    __syncthreads();
    if (threadIdx.x < 32) {
        float v = (threadIdx.x < (blockDim.x >> 5)) ? red[threadIdx.x] : 0.f;
#pragma unroll
        for (int o = 16; o; o >>= 1) v += __shfl_xor_sync(0xffffffffu, v, o);
        if (threadIdx.x == 0) red[0] = v;
    }
    __syncthreads();
    float scale = rsqrtf(red[0] / (float)p.D + 1e-6f);
    for (int d = threadIdx.x; d < p.D; d += blockDim.x) {
        float v = p.w[d] * xr[d] * scale;
        bf16 h, l; split1(v, h, l);
        p.yh[(size_t)row * p.D + d] = h;
        p.yl[(size_t)row * p.D + d] = l;
    }
}

// ---------------- YaRN ----------------
__device__ __forceinline__ void yarn_cs(int pos, int j, float& c, float& s) {
    float ex   = __expf(-(float)(2 * j) * (9.210340371976184f / 64.f));
    float fi   = ex * 0.025f;
    float ramp = ((float)j - 10.f) * (1.f / 13.f);
    ramp = fminf(fmaxf(ramp, 0.f), 1.f);
    float invf = fi * ramp + ex * (1.f - ramp);
    float ang  = (float)pos * invf;
    c = cosf(ang); s = sinf(ang);
}

__global__ void rope_k_kernel(const float* __restrict__ ckv, const int* __restrict__ pos_ids,
                              bf16* __restrict__ kh, bf16* __restrict__ kl) {
    const int t = blockIdx.x;
    const int j = threadIdx.x;
    const int pos = pos_ids[t];
    const float* x = ckv + (size_t)t * KVW + KVLORA;
    float c, s; yarn_cs(pos, j, c, s);
    float x0 = x[2 * j], x1 = x[2 * j + 1];
    float r0 = x0 * c - x1 * s, r1 = x1 * c + x0 * s;
    bf16 h, l;
    split1(r0, h, l); kh[t * ROPE_D + j] = h;      kl[t * ROPE_D + j] = l;
    split1(r1, h, l); kh[t * ROPE_D + 32 + j] = h; kl[t * ROPE_D + 32 + j] = l;
}

__global__ void rope_q_kernel(bf16* __restrict__ qh, bf16* __restrict__ ql,
                              const int* __restrict__ pos_ids) {
    const int t = blockIdx.x >> 4;
    const int h = blockIdx.x & 15;
    const int j = threadIdx.x;
    const int pos = pos_ids[t];
    bf16* xh = qh + (size_t)t * (NHEADS * QHD) + h * QHD + NOPE;
    bf16* xl = ql + (size_t)t * (NHEADS * QHD) + h * QHD + NOPE;
    float c, s; yarn_cs(pos, j, c, s);
    float x0 = __bfloat162float(xh[2*j])   + __bfloat162float(xl[2*j]);
    float x1 = __bfloat162float(xh[2*j+1]) + __bfloat162float(xl[2*j+1]);
    float r0 = x0 * c - x1 * s, r1 = x1 * c + x0 * s;
    __syncwarp();
    bf16 hh, ll;
    split1(r0, hh, ll); xh[j] = hh;      xl[j] = ll;
    split1(r1, hh, ll); xh[32 + j] = hh; xl[32 + j] = ll;
}

// ============================================================================
// Flash attention, split-bf16 HMMA. BM=128, BN=64, 8 warps. (R5, unchanged)
// ============================================================================
#define FL_KSTR 400
#define FL_VSTR 272
#define FL_PSTR 144
#define FL_KVSTG (64 * FL_KSTR * 2 + 64 * FL_VSTR * 2)
#define FL_VOFF  (64 * FL_KSTR * 2)
#define FL_PH  (2 * FL_KVSTG)
#define FL_PL  (FL_PH + 128 * FL_PSTR)
#define FL_SMEM (FL_PL + 128 * FL_PSTR)
#define FL_QSTR 400

__global__ __launch_bounds__(256, 1) void flash_mma(
    const bf16* __restrict__ qh, const bf16* __restrict__ ql,
    const bf16* __restrict__ kvh, const bf16* __restrict__ kvl,
    const bf16* __restrict__ kpeh, const bf16* __restrict__ kpel,
    bf16* __restrict__ ctxh, bf16* __restrict__ ctxl)
{
    extern __shared__ char sm[];
    const uint32_t sb = smem_u32(sm);
    const int qt = (int)gridDim.x - 1 - (int)blockIdx.x;
    const int hh = blockIdx.y, b = blockIdx.z;
    const int tid = threadIdx.x, wid = tid >> 5, lane = tid & 31;
    const int gid = lane >> 2, tig = lane & 3;
    const int t0 = b * S_LEN;

    const uint32_t a_row = wid * 16 + (lane & 15);
    const uint32_t a_colb = (lane >> 4) * 16;
    const uint32_t k_roff = (lane & 7) + ((lane >> 4) << 3);
    const uint32_t k_colb = ((lane >> 3) & 1) * 16;
    const uint32_t v_koff = (lane & 7) + ((lane >> 3) & 1) * 8;
    const uint32_t v_noff = (lane >> 4) * 8;

    for (int idx = tid; idx < 128 * 24; idx += 256) {
        int r = idx / 24, u = idx % 24;
        size_t g = (size_t)(t0 + qt * 128 + r) * (NHEADS * QHD) + hh * QHD + u * 8;
        *(uint4*)(sm + r * FL_QSTR + u * 16) = *(const uint4*)(qh + g);
        *(uint4*)(sm + 51200 + r * FL_QSTR + u * 16) = *(const uint4*)(ql + g);
    }
    __syncthreads();
    uint32_t qfh[12][4], qfl[12][4];
#pragma unroll
    for (int ks = 0; ks < 12; ++ks) {
        ldm4(qfh[ks], sb + a_row * FL_QSTR + a_colb + ks * 32);
        ldm4(qfl[ks], sb + 51200 + a_row * FL_QSTR + a_colb + ks * 32);
    }
    __syncthreads();

    auto issue_kv = [&](int kt) {
        const uint32_t stb = sb + (kt & 1) * FL_KVSTG;
        for (int idx = tid; idx < 64 * 24; idx += 256) {
            int r = idx / 24, u = idx % 24;
            int t = t0 + kt * 64 + r;
            const bf16 *srch, *srcl;
            if (u < 16) {
                size_t g = (size_t)t * (NHEADS * 256) + hh * 256 + u * 8;
                srch = kvh + g; srcl = kvl + g;
            } else {
                size_t g = (size_t)t * ROPE_D + (u - 16) * 8;
                srch = kpeh + g; srcl = kpel + g;
            }
            uint32_t off = r * FL_KSTR + u * 16;
            cpa16(stb + off, srch, 16);
            cpa16(stb + 64 * FL_KSTR + off, srcl, 16);
        }
        for (int idx = tid; idx < 64 * 16; idx += 256) {
            int r = idx >> 4, u = idx & 15;
            size_t g = (size_t)(t0 + kt * 64 + r) * (NHEADS * 256) + hh * 256 + 128 + u * 8;
            uint32_t off = FL_VOFF + r * FL_VSTR + u * 16;
            cpa16(stb + off, kvh + g, 16);
            cpa16(stb + 64 * FL_VSTR + off, kvl + g, 16);
        }
        asm volatile("cp.async.commit_group;" ::: "memory");
    };

    float m_i[2], l_i[2], O[16][4];
    m_i[0] = m_i[1] = -1e30f; l_i[0] = l_i[1] = 0.f;
#pragma unroll
    for (int nf = 0; nf < 16; ++nf)
#pragma unroll
        for (int e = 0; e < 4; ++e) O[nf][e] = 0.f;

    const float mm = 0.1f * logf(40.f) + 1.f;
    const float sc = mm * mm * rsqrtf(192.f);

    const int nkt = 2 * qt + 2;
    issue_kv(0);

    for (int kt = 0; kt < nkt; ++kt) {
        if (kt + 1 < nkt) {
            issue_kv(kt + 1);
            asm volatile("cp.async.wait_group 1;" ::: "memory");
        } else {
            asm volatile("cp.async.wait_group 0;" ::: "memory");
        }
        __syncthreads();
        const uint32_t stb = sb + (kt & 1) * FL_KVSTG;

        float s[8][4];
#pragma unroll
        for (int nf = 0; nf < 8; ++nf)
#pragma unroll
            for (int e = 0; e < 4; ++e) s[nf][e] = 0.f;

#pragma unroll
        for (int ks = 0; ks < 12; ++ks) {
#pragma unroll
            for (int jb = 0; jb < 4; ++jb) {
                uint32_t bh4[4], bl4[4];
                uint32_t brow = jb * 16 + k_roff;
                ldm4(bh4, stb + brow * FL_KSTR + k_colb + ks * 32);
                mma16816(s[2*jb],   qfh[ks], &bh4[0]);
                mma16816(s[2*jb+1], qfh[ks], &bh4[2]);
                mma16816(s[2*jb],   qfl[ks], &bh4[0]);
                mma16816(s[2*jb+1], qfl[ks], &bh4[2]);
                ldm4(bl4, stb + 64 * FL_KSTR + brow * FL_KSTR + k_colb + ks * 32);
                mma16816(s[2*jb],   qfh[ks], &bl4[0]);
                mma16816(s[2*jb+1], qfh[ks], &bl4[2]);
            }
        }

#pragma unroll
        for (int rr = 0; rr < 2; ++rr) {
            int grow = qt * 128 + wid * 16 + gid + rr * 8;
            float tmax = -1e30f;
#pragma unroll
            for (int nf = 0; nf < 8; ++nf) {
#pragma unroll
                for (int e = 0; e < 2; ++e) {
                    int gcol = kt * 64 + nf * 8 + tig * 2 + e;
                    float v = s[nf][rr * 2 + e] * sc;
                    if (gcol > grow) v = -1e30f;
                    s[nf][rr * 2 + e] = v;
                    tmax = fmaxf(tmax, v);
                }
            }
            tmax = fmaxf(tmax, __shfl_xor_sync(0xffffffffu, tmax, 1));
            tmax = fmaxf(tmax, __shfl_xor_sync(0xffffffffu, tmax, 2));
            float nm = fmaxf(m_i[rr], tmax);
            float fac = __expf(m_i[rr] - nm);
            float psum = 0.f;
#pragma unroll
            for (int nf = 0; nf < 8; ++nf) {
#pragma unroll
                for (int e = 0; e < 2; ++e) {
                    float p = __expf(s[nf][rr * 2 + e] - nm);
                    s[nf][rr * 2 + e] = p;
                    psum += p;
                }
            }
            psum += __shfl_xor_sync(0xffffffffu, psum, 1);
            psum += __shfl_xor_sync(0xffffffffu, psum, 2);
            l_i[rr] = l_i[rr] * fac + psum;
            m_i[rr] = nm;
#pragma unroll
            for (int nf = 0; nf < 16; ++nf) {
                O[nf][rr * 2] *= fac;
                O[nf][rr * 2 + 1] *= fac;
            }
        }

#pragma unroll
        for (int rr = 0; rr < 2; ++rr) {
            uint32_t prow = wid * 16 + gid + rr * 8;
#pragma unroll
            for (int nf = 0; nf < 8; ++nf) {
                float p0 = s[nf][rr * 2], p1 = s[nf][rr * 2 + 1];
                bf16 h0,l0,h1,l1;
                split1(p0, h0, l0); split1(p1, h1, l1);
                bf162 hp, lp; hp.x=h0; hp.y=h1; lp.x=l0; lp.y=l1;
                uint32_t off = prow * FL_PSTR + (nf * 8 + tig * 2) * 2;
                *(uint32_t*)(sm + FL_PH + off) = *(uint32_t*)&hp;
                *(uint32_t*)(sm + FL_PL + off) = *(uint32_t*)&lp;
            }
        }
        __syncwarp();

#pragma unroll
        for (int ks = 0; ks < 4; ++ks) {
            uint32_t aph[4], apl[4];
            ldm4(aph, sb + FL_PH + a_row * FL_PSTR + a_colb + ks * 32);
            ldm4(apl, sb + FL_PL + a_row * FL_PSTR + a_colb + ks * 32);
            uint32_t vrow = ks * 16 + v_koff;
#pragma unroll
            for (int nb = 0; nb < 8; ++nb) {
                uint32_t bvh[4], bvl[4];
                uint32_t vcol = (nb * 16 + v_noff) * 2;
                ldm4t(bvh, stb + FL_VOFF + vrow * FL_VSTR + vcol);
                mma16816(O[2*nb],   aph, &bvh[0]);
                mma16816(O[2*nb+1], aph, &bvh[2]);
                mma16816(O[2*nb],   apl, &bvh[0]);
                mma16816(O[2*nb+1], apl, &bvh[2]);
                ldm4t(bvl, stb + FL_VOFF + 64 * FL_VSTR + vrow * FL_VSTR + vcol);
                mma16816(O[2*nb],   aph, &bvl[0]);
                mma16816(O[2*nb+1], aph, &bvl[2]);
            }
        }
        __syncthreads();
    }

#pragma unroll
    for (int rr = 0; rr < 2; ++rr) {
        float inv = 1.f / l_i[rr];
        int row = t0 + qt * 128 + wid * 16 + gid + rr * 8;
#pragma unroll
        for (int nf = 0; nf < 16; ++nf) {
            int col = nf * 8 + tig * 2;
            float v0 = O[nf][rr * 2] * inv, v1 = O[nf][rr * 2 + 1] * inv;
            bf16 h0,l0,h1,l1;
            split1(v0, h0, l0); split1(v1, h1, l1);
            bf162 hp, lp; hp.x=h0; hp.y=h1; lp.x=l0; lp.y=l1;
            size_t g = (size_t)row * (NHEADS * VHD) + hh * VHD + col;
            *(uint32_t*)(ctxh + g) = *(uint32_t*)&hp;
            *(uint32_t*)(ctxl + g) = *(uint32_t*)&lp;
        }
    }
}

// ---------------- launch ----------------
extern "C" void kernel_launch(void* const* d_in, const int* in_sizes, int n_in,
                              void* d_out, int out_size) {
    (void)in_sizes; (void)n_in; (void)out_size;
    const float* X     = (const float*)d_in[0];
    const int*   pos   = (const int*)  d_in[1];
    const float* wq_a  = (const float*)d_in[2];
    const float* qln   = (const float*)d_in[3];
    const float* wq_b  = (const float*)d_in[4];
    const float* wkv_a = (const float*)d_in[5];
    const float* kvln  = (const float*)d_in[6];
    const float* wkv_b = (const float*)d_in[7];
    const float* wo    = (const float*)d_in[8];
    float* out = (float*)d_out;

    float *qa, *ckv;
    bf16 *Xh,*Xl,*wqah,*wqal,*wqbh,*wqbl,*wkvah,*wkval,*wkvbh,*wkvbl,*woh,*wol;
    bf16 *qanh,*qanl,*ckvnh,*ckvnl,*qhb,*qlb,*kvh,*kvl,*kpeh,*kpel,*ctxh,*ctxl;
    cudaGetSymbolAddress((void**)&qa, g_qa);
    cudaGetSymbolAddress((void**)&ckv, g_ckv);
    cudaGetSymbolAddress((void**)&Xh, g_Xh);     cudaGetSymbolAddress((void**)&Xl, g_Xl);
    cudaGetSymbolAddress((void**)&wqah, g_wqa_h); cudaGetSymbolAddress((void**)&wqal, g_wqa_l);
    cudaGetSymbolAddress((void**)&wqbh, g_wqb_h); cudaGetSymbolAddress((void**)&wqbl, g_wqb_l);
    cudaGetSymbolAddress((void**)&wkvah, g_wkva_h); cudaGetSymbolAddress((void**)&wkval, g_wkva_l);
    cudaGetSymbolAddress((void**)&wkvbh, g_wkvb_h); cudaGetSymbolAddress((void**)&wkvbl, g_wkvb_l);
    cudaGetSymbolAddress((void**)&woh, g_wo_h);  cudaGetSymbolAddress((void**)&wol, g_wo_l);
    cudaGetSymbolAddress((void**)&qanh, g_qan_h); cudaGetSymbolAddress((void**)&qanl, g_qan_l);
    cudaGetSymbolAddress((void**)&ckvnh, g_ckvn_h); cudaGetSymbolAddress((void**)&ckvnl, g_ckvn_l);
    cudaGetSymbolAddress((void**)&qhb, g_qh);    cudaGetSymbolAddress((void**)&qlb, g_ql);
    cudaGetSymbolAddress((void**)&kvh, g_kvh);   cudaGetSymbolAddress((void**)&kvl, g_kvl);
    cudaGetSymbolAddress((void**)&kpeh, g_kpeh); cudaGetSymbolAddress((void**)&kpel, g_kpel);
    cudaGetSymbolAddress((void**)&ctxh, g_ctxh); cudaGetSymbolAddress((void**)&ctxl, g_ctxl);

    cudaFuncSetAttribute(bf_gemm_dual, cudaFuncAttributeMaxDynamicSharedMemorySize, GEMM_SMEM);
    cudaFuncSetAttribute(flash_mma, cudaFuncAttributeMaxDynamicSharedMemorySize, FL_SMEM);

    const dim3 blk(256);
    const int mt = T_TOK / 128;  // 32

    // merged input conversions (6 regions)
    {
        Cvt6P P;
        P.x[0]=X;     P.h[0]=Xh;    P.l[0]=Xl;
        P.x[1]=wq_a;  P.h[1]=wqah;  P.l[1]=wqal;
        P.x[2]=wq_b;  P.h[2]=wqbh;  P.l[2]=wqbl;
        P.x[3]=wkv_a; P.h[3]=wkvah; P.l[3]=wkval;
        P.x[4]=wkv_b; P.h[4]=wkvbh; P.l[4]=wkvbl;
        P.x[5]=wo;    P.h[5]=woh;   P.l[5]=wol;
        int lens[6] = { T_TOK*HIDDEN/4, QLORA*HIDDEN/4, NHEADS*QHD*QLORA/4,
                        KVW*HIDDEN/4, NHEADS*256*KVLORA/4, HIDDEN*NHEADS*VHD/4 };
        P.off[0] = 0;
        for (int i = 0; i < 6; ++i) P.off[i+1] = P.off[i] + lens[i];
        cvt6_kernel<<<(P.off[6] + 255) / 256, 256>>>(P);
    }

    // fused a-projections: wq_a (x<12) + wkv_a (x>=12)
    {
        GemmP p0 = { Xh, Xl, wqah, wqal, qa, nullptr, nullptr, QLORA, HIDDEN };
        GemmP p1 = { Xh, Xl, wkvah, wkval, ckv, nullptr, nullptr, KVW, HIDDEN };
        bf_gemm_dual<<<dim3(QLORA/128 + (KVW+127)/128, mt), blk, GEMM_SMEM>>>(p0, p1, QLORA/128);
    }

    // fused rmsnorms
    {
        RmsP p0 = { qa, qln, qanh, qanl, QLORA, QLORA };
        RmsP p1 = { ckv, kvln, ckvnh, ckvnl, KVLORA, KVW };
        rmsnorm_dual<<<dim3(T_TOK, 2), 256>>>(p0, p1);
    }
    rope_k_kernel<<<T_TOK, 32>>>(ckv, pos, kpeh, kpel);

    // fused b-projections: wq_b (x<24) + wkv_b (x>=24)
    {
        GemmP p0 = { qanh, qanl, wqbh, wqbl, nullptr, qhb, qlb, NHEADS*QHD, QLORA };
        GemmP p1 = { ckvnh, ckvnl, wkvbh, wkvbl, nullptr, kvh, kvl, NHEADS*256, KVLORA };
        bf_gemm_dual<<<dim3((NHEADS*QHD)/128 + (NHEADS*256)/128, mt), blk, GEMM_SMEM>>>(
            p0, p1, (NHEADS*QHD)/128);
    }

    rope_q_kernel<<<T_TOK * NHEADS, 32>>>(qhb, qlb, pos);

    flash_mma<<<dim3(S_LEN / 128, NHEADS, BATCH), blk, FL_SMEM>>>(qhb, qlb, kvh, kvl,
                                                                  kpeh, kpel, ctxh, ctxl);

    // output projection (single problem via dual kernel)
    {
        GemmP p0 = { ctxh, ctxl, woh, wol, out, nullptr, nullptr, HIDDEN, NHEADS*VHD };
        bf_gemm_dual<<<dim3(HIDDEN/128, mt), blk, GEMM_SMEM>>>(p0, p0, HIDDEN/128);
    }
}

// round 8
// speedup vs baseline: 1.9051x; 1.0830x over previous
#include <cuda_runtime.h>
#include <cuda_bf16.h>
#include <cuda_fp16.h>
#include <math.h>
#include <stdint.h>

// ---------------- problem constants ----------------
#define S_LEN   2048
#define BATCH   2
#define T_TOK   (BATCH * S_LEN)
#define HIDDEN  2048
#define QLORA   1536
#define KVLORA  512
#define NHEADS  16
#define NOPE    128
#define ROPE_D  64
#define QHD     192
#define VHD     128
#define KVW     576

typedef __nv_bfloat16 bf16;
typedef __nv_bfloat162 bf162;

// ---------------- scratch ----------------
__device__ float g_qa [T_TOK * QLORA];
__device__ float g_ckv[T_TOK * KVW];

__device__ bf16 g_Xh[T_TOK * HIDDEN],       g_Xl[T_TOK * HIDDEN];
__device__ bf16 g_wqa_h[QLORA * HIDDEN],    g_wqa_l[QLORA * HIDDEN];
__device__ bf16 g_wqb_h[NHEADS*QHD*QLORA],  g_wqb_l[NHEADS*QHD*QLORA];
__device__ bf16 g_wkva_h[KVW * HIDDEN],     g_wkva_l[KVW * HIDDEN];
__device__ bf16 g_wkvb_h[NHEADS*256*KVLORA],g_wkvb_l[NHEADS*256*KVLORA];
__device__ bf16 g_wo_h[HIDDEN*NHEADS*VHD],  g_wo_l[HIDDEN*NHEADS*VHD];
__device__ bf16 g_qan_h[T_TOK * QLORA],     g_qan_l[T_TOK * QLORA];
__device__ bf16 g_ckvn_h[T_TOK * KVLORA],   g_ckvn_l[T_TOK * KVLORA];
// flash-path fp16 tensors
__device__ __half g_q16h[T_TOK * NHEADS * QHD], g_q16l[T_TOK * NHEADS * QHD];
__device__ __half g_kv16[T_TOK * NHEADS * 256];
__device__ __half g_kpe16[T_TOK * ROPE_D];
__device__ bf16 g_ctxh[T_TOK * NHEADS*VHD], g_ctxl[T_TOK * NHEADS*VHD];

// ---------------- common helpers ----------------
__device__ __forceinline__ uint32_t smem_u32(const void* p) {
    uint32_t a;
    asm("{ .reg .u64 t; cvta.to.shared.u64 t, %1; cvt.u32.u64 %0, t; }" : "=r"(a) : "l"(p));
    return a;
}
__device__ __forceinline__ void ldm4(uint32_t* r, uint32_t addr) {
    asm volatile("ldmatrix.sync.aligned.m8n8.x4.shared.b16 {%0,%1,%2,%3}, [%4];"
                 : "=r"(r[0]), "=r"(r[1]), "=r"(r[2]), "=r"(r[3]) : "r"(addr));
}
__device__ __forceinline__ void ldm4t(uint32_t* r, uint32_t addr) {
    asm volatile("ldmatrix.sync.aligned.m8n8.x4.trans.shared.b16 {%0,%1,%2,%3}, [%4];"
                 : "=r"(r[0]), "=r"(r[1]), "=r"(r[2]), "=r"(r[3]) : "r"(addr));
}
__device__ __forceinline__ void mma16816(float* d, const uint32_t* a, const uint32_t* b) {
    asm volatile("mma.sync.aligned.m16n8k16.row.col.f32.bf16.bf16.f32 "
                 "{%0,%1,%2,%3}, {%4,%5,%6,%7}, {%8,%9}, {%0,%1,%2,%3};"
                 : "+f"(d[0]), "+f"(d[1]), "+f"(d[2]), "+f"(d[3])
                 : "r"(a[0]), "r"(a[1]), "r"(a[2]), "r"(a[3]), "r"(b[0]), "r"(b[1]));
}
__device__ __forceinline__ void mma16816h(float* d, const uint32_t* a, const uint32_t* b) {
    asm volatile("mma.sync.aligned.m16n8k16.row.col.f32.f16.f16.f32 "
                 "{%0,%1,%2,%3}, {%4,%5,%6,%7}, {%8,%9}, {%0,%1,%2,%3};"
                 : "+f"(d[0]), "+f"(d[1]), "+f"(d[2]), "+f"(d[3])
                 : "r"(a[0]), "r"(a[1]), "r"(a[2]), "r"(a[3]), "r"(b[0]), "r"(b[1]));
}
__device__ __forceinline__ void cpa16(uint32_t dst, const void* src, uint32_t sz) {
    asm volatile("cp.async.cg.shared.global [%0], [%1], 16, %2;"
                 :: "r"(dst), "l"(src), "r"(sz) : "memory");
}
__device__ __forceinline__ void split1(float v, bf16& h, bf16& l) {
    h = __float2bfloat16_rn(v);
    l = __float2bfloat16_rn(v - __bfloat162float(h));
}
__device__ __forceinline__ void split1h(float v, __half& h, __half& l) {
    h = __float2half_rn(v);
    l = __float2half_rn(v - __half2float(h));
}

// ---------------- merged convert fp32 -> (hi, lo) bf16, 6 regions ----------------
struct Cvt6P {
    const float* x[6];
    bf16* h[6];
    bf16* l[6];
    int off[7];
};
__global__ void cvt6_kernel(Cvt6P P) {
    int i = blockIdx.x * blockDim.x + threadIdx.x;
    if (i >= P.off[6]) return;
    int r = 0;
#pragma unroll
    for (int k = 1; k < 6; ++k) if (i >= P.off[k]) r = k;
    int j = i - P.off[r];
    float4 v = ((const float4*)P.x[r])[j];
    bf16 h0,h1,h2,h3,l0,l1,l2,l3;
    split1(v.x,h0,l0); split1(v.y,h1,l1); split1(v.z,h2,l2); split1(v.w,h3,l3);
    bf162 hp0, hp1, lp0, lp1;
    hp0.x=h0; hp0.y=h1; hp1.x=h2; hp1.y=h3;
    lp0.x=l0; lp0.y=l1; lp1.x=l2; lp1.y=l3;
    uint2 hh, ll;
    hh.x=*(uint32_t*)&hp0; hh.y=*(uint32_t*)&hp1;
    ll.x=*(uint32_t*)&lp0; ll.y=*(uint32_t*)&lp1;
    ((uint2*)P.h[r])[j] = hh;
    ((uint2*)P.l[r])[j] = ll;
}

// ============================================================================
// bf16 split GEMM (128x128 CTA, 2 CTAs/SM), dual-problem launch.
// Epilogue modes: fp32 C | bf16 hi/lo | fp16 hi(/lo)
// ============================================================================
#define SMSTR 48
#define TILEB (128 * SMSTR)
#define STAGEB (4 * TILEB)
#define NSTAGE 4
#define GEMM_SMEM (NSTAGE * STAGEB)

struct GemmP {
    const bf16 *Ah, *Al, *Bh, *Bl;
    float* C;
    bf16 *Ch, *Cl;
    __half *Hh, *Hl;
    int N, K;
};

__global__ __launch_bounds__(256, 2) void bf_gemm_dual(GemmP P0, GemmP P1, int xsplit) {
    extern __shared__ char sm[];
    const bool first = ((int)blockIdx.x < xsplit);
    const GemmP p = first ? P0 : P1;
    const int n0 = (first ? blockIdx.x : (blockIdx.x - xsplit)) * 128;
    const int K = p.K, N = p.N;

    const int tid = threadIdx.x;
    const int wid = tid >> 5;
    const int lane = tid & 31;
    const int m0 = blockIdx.y * 128;
    const int nvalid = (N - n0 < 128) ? (N - n0) : 128;

    const uint32_t sbase = smem_u32(sm);
    const int wr = wid >> 2, wc = wid & 3;
    const uint32_t a_row = wr * 64 + (lane & 15);
    const uint32_t a_colb = (lane >> 4) * 16;
    const uint32_t b_row = wc * 32 + (lane & 7) + ((lane >> 4) << 3);
    const uint32_t b_colb = ((lane >> 3) & 1) * 16;

    float acc[4][4][4];
#pragma unroll
    for (int i = 0; i < 4; ++i)
#pragma unroll
        for (int j = 0; j < 4; ++j)
#pragma unroll
            for (int e = 0; e < 4; ++e) acc[i][j][e] = 0.f;

    const int nch = K >> 4;

    auto issue_chunk = [&](int c) {
        const int k0 = c << 4;
        const uint32_t stb = sbase + (c & (NSTAGE - 1)) * STAGEB;
#pragma unroll
        for (int i = 0; i < 4; ++i) {
            int u = tid + i * 256;
            int tile = u >> 8;
            int row = (u & 255) >> 1;
            int c16 = u & 1;
            uint32_t dst = stb + tile * TILEB + row * SMSTR + c16 * 16;
            const bf16* src;
            uint32_t sz = 16;
            if (tile == 0)      src = p.Ah + (size_t)(m0 + row) * K + k0 + c16 * 8;
            else if (tile == 1) src = p.Al + (size_t)(m0 + row) * K + k0 + c16 * 8;
            else {
                const bf16* base = (tile == 2) ? p.Bh : p.Bl;
                src = base + (size_t)(n0 + row) * K + k0 + c16 * 8;
                if (row >= nvalid) sz = 0;
            }
            cpa16(dst, src, sz);
        }
        asm volatile("cp.async.commit_group;" ::: "memory");
    };

    issue_chunk(0);
    if (nch > 1) issue_chunk(1); else asm volatile("cp.async.commit_group;" ::: "memory");
    if (nch > 2) issue_chunk(2); else asm volatile("cp.async.commit_group;" ::: "memory");

    for (int c = 0; c < nch; ++c) {
        asm volatile("cp.async.wait_group 2;" ::: "memory");
        __syncthreads();
        if (c + 3 < nch) issue_chunk(c + 3);
        else asm volatile("cp.async.commit_group;" ::: "memory");

        const uint32_t stb = sbase + (c & (NSTAGE - 1)) * STAGEB;
        uint32_t ah[4][4], bh[2][4];
#pragma unroll
        for (int i = 0; i < 4; ++i)
            ldm4(ah[i], stb + (a_row + i * 16) * SMSTR + a_colb);
#pragma unroll
        for (int jp = 0; jp < 2; ++jp)
            ldm4(bh[jp], stb + 2 * TILEB + (b_row + jp * 16) * SMSTR + b_colb);
#pragma unroll
        for (int i = 0; i < 4; ++i)
#pragma unroll
            for (int j = 0; j < 4; ++j)
                mma16816(acc[i][j], ah[i], &bh[j >> 1][(j & 1) * 2]);
        {
            uint32_t al[4][4];
#pragma unroll
            for (int i = 0; i < 4; ++i)
                ldm4(al[i], stb + TILEB + (a_row + i * 16) * SMSTR + a_colb);
#pragma unroll
            for (int i = 0; i < 4; ++i)
#pragma unroll
                for (int j = 0; j < 4; ++j)
                    mma16816(acc[i][j], al[i], &bh[j >> 1][(j & 1) * 2]);
        }
        {
            uint32_t bl[2][4];
#pragma unroll
            for (int jp = 0; jp < 2; ++jp)
                ldm4(bl[jp], stb + 3 * TILEB + (b_row + jp * 16) * SMSTR + b_colb);
#pragma unroll
            for (int i = 0; i < 4; ++i)
#pragma unroll
                for (int j = 0; j < 4; ++j)
                    mma16816(acc[i][j], ah[i], &bl[j >> 1][(j & 1) * 2]);
        }
    }

    const int gid = lane >> 2, tig = lane & 3;
#pragma unroll
    for (int i = 0; i < 4; ++i) {
#pragma unroll
        for (int rr = 0; rr < 2; ++rr) {
            int row = m0 + wr * 64 + i * 16 + gid + rr * 8;
#pragma unroll
            for (int j = 0; j < 4; ++j) {
                int col = n0 + wc * 32 + j * 8 + tig * 2;
                if (col < N) {
                    float v0 = acc[i][j][rr * 2], v1 = acc[i][j][rr * 2 + 1];
                    if (p.C) *(float2*)(p.C + (size_t)row * N + col) = make_float2(v0, v1);
                    if (p.Ch) {
                        bf162 hp, lp;
                        bf16 h0,l0,h1,l1;
                        split1(v0,h0,l0); split1(v1,h1,l1);
                        hp.x=h0; hp.y=h1; lp.x=l0; lp.y=l1;
                        *(uint32_t*)(p.Ch + (size_t)row * N + col) = *(uint32_t*)&hp;
                        *(uint32_t*)(p.Cl + (size_t)row * N + col) = *(uint32_t*)&lp;
                    }
                    if (p.Hh) {
                        __half h0,l0,h1,l1;
                        split1h(v0,h0,l0); split1h(v1,h1,l1);
                        __half2 hp = __halves2half2(h0, h1);
                        *(uint32_t*)(p.Hh + (size_t)row * N + col) = *(uint32_t*)&hp;
                        if (p.Hl) {
                            __half2 lp = __halves2half2(l0, l1);
                            *(uint32_t*)(p.Hl + (size_t)row * N + col) = *(uint32_t*)&lp;
                        }
                    }
                }
            }
        }
    }
}

// ---------------- dual RMSNorm -> bf16 hi/lo ----------------
struct RmsP {
    const float* x; const float* w;
    bf16 *yh, *yl;
    int D, in_stride;
};
__global__ void rmsnorm_dual(RmsP P0, RmsP P1) {
    const RmsP p = (blockIdx.y == 0) ? P0 : P1;
    const int row = blockIdx.x;
    const float* xr = p.x + (size_t)row * p.in_stride;
    float ss = 0.f;
    for (int d = threadIdx.x; d < p.D; d += blockDim.x) { float v = xr[d]; ss += v * v; }
    __shared__ float red[32];
#pragma unroll
    for (int o = 16; o; o >>= 1) ss += __shfl_xor_sync(0xffffffffu, ss, o);
    if ((threadIdx.x & 31) == 0) red[threadIdx.x >> 5] = ss;
    __syncthreads();
    if (threadIdx.x < 32) {
        float v = (threadIdx.x < (blockDim.x >> 5)) ? red[threadIdx.x] : 0.f;
#pragma unroll
        for (int o = 16; o; o >>= 1) v += __shfl_xor_sync(0xffffffffu, v, o);
        if (threadIdx.x == 0) red[0] = v;
    }
    __syncthreads();
    float scale = rsqrtf(red[0] / (float)p.D + 1e-6f);
    for (int d = threadIdx.x; d < p.D; d += blockDim.x) {
        float v = p.w[d] * xr[d] * scale;
        bf16 h, l; split1(v, h, l);
        p.yh[(size_t)row * p.D + d] = h;
        p.yl[(size_t)row * p.D + d] = l;
    }
}

// ---------------- YaRN ----------------
__device__ __forceinline__ void yarn_cs(int pos, int j, float& c, float& s) {
    float ex   = __expf(-(float)(2 * j) * (9.210340371976184f / 64.f));
    float fi   = ex * 0.025f;
    float ramp = ((float)j - 10.f) * (1.f / 13.f);
    ramp = fminf(fmaxf(ramp, 0.f), 1.f);
    float invf = fi * ramp + ex * (1.f - ramp);
    float ang  = (float)pos * invf;
    c = cosf(ang); s = sinf(ang);
}

__global__ void rope_k_kernel(const float* __restrict__ ckv, const int* __restrict__ pos_ids,
                              __half* __restrict__ kpe) {
    const int t = blockIdx.x;
    const int j = threadIdx.x;
    const int pos = pos_ids[t];
    const float* x = ckv + (size_t)t * KVW + KVLORA;
    float c, s; yarn_cs(pos, j, c, s);
    float x0 = x[2 * j], x1 = x[2 * j + 1];
    kpe[t * ROPE_D + j]      = __float2half_rn(x0 * c - x1 * s);
    kpe[t * ROPE_D + 32 + j] = __float2half_rn(x1 * c + x0 * s);
}

__global__ void rope_q_kernel(__half* __restrict__ qh, __half* __restrict__ ql,
                              const int* __restrict__ pos_ids) {
    const int t = blockIdx.x >> 4;
    const int h = blockIdx.x & 15;
    const int j = threadIdx.x;
    const int pos = pos_ids[t];
    __half* xh = qh + (size_t)t * (NHEADS * QHD) + h * QHD + NOPE;
    __half* xl = ql + (size_t)t * (NHEADS * QHD) + h * QHD + NOPE;
    float c, s; yarn_cs(pos, j, c, s);
    float x0 = __half2float(xh[2*j])   + __half2float(xl[2*j]);
    float x1 = __half2float(xh[2*j+1]) + __half2float(xl[2*j+1]);
    float r0 = x0 * c - x1 * s, r1 = x1 * c + x0 * s;
    __syncwarp();
    __half hh, ll;
    split1h(r0, hh, ll); xh[j] = hh;      xl[j] = ll;
    split1h(r1, hh, ll); xh[32 + j] = hh; xl[32 + j] = ll;
}

// ============================================================================
// Flash attention, fp16 HMMA. BM=128, BN=64, 8 warps.
// S = Qh*K + Ql*K (K fp16 single); O = Ph*V + Pl*V (V fp16 single).
// ============================================================================
#define FL_KSTR 400
#define FL_VSTR 272
#define FL_PSTR 144
#define FL_KVSTG (64 * FL_KSTR + 64 * FL_VSTR)      // 43008 (K + V, single)
#define FL_VOFF  (64 * FL_KSTR)
#define FL_QSTR 400
// Q staging: hi at 0, lo at 51200 (prologue only; overlaps KV stages)
#define FL_PH  102400                               // above Q staging & KV stages
#define FL_PL  (FL_PH + 128 * FL_PSTR)
#define FL_SMEM (FL_PL + 128 * FL_PSTR)             // 139264

__global__ __launch_bounds__(256, 1) void flash_mma(
    const __half* __restrict__ qh, const __half* __restrict__ ql,
    const __half* __restrict__ kv,
    const __half* __restrict__ kpe,
    bf16* __restrict__ ctxh, bf16* __restrict__ ctxl)
{
    extern __shared__ char sm[];
    const uint32_t sb = smem_u32(sm);
    const int qt = (int)gridDim.x - 1 - (int)blockIdx.x;
    const int hh = blockIdx.y, b = blockIdx.z;
    const int tid = threadIdx.x, wid = tid >> 5, lane = tid & 31;
    const int gid = lane >> 2, tig = lane & 3;
    const int t0 = b * S_LEN;

    const uint32_t a_row = wid * 16 + (lane & 15);
    const uint32_t a_colb = (lane >> 4) * 16;
    const uint32_t k_roff = (lane & 7) + ((lane >> 4) << 3);
    const uint32_t k_colb = ((lane >> 3) & 1) * 16;
    const uint32_t v_koff = (lane & 7) + ((lane >> 3) & 1) * 8;
    const uint32_t v_noff = (lane >> 4) * 8;

    // stage Q (hi+lo fp16) and pull fragments to registers
    for (int idx = tid; idx < 128 * 24; idx += 256) {
        int r = idx / 24, u = idx % 24;
        size_t g = (size_t)(t0 + qt * 128 + r) * (NHEADS * QHD) + hh * QHD + u * 8;
        *(uint4*)(sm + r * FL_QSTR + u * 16) = *(const uint4*)(qh + g);
        *(uint4*)(sm + 51200 + r * FL_QSTR + u * 16) = *(const uint4*)(ql + g);
    }
    __syncthreads();
    uint32_t qfh[12][4], qfl[12][4];
#pragma unroll
    for (int ks = 0; ks < 12; ++ks) {
        ldm4(qfh[ks], sb + a_row * FL_QSTR + a_colb + ks * 32);
        ldm4(qfl[ks], sb + 51200 + a_row * FL_QSTR + a_colb + ks * 32);
    }
    __syncthreads();

    auto issue_kv = [&](int kt) {
        const uint32_t stb = sb + (kt & 1) * FL_KVSTG;
        for (int idx = tid; idx < 64 * 24; idx += 256) {
            int r = idx / 24, u = idx % 24;
            int t = t0 + kt * 64 + r;
            const __half* src;
            if (u < 16) src = kv + (size_t)t * (NHEADS * 256) + hh * 256 + u * 8;
            else        src = kpe + (size_t)t * ROPE_D + (u - 16) * 8;
            cpa16(stb + r * FL_KSTR + u * 16, src, 16);
        }
        for (int idx = tid; idx < 64 * 16; idx += 256) {
            int r = idx >> 4, u = idx & 15;
            size_t g = (size_t)(t0 + kt * 64 + r) * (NHEADS * 256) + hh * 256 + 128 + u * 8;
            cpa16(stb + FL_VOFF + r * FL_VSTR + u * 16, kv + g, 16);
        }
        asm volatile("cp.async.commit_group;" ::: "memory");
    };

    float m_i[2], l_i[2], O[16][4];
    m_i[0] = m_i[1] = -1e30f; l_i[0] = l_i[1] = 0.f;
#pragma unroll
    for (int nf = 0; nf < 16; ++nf)
#pragma unroll
        for (int e = 0; e < 4; ++e) O[nf][e] = 0.f;

    const float mm = 0.1f * logf(40.f) + 1.f;
    const float sc = mm * mm * rsqrtf(192.f);

    const int nkt = 2 * qt + 2;
    issue_kv(0);

    for (int kt = 0; kt < nkt; ++kt) {
        if (kt + 1 < nkt) {
            issue_kv(kt + 1);
            asm volatile("cp.async.wait_group 1;" ::: "memory");
        } else {
            asm volatile("cp.async.wait_group 0;" ::: "memory");
        }
        __syncthreads();
        const uint32_t stb = sb + (kt & 1) * FL_KVSTG;

        // ---- QK: 2-term (K single) ----
        float s[8][4];
#pragma unroll
        for (int nf = 0; nf < 8; ++nf)
#pragma unroll
            for (int e = 0; e < 4; ++e) s[nf][e] = 0.f;

#pragma unroll
        for (int ks = 0; ks < 12; ++ks) {
#pragma unroll
            for (int jb = 0; jb < 4; ++jb) {
                uint32_t bh4[4];
                uint32_t brow = jb * 16 + k_roff;
                ldm4(bh4, stb + brow * FL_KSTR + k_colb + ks * 32);
                mma16816h(s[2*jb],   qfh[ks], &bh4[0]);
                mma16816h(s[2*jb+1], qfh[ks], &bh4[2]);
                mma16816h(s[2*jb],   qfl[ks], &bh4[0]);
                mma16816h(s[2*jb+1], qfl[ks], &bh4[2]);
            }
        }

        // ---- softmax ----
#pragma unroll
        for (int rr = 0; rr < 2; ++rr) {
            int grow = qt * 128 + wid * 16 + gid + rr * 8;
            float tmax = -1e30f;
#pragma unroll
            for (int nf = 0; nf < 8; ++nf) {
#pragma unroll
                for (int e = 0; e < 2; ++e) {
                    int gcol = kt * 64 + nf * 8 + tig * 2 + e;
                    float v = s[nf][rr * 2 + e] * sc;
                    if (gcol > grow) v = -1e30f;
                    s[nf][rr * 2 + e] = v;
                    tmax = fmaxf(tmax, v);
                }
            }
            tmax = fmaxf(tmax, __shfl_xor_sync(0xffffffffu, tmax, 1));
            tmax = fmaxf(tmax, __shfl_xor_sync(0xffffffffu, tmax, 2));
            float nm = fmaxf(m_i[rr], tmax);
            float fac = __expf(m_i[rr] - nm);
            float psum = 0.f;
#pragma unroll
            for (int nf = 0; nf < 8; ++nf) {
#pragma unroll
                for (int e = 0; e < 2; ++e) {
                    float p = __expf(s[nf][rr * 2 + e] - nm);
                    s[nf][rr * 2 + e] = p;
                    psum += p;
                }
            }
            psum += __shfl_xor_sync(0xffffffffu, psum, 1);
            psum += __shfl_xor_sync(0xffffffffu, psum, 2);
            l_i[rr] = l_i[rr] * fac + psum;
            m_i[rr] = nm;
#pragma unroll
            for (int nf = 0; nf < 16; ++nf) {
                O[nf][rr * 2] *= fac;
                O[nf][rr * 2 + 1] *= fac;
            }
        }

        // ---- P hi/lo (fp16) to smem ----
#pragma unroll
        for (int rr = 0; rr < 2; ++rr) {
            uint32_t prow = wid * 16 + gid + rr * 8;
#pragma unroll
            for (int nf = 0; nf < 8; ++nf) {
                __half h0,l0,h1,l1;
                split1h(s[nf][rr * 2], h0, l0);
                split1h(s[nf][rr * 2 + 1], h1, l1);
                __half2 hp = __halves2half2(h0, h1);
                __half2 lp = __halves2half2(l0, l1);
                uint32_t off = prow * FL_PSTR + (nf * 8 + tig * 2) * 2;
                *(uint32_t*)(sm + FL_PH + off) = *(uint32_t*)&hp;
                *(uint32_t*)(sm + FL_PL + off) = *(uint32_t*)&lp;
            }
        }
        __syncwarp();

        // ---- AV: 2-term (V single) ----
#pragma unroll
        for (int ks = 0; ks < 4; ++ks) {
            uint32_t aph[4], apl[4];
            ldm4(aph, sb + FL_PH + a_row * FL_PSTR + a_colb + ks * 32);
            ldm4(apl, sb + FL_PL + a_row * FL_PSTR + a_colb + ks * 32);
            uint32_t vrow = ks * 16 + v_koff;
#pragma unroll
            for (int nb = 0; nb < 8; ++nb) {
                uint32_t bvh[4];
                uint32_t vcol = (nb * 16 + v_noff) * 2;
                ldm4t(bvh, stb + FL_VOFF + vrow * FL_VSTR + vcol);
                mma16816h(O[2*nb],   aph, &bvh[0]);
                mma16816h(O[2*nb+1], aph, &bvh[2]);
                mma16816h(O[2*nb],   apl, &bvh[0]);
                mma16816h(O[2*nb+1], apl, &bvh[2]);
            }
        }
        __syncthreads();
    }

    // ---- epilogue: ctx bf16 hi/lo ----
#pragma unroll
    for (int rr = 0; rr < 2; ++rr) {
        float inv = 1.f / l_i[rr];
        int row = t0 + qt * 128 + wid * 16 + gid + rr * 8;
#pragma unroll
        for (int nf = 0; nf < 16; ++nf) {
            int col = nf * 8 + tig * 2;
            float v0 = O[nf][rr * 2] * inv, v1 = O[nf][rr * 2 + 1] * inv;
            bf16 h0,l0,h1,l1;
            split1(v0, h0, l0); split1(v1, h1, l1);
            bf162 hp, lp; hp.x=h0; hp.y=h1; lp.x=l0; lp.y=l1;
            size_t g = (size_t)row * (NHEADS * VHD) + hh * VHD + col;
            *(uint32_t*)(ctxh + g) = *(uint32_t*)&hp;
            *(uint32_t*)(ctxl + g) = *(uint32_t*)&lp;
        }
    }
}

// ---------------- launch ----------------
extern "C" void kernel_launch(void* const* d_in, const int* in_sizes, int n_in,
                              void* d_out, int out_size) {
    (void)in_sizes; (void)n_in; (void)out_size;
    const float* X     = (const float*)d_in[0];
    const int*   pos   = (const int*)  d_in[1];
    const float* wq_a  = (const float*)d_in[2];
    const float* qln   = (const float*)d_in[3];
    const float* wq_b  = (const float*)d_in[4];
    const float* wkv_a = (const float*)d_in[5];
    const float* kvln  = (const float*)d_in[6];
    const float* wkv_b = (const float*)d_in[7];
    const float* wo    = (const float*)d_in[8];
    float* out = (float*)d_out;

    float *qa, *ckv;
    bf16 *Xh,*Xl,*wqah,*wqal,*wqbh,*wqbl,*wkvah,*wkval,*wkvbh,*wkvbl,*woh,*wol;
    bf16 *qanh,*qanl,*ckvnh,*ckvnl,*ctxh,*ctxl;
    __half *q16h,*q16l,*kv16,*kpe16;
    cudaGetSymbolAddress((void**)&qa, g_qa);
    cudaGetSymbolAddress((void**)&ckv, g_ckv);
    cudaGetSymbolAddress((void**)&Xh, g_Xh);     cudaGetSymbolAddress((void**)&Xl, g_Xl);
    cudaGetSymbolAddress((void**)&wqah, g_wqa_h); cudaGetSymbolAddress((void**)&wqal, g_wqa_l);
    cudaGetSymbolAddress((void**)&wqbh, g_wqb_h); cudaGetSymbolAddress((void**)&wqbl, g_wqb_l);
    cudaGetSymbolAddress((void**)&wkvah, g_wkva_h); cudaGetSymbolAddress((void**)&wkval, g_wkva_l);
    cudaGetSymbolAddress((void**)&wkvbh, g_wkvb_h); cudaGetSymbolAddress((void**)&wkvbl, g_wkvb_l);
    cudaGetSymbolAddress((void**)&woh, g_wo_h);  cudaGetSymbolAddress((void**)&wol, g_wo_l);
    cudaGetSymbolAddress((void**)&qanh, g_qan_h); cudaGetSymbolAddress((void**)&qanl, g_qan_l);
    cudaGetSymbolAddress((void**)&ckvnh, g_ckvn_h); cudaGetSymbolAddress((void**)&ckvnl, g_ckvn_l);
    cudaGetSymbolAddress((void**)&q16h, g_q16h); cudaGetSymbolAddress((void**)&q16l, g_q16l);
    cudaGetSymbolAddress((void**)&kv16, g_kv16);
    cudaGetSymbolAddress((void**)&kpe16, g_kpe16);
    cudaGetSymbolAddress((void**)&ctxh, g_ctxh); cudaGetSymbolAddress((void**)&ctxl, g_ctxl);

    cudaFuncSetAttribute(bf_gemm_dual, cudaFuncAttributeMaxDynamicSharedMemorySize, GEMM_SMEM);
    cudaFuncSetAttribute(flash_mma, cudaFuncAttributeMaxDynamicSharedMemorySize, FL_SMEM);

    const dim3 blk(256);
    const int mt = T_TOK / 128;  // 32

    // merged input conversions
    {
        Cvt6P P;
        P.x[0]=X;     P.h[0]=Xh;    P.l[0]=Xl;
        P.x[1]=wq_a;  P.h[1]=wqah;  P.l[1]=wqal;
        P.x[2]=wq_b;  P.h[2]=wqbh;  P.l[2]=wqbl;
        P.x[3]=wkv_a; P.h[3]=wkvah; P.l[3]=wkval;
        P.x[4]=wkv_b; P.h[4]=wkvbh; P.l[4]=wkvbl;
        P.x[5]=wo;    P.h[5]=woh;   P.l[5]=wol;
        int lens[6] = { T_TOK*HIDDEN/4, QLORA*HIDDEN/4, NHEADS*QHD*QLORA/4,
                        KVW*HIDDEN/4, NHEADS*256*KVLORA/4, HIDDEN*NHEADS*VHD/4 };
        P.off[0] = 0;
        for (int i = 0; i < 6; ++i) P.off[i+1] = P.off[i] + lens[i];
        cvt6_kernel<<<(P.off[6] + 255) / 256, 256>>>(P);
    }

    // fused a-projections
    {
        GemmP p0 = { Xh, Xl, wqah, wqal, qa, nullptr, nullptr, nullptr, nullptr, QLORA, HIDDEN };
        GemmP p1 = { Xh, Xl, wkvah, wkval, ckv, nullptr, nullptr, nullptr, nullptr, KVW, HIDDEN };
        bf_gemm_dual<<<dim3(QLORA/128 + (KVW+127)/128, mt), blk, GEMM_SMEM>>>(p0, p1, QLORA/128);
    }

    // fused rmsnorms
    {
        RmsP p0 = { qa, qln, qanh, qanl, QLORA, QLORA };
        RmsP p1 = { ckv, kvln, ckvnh, ckvnl, KVLORA, KVW };
        rmsnorm_dual<<<dim3(T_TOK, 2), 256>>>(p0, p1);
    }
    rope_k_kernel<<<T_TOK, 32>>>(ckv, pos, kpe16);

    // fused b-projections: q -> fp16 hi/lo ; kv -> fp16 hi only
    {
        GemmP p0 = { qanh, qanl, wqbh, wqbl, nullptr, nullptr, nullptr, q16h, q16l,
                     NHEADS*QHD, QLORA };
        GemmP p1 = { ckvnh, ckvnl, wkvbh, wkvbl, nullptr, nullptr, nullptr, kv16, nullptr,
                     NHEADS*256, KVLORA };
        bf_gemm_dual<<<dim3((NHEADS*QHD)/128 + (NHEADS*256)/128, mt), blk, GEMM_SMEM>>>(
            p0, p1, (NHEADS*QHD)/128);
    }

    rope_q_kernel<<<T_TOK * NHEADS, 32>>>(q16h, q16l, pos);

    flash_mma<<<dim3(S_LEN / 128, NHEADS, BATCH), blk, FL_SMEM>>>(q16h, q16l, kv16, kpe16,
                                                                  ctxh, ctxl);

    // output projection
    {
        GemmP p0 = { ctxh, ctxl, woh, wol, out, nullptr, nullptr, nullptr, nullptr,
                     HIDDEN, NHEADS*VHD };
        bf_gemm_dual<<<dim3(HIDDEN/128, mt), blk, GEMM_SMEM>>>(p0, p0, HIDDEN/128);
    }
}

// round 9
// speedup vs baseline: 2.4787x; 1.3011x over previous
#include <cuda_runtime.h>
#include <cuda_bf16.h>
#include <cuda_fp16.h>
#include <math.h>
#include <stdint.h>

// ---------------- problem constants ----------------
#define S_LEN   2048
#define BATCH   2
#define T_TOK   (BATCH * S_LEN)
#define HIDDEN  2048
#define QLORA   1536
#define KVLORA  512
#define NHEADS  16
#define NOPE    128
#define ROPE_D  64
#define QHD     192
#define VHD     128
#define KVW     576

// ---------------- scratch ----------------
__device__ float g_qa [T_TOK * QLORA];
__device__ float g_ckv[T_TOK * KVW];

__device__ __half g_Xh[T_TOK * HIDDEN],  g_Xl[T_TOK * HIDDEN];
__device__ __half g_wqa16[QLORA * HIDDEN];
__device__ __half g_wqb16[NHEADS*QHD*QLORA];
__device__ __half g_wkva16[KVW * HIDDEN];
__device__ __half g_wkvb16[NHEADS*256*KVLORA];
__device__ __half g_wo16[HIDDEN*NHEADS*VHD];
__device__ __half g_qan_h[T_TOK * QLORA],  g_qan_l[T_TOK * QLORA];
__device__ __half g_ckvn_h[T_TOK * KVLORA], g_ckvn_l[T_TOK * KVLORA];
__device__ __half g_q16h[T_TOK * NHEADS * QHD], g_q16l[T_TOK * NHEADS * QHD];
__device__ __half g_kv16[T_TOK * NHEADS * 256];
__device__ __half g_kpe16[T_TOK * ROPE_D];
__device__ __half g_ctxh[T_TOK * NHEADS*VHD], g_ctxl[T_TOK * NHEADS*VHD];

// ---------------- common helpers ----------------
__device__ __forceinline__ uint32_t smem_u32(const void* p) {
    uint32_t a;
    asm("{ .reg .u64 t; cvta.to.shared.u64 t, %1; cvt.u32.u64 %0, t; }" : "=r"(a) : "l"(p));
    return a;
}
__device__ __forceinline__ void ldm4(uint32_t* r, uint32_t addr) {
    asm volatile("ldmatrix.sync.aligned.m8n8.x4.shared.b16 {%0,%1,%2,%3}, [%4];"
                 : "=r"(r[0]), "=r"(r[1]), "=r"(r[2]), "=r"(r[3]) : "r"(addr));
}
__device__ __forceinline__ void ldm4t(uint32_t* r, uint32_t addr) {
    asm volatile("ldmatrix.sync.aligned.m8n8.x4.trans.shared.b16 {%0,%1,%2,%3}, [%4];"
                 : "=r"(r[0]), "=r"(r[1]), "=r"(r[2]), "=r"(r[3]) : "r"(addr));
}
__device__ __forceinline__ void mma16816h(float* d, const uint32_t* a, const uint32_t* b) {
    asm volatile("mma.sync.aligned.m16n8k16.row.col.f32.f16.f16.f32 "
                 "{%0,%1,%2,%3}, {%4,%5,%6,%7}, {%8,%9}, {%0,%1,%2,%3};"
                 : "+f"(d[0]), "+f"(d[1]), "+f"(d[2]), "+f"(d[3])
                 : "r"(a[0]), "r"(a[1]), "r"(a[2]), "r"(a[3]), "r"(b[0]), "r"(b[1]));
}
__device__ __forceinline__ void cpa16(uint32_t dst, const void* src, uint32_t sz) {
    asm volatile("cp.async.cg.shared.global [%0], [%1], 16, %2;"
                 :: "r"(dst), "l"(src), "r"(sz) : "memory");
}
__device__ __forceinline__ void split1h(float v, __half& h, __half& l) {
    h = __float2half_rn(v);
    l = __float2half_rn(v - __half2float(h));
}

// ---------------- merged convert fp32 -> fp16 (hi[,lo]), 6 regions ----------------
struct Cvt6P {
    const float* x[6];
    __half* h[6];
    __half* l[6];     // nullptr -> single-precision only
    int off[7];       // prefix sums, float4 units
};
__global__ void cvt6_kernel(Cvt6P P) {
    int i = blockIdx.x * blockDim.x + threadIdx.x;
    if (i >= P.off[6]) return;
    int r = 0;
#pragma unroll
    for (int k = 1; k < 6; ++k) if (i >= P.off[k]) r = k;
    int j = i - P.off[r];
    float4 v = ((const float4*)P.x[r])[j];
    __half h0,h1,h2,h3,l0,l1,l2,l3;
    split1h(v.x,h0,l0); split1h(v.y,h1,l1); split1h(v.z,h2,l2); split1h(v.w,h3,l3);
    __half2 hp0 = __halves2half2(h0,h1), hp1 = __halves2half2(h2,h3);
    uint2 hh; hh.x = *(uint32_t*)&hp0; hh.y = *(uint32_t*)&hp1;
    ((uint2*)P.h[r])[j] = hh;
    if (P.l[r]) {
        __half2 lp0 = __halves2half2(l0,l1), lp1 = __halves2half2(l2,l3);
        uint2 ll; ll.x = *(uint32_t*)&lp0; ll.y = *(uint32_t*)&lp1;
        ((uint2*)P.l[r])[j] = ll;
    }
}

// ============================================================================
// fp16 GEMM: C = (Ah+Al) * B^T, A 2-term, B single. 128x128 CTA, 2 CTAs/SM.
// BK=16, 4-stage cp.async (3 tiles/stage), one sync per chunk, 8 warps.
// ============================================================================
#define SMSTR 48
#define TILEB (128 * SMSTR)           // 6144
#define STAGEB (3 * TILEB)            // 18432 (Ah, Al, B)
#define NSTAGE 4
#define GEMM_SMEM (NSTAGE * STAGEB)   // 73728

struct GemmP {
    const __half *Ah, *Al, *B;
    float* C;
    __half *Hh, *Hl;      // fp16 hi/lo outputs (Hl nullable)
    int N, K;
};

__global__ __launch_bounds__(256, 2) void fp_gemm_dual(GemmP P0, GemmP P1, int xsplit) {
    extern __shared__ char sm[];
    const bool first = ((int)blockIdx.x < xsplit);
    const GemmP p = first ? P0 : P1;
    const int n0 = (first ? blockIdx.x : (blockIdx.x - xsplit)) * 128;
    const int K = p.K, N = p.N;

    const int tid = threadIdx.x;
    const int wid = tid >> 5;
    const int lane = tid & 31;
    const int m0 = blockIdx.y * 128;
    const int nvalid = (N - n0 < 128) ? (N - n0) : 128;

    const uint32_t sbase = smem_u32(sm);
    const int wr = wid >> 2, wc = wid & 3;
    const uint32_t a_row = wr * 64 + (lane & 15);
    const uint32_t a_colb = (lane >> 4) * 16;
    const uint32_t b_row = wc * 32 + (lane & 7) + ((lane >> 4) << 3);
    const uint32_t b_colb = ((lane >> 3) & 1) * 16;

    float acc[4][4][4];
#pragma unroll
    for (int i = 0; i < 4; ++i)
#pragma unroll
        for (int j = 0; j < 4; ++j)
#pragma unroll
            for (int e = 0; e < 4; ++e) acc[i][j][e] = 0.f;

    const int nch = K >> 4;

    // copy: 768 x 16B units per chunk, 3 per thread
    auto issue_chunk = [&](int c) {
        const int k0 = c << 4;
        const uint32_t stb = sbase + (c & (NSTAGE - 1)) * STAGEB;
#pragma unroll
        for (int i = 0; i < 3; ++i) {
            int u = tid + i * 256;
            int tile = u >> 8;              // 0=Ah 1=Al 2=B
            int row = (u & 255) >> 1;
            int c16 = u & 1;
            uint32_t dst = stb + tile * TILEB + row * SMSTR + c16 * 16;
            const __half* src;
            uint32_t sz = 16;
            if (tile == 0)      src = p.Ah + (size_t)(m0 + row) * K + k0 + c16 * 8;
            else if (tile == 1) src = p.Al + (size_t)(m0 + row) * K + k0 + c16 * 8;
            else {
                src = p.B + (size_t)(n0 + row) * K + k0 + c16 * 8;
                if (row >= nvalid) sz = 0;
            }
            cpa16(dst, src, sz);
        }
        asm volatile("cp.async.commit_group;" ::: "memory");
    };

    issue_chunk(0);
    if (nch > 1) issue_chunk(1); else asm volatile("cp.async.commit_group;" ::: "memory");
    if (nch > 2) issue_chunk(2); else asm volatile("cp.async.commit_group;" ::: "memory");

    for (int c = 0; c < nch; ++c) {
        asm volatile("cp.async.wait_group 2;" ::: "memory");
        __syncthreads();
        if (c + 3 < nch) issue_chunk(c + 3);
        else asm volatile("cp.async.commit_group;" ::: "memory");

        const uint32_t stb = sbase + (c & (NSTAGE - 1)) * STAGEB;
        uint32_t ah[4][4], bh[2][4];
#pragma unroll
        for (int i = 0; i < 4; ++i)
            ldm4(ah[i], stb + (a_row + i * 16) * SMSTR + a_colb);
#pragma unroll
        for (int jp = 0; jp < 2; ++jp)
            ldm4(bh[jp], stb + 2 * TILEB + (b_row + jp * 16) * SMSTR + b_colb);
#pragma unroll
        for (int i = 0; i < 4; ++i)
#pragma unroll
            for (int j = 0; j < 4; ++j)
                mma16816h(acc[i][j], ah[i], &bh[j >> 1][(j & 1) * 2]);
        {
            uint32_t al[4][4];
#pragma unroll
            for (int i = 0; i < 4; ++i)
                ldm4(al[i], stb + TILEB + (a_row + i * 16) * SMSTR + a_colb);
#pragma unroll
            for (int i = 0; i < 4; ++i)
#pragma unroll
                for (int j = 0; j < 4; ++j)
                    mma16816h(acc[i][j], al[i], &bh[j >> 1][(j & 1) * 2]);
        }
    }

    const int gid = lane >> 2, tig = lane & 3;
#pragma unroll
    for (int i = 0; i < 4; ++i) {
#pragma unroll
        for (int rr = 0; rr < 2; ++rr) {
            int row = m0 + wr * 64 + i * 16 + gid + rr * 8;
#pragma unroll
            for (int j = 0; j < 4; ++j) {
                int col = n0 + wc * 32 + j * 8 + tig * 2;
                if (col < N) {
                    float v0 = acc[i][j][rr * 2], v1 = acc[i][j][rr * 2 + 1];
                    if (p.C) *(float2*)(p.C + (size_t)row * N + col) = make_float2(v0, v1);
                    if (p.Hh) {
                        __half h0,l0,h1,l1;
                        split1h(v0,h0,l0); split1h(v1,h1,l1);
                        __half2 hp = __halves2half2(h0, h1);
                        *(uint32_t*)(p.Hh + (size_t)row * N + col) = *(uint32_t*)&hp;
                        if (p.Hl) {
                            __half2 lp = __halves2half2(l0, l1);
                            *(uint32_t*)(p.Hl + (size_t)row * N + col) = *(uint32_t*)&lp;
                        }
                    }
                }
            }
        }
    }
}

// ---------------- dual RMSNorm -> fp16 hi/lo ----------------
struct RmsP {
    const float* x; const float* w;
    __half *yh, *yl;
    int D, in_stride;
};
__global__ void rmsnorm_dual(RmsP P0, RmsP P1) {
    const RmsP p = (blockIdx.y == 0) ? P0 : P1;
    const int row = blockIdx.x;
    const float* xr = p.x + (size_t)row * p.in_stride;
    float ss = 0.f;
    for (int d = threadIdx.x; d < p.D; d += blockDim.x) { float v = xr[d]; ss += v * v; }
    __shared__ float red[32];
#pragma unroll
    for (int o = 16; o; o >>= 1) ss += __shfl_xor_sync(0xffffffffu, ss, o);
    if ((threadIdx.x & 31) == 0) red[threadIdx.x >> 5] = ss;
    __syncthreads();
    if (threadIdx.x < 32) {
        float v = (threadIdx.x < (blockDim.x >> 5)) ? red[threadIdx.x] : 0.f;
#pragma unroll
        for (int o = 16; o; o >>= 1) v += __shfl_xor_sync(0xffffffffu, v, o);
        if (threadIdx.x == 0) red[0] = v;
    }
    __syncthreads();
    float scale = rsqrtf(red[0] / (float)p.D + 1e-6f);
    for (int d = threadIdx.x; d < p.D; d += blockDim.x) {
        float v = p.w[d] * xr[d] * scale;
        __half h, l; split1h(v, h, l);
        p.yh[(size_t)row * p.D + d] = h;
        p.yl[(size_t)row * p.D + d] = l;
    }
}

// ---------------- YaRN ----------------
__device__ __forceinline__ void yarn_cs(int pos, int j, float& c, float& s) {
    float ex   = __expf(-(float)(2 * j) * (9.210340371976184f / 64.f));
    float fi   = ex * 0.025f;
    float ramp = ((float)j - 10.f) * (1.f / 13.f);
    ramp = fminf(fmaxf(ramp, 0.f), 1.f);
    float invf = fi * ramp + ex * (1.f - ramp);
    float ang  = (float)pos * invf;
    c = cosf(ang); s = sinf(ang);
}

__global__ void rope_k_kernel(const float* __restrict__ ckv, const int* __restrict__ pos_ids,
                              __half* __restrict__ kpe) {
    const int t = blockIdx.x;
    const int j = threadIdx.x;
    const int pos = pos_ids[t];
    const float* x = ckv + (size_t)t * KVW + KVLORA;
    float c, s; yarn_cs(pos, j, c, s);
    float x0 = x[2 * j], x1 = x[2 * j + 1];
    kpe[t * ROPE_D + j]      = __float2half_rn(x0 * c - x1 * s);
    kpe[t * ROPE_D + 32 + j] = __float2half_rn(x1 * c + x0 * s);
}

__global__ void rope_q_kernel(__half* __restrict__ qh, __half* __restrict__ ql,
                              const int* __restrict__ pos_ids) {
    const int t = blockIdx.x >> 4;
    const int h = blockIdx.x & 15;
    const int j = threadIdx.x;
    const int pos = pos_ids[t];
    __half* xh = qh + (size_t)t * (NHEADS * QHD) + h * QHD + NOPE;
    __half* xl = ql + (size_t)t * (NHEADS * QHD) + h * QHD + NOPE;
    float c, s; yarn_cs(pos, j, c, s);
    float x0 = __half2float(xh[2*j])   + __half2float(xl[2*j]);
    float x1 = __half2float(xh[2*j+1]) + __half2float(xl[2*j+1]);
    float r0 = x0 * c - x1 * s, r1 = x1 * c + x0 * s;
    __syncwarp();
    __half hh, ll;
    split1h(r0, hh, ll); xh[j] = hh;      xl[j] = ll;
    split1h(r1, hh, ll); xh[32 + j] = hh; xl[32 + j] = ll;
}

// ============================================================================
// Flash attention, fp16 HMMA. BM=128, BN=64, 8 warps. (R8, ctx output fp16)
// ============================================================================
#define FL_KSTR 400
#define FL_VSTR 272
#define FL_PSTR 144
#define FL_KVSTG (64 * FL_KSTR + 64 * FL_VSTR)
#define FL_VOFF  (64 * FL_KSTR)
#define FL_QSTR 400
#define FL_PH  102400
#define FL_PL  (FL_PH + 128 * FL_PSTR)
#define FL_SMEM (FL_PL + 128 * FL_PSTR)

__global__ __launch_bounds__(256, 1) void flash_mma(
    const __half* __restrict__ qh, const __half* __restrict__ ql,
    const __half* __restrict__ kv,
    const __half* __restrict__ kpe,
    __half* __restrict__ ctxh, __half* __restrict__ ctxl)
{
    extern __shared__ char sm[];
    const uint32_t sb = smem_u32(sm);
    const int qt = (int)gridDim.x - 1 - (int)blockIdx.x;
    const int hh = blockIdx.y, b = blockIdx.z;
    const int tid = threadIdx.x, wid = tid >> 5, lane = tid & 31;
    const int gid = lane >> 2, tig = lane & 3;
    const int t0 = b * S_LEN;

    const uint32_t a_row = wid * 16 + (lane & 15);
    const uint32_t a_colb = (lane >> 4) * 16;
    const uint32_t k_roff = (lane & 7) + ((lane >> 4) << 3);
    const uint32_t k_colb = ((lane >> 3) & 1) * 16;
    const uint32_t v_koff = (lane & 7) + ((lane >> 3) & 1) * 8;
    const uint32_t v_noff = (lane >> 4) * 8;

    for (int idx = tid; idx < 128 * 24; idx += 256) {
        int r = idx / 24, u = idx % 24;
        size_t g = (size_t)(t0 + qt * 128 + r) * (NHEADS * QHD) + hh * QHD + u * 8;
        *(uint4*)(sm + r * FL_QSTR + u * 16) = *(const uint4*)(qh + g);
        *(uint4*)(sm + 51200 + r * FL_QSTR + u * 16) = *(const uint4*)(ql + g);
    }
    __syncthreads();
    uint32_t qfh[12][4], qfl[12][4];
#pragma unroll
    for (int ks = 0; ks < 12; ++ks) {
        ldm4(qfh[ks], sb + a_row * FL_QSTR + a_colb + ks * 32);
        ldm4(qfl[ks], sb + 51200 + a_row * FL_QSTR + a_colb + ks * 32);
    }
    __syncthreads();

    auto issue_kv = [&](int kt) {
        const uint32_t stb = sb + (kt & 1) * FL_KVSTG;
        for (int idx = tid; idx < 64 * 24; idx += 256) {
            int r = idx / 24, u = idx % 24;
            int t = t0 + kt * 64 + r;
            const __half* src;
            if (u < 16) src = kv + (size_t)t * (NHEADS * 256) + hh * 256 + u * 8;
            else        src = kpe + (size_t)t * ROPE_D + (u - 16) * 8;
            cpa16(stb + r * FL_KSTR + u * 16, src, 16);
        }
        for (int idx = tid; idx < 64 * 16; idx += 256) {
            int r = idx >> 4, u = idx & 15;
            size_t g = (size_t)(t0 + kt * 64 + r) * (NHEADS * 256) + hh * 256 + 128 + u * 8;
            cpa16(stb + FL_VOFF + r * FL_VSTR + u * 16, kv + g, 16);
        }
        asm volatile("cp.async.commit_group;" ::: "memory");
    };

    float m_i[2], l_i[2], O[16][4];
    m_i[0] = m_i[1] = -1e30f; l_i[0] = l_i[1] = 0.f;
#pragma unroll
    for (int nf = 0; nf < 16; ++nf)
#pragma unroll
        for (int e = 0; e < 4; ++e) O[nf][e] = 0.f;

    const float mm = 0.1f * logf(40.f) + 1.f;
    const float sc = mm * mm * rsqrtf(192.f);

    const int nkt = 2 * qt + 2;
    issue_kv(0);

    for (int kt = 0; kt < nkt; ++kt) {
        if (kt + 1 < nkt) {
            issue_kv(kt + 1);
            asm volatile("cp.async.wait_group 1;" ::: "memory");
        } else {
            asm volatile("cp.async.wait_group 0;" ::: "memory");
        }
        __syncthreads();
        const uint32_t stb = sb + (kt & 1) * FL_KVSTG;

        float s[8][4];
#pragma unroll
        for (int nf = 0; nf < 8; ++nf)
#pragma unroll
            for (int e = 0; e < 4; ++e) s[nf][e] = 0.f;

#pragma unroll
        for (int ks = 0; ks < 12; ++ks) {
#pragma unroll
            for (int jb = 0; jb < 4; ++jb) {
                uint32_t bh4[4];
                uint32_t brow = jb * 16 + k_roff;
                ldm4(bh4, stb + brow * FL_KSTR + k_colb + ks * 32);
                mma16816h(s[2*jb],   qfh[ks], &bh4[0]);
                mma16816h(s[2*jb+1], qfh[ks], &bh4[2]);
                mma16816h(s[2*jb],   qfl[ks], &bh4[0]);
                mma16816h(s[2*jb+1], qfl[ks], &bh4[2]);
            }
        }

#pragma unroll
        for (int rr = 0; rr < 2; ++rr) {
            int grow = qt * 128 + wid * 16 + gid + rr * 8;
            float tmax = -1e30f;
#pragma unroll
            for (int nf = 0; nf < 8; ++nf) {
#pragma unroll
                for (int e = 0; e < 2; ++e) {
                    int gcol = kt * 64 + nf * 8 + tig * 2 + e;
                    float v = s[nf][rr * 2 + e] * sc;
                    if (gcol > grow) v = -1e30f;
                    s[nf][rr * 2 + e] = v;
                    tmax = fmaxf(tmax, v);
                }
            }
            tmax = fmaxf(tmax, __shfl_xor_sync(0xffffffffu, tmax, 1));
            tmax = fmaxf(tmax, __shfl_xor_sync(0xffffffffu, tmax, 2));
            float nm = fmaxf(m_i[rr], tmax);
            float fac = __expf(m_i[rr] - nm);
            float psum = 0.f;
#pragma unroll
            for (int nf = 0; nf < 8; ++nf) {
#pragma unroll
                for (int e = 0; e < 2; ++e) {
                    float p = __expf(s[nf][rr * 2 + e] - nm);
                    s[nf][rr * 2 + e] = p;
                    psum += p;
                }
            }
            psum += __shfl_xor_sync(0xffffffffu, psum, 1);
            psum += __shfl_xor_sync(0xffffffffu, psum, 2);
            l_i[rr] = l_i[rr] * fac + psum;
            m_i[rr] = nm;
#pragma unroll
            for (int nf = 0; nf < 16; ++nf) {
                O[nf][rr * 2] *= fac;
                O[nf][rr * 2 + 1] *= fac;
            }
        }

#pragma unroll
        for (int rr = 0; rr < 2; ++rr) {
            uint32_t prow = wid * 16 + gid + rr * 8;
#pragma unroll
            for (int nf = 0; nf < 8; ++nf) {
                __half h0,l0,h1,l1;
                split1h(s[nf][rr * 2], h0, l0);
                split1h(s[nf][rr * 2 + 1], h1, l1);
                __half2 hp = __halves2half2(h0, h1);
                __half2 lp = __halves2half2(l0, l1);
                uint32_t off = prow * FL_PSTR + (nf * 8 + tig * 2) * 2;
                *(uint32_t*)(sm + FL_PH + off) = *(uint32_t*)&hp;
                *(uint32_t*)(sm + FL_PL + off) = *(uint32_t*)&lp;
            }
        }
        __syncwarp();

#pragma unroll
        for (int ks = 0; ks < 4; ++ks) {
            uint32_t aph[4], apl[4];
            ldm4(aph, sb + FL_PH + a_row * FL_PSTR + a_colb + ks * 32);
            ldm4(apl, sb + FL_PL + a_row * FL_PSTR + a_colb + ks * 32);
            uint32_t vrow = ks * 16 + v_koff;
#pragma unroll
            for (int nb = 0; nb < 8; ++nb) {
                uint32_t bvh[4];
                uint32_t vcol = (nb * 16 + v_noff) * 2;
                ldm4t(bvh, stb + FL_VOFF + vrow * FL_VSTR + vcol);
                mma16816h(O[2*nb],   aph, &bvh[0]);
                mma16816h(O[2*nb+1], aph, &bvh[2]);
                mma16816h(O[2*nb],   apl, &bvh[0]);
                mma16816h(O[2*nb+1], apl, &bvh[2]);
            }
        }
        __syncthreads();
    }

#pragma unroll
    for (int rr = 0; rr < 2; ++rr) {
        float inv = 1.f / l_i[rr];
        int row = t0 + qt * 128 + wid * 16 + gid + rr * 8;
#pragma unroll
        for (int nf = 0; nf < 16; ++nf) {
            int col = nf * 8 + tig * 2;
            float v0 = O[nf][rr * 2] * inv, v1 = O[nf][rr * 2 + 1] * inv;
            __half h0,l0,h1,l1;
            split1h(v0, h0, l0); split1h(v1, h1, l1);
            __half2 hp = __halves2half2(h0, h1);
            __half2 lp = __halves2half2(l0, l1);
            size_t g = (size_t)row * (NHEADS * VHD) + hh * VHD + col;
            *(uint32_t*)(ctxh + g) = *(uint32_t*)&hp;
            *(uint32_t*)(ctxl + g) = *(uint32_t*)&lp;
        }
    }
}

// ---------------- launch ----------------
extern "C" void kernel_launch(void* const* d_in, const int* in_sizes, int n_in,
                              void* d_out, int out_size) {
    (void)in_sizes; (void)n_in; (void)out_size;
    const float* X     = (const float*)d_in[0];
    const int*   pos   = (const int*)  d_in[1];
    const float* wq_a  = (const float*)d_in[2];
    const float* qln   = (const float*)d_in[3];
    const float* wq_b  = (const float*)d_in[4];
    const float* wkv_a = (const float*)d_in[5];
    const float* kvln  = (const float*)d_in[6];
    const float* wkv_b = (const float*)d_in[7];
    const float* wo    = (const float*)d_in[8];
    float* out = (float*)d_out;

    float *qa, *ckv;
    __half *Xh,*Xl,*wqa16,*wqb16,*wkva16,*wkvb16,*wo16;
    __half *qanh,*qanl,*ckvnh,*ckvnl,*q16h,*q16l,*kv16,*kpe16,*ctxh,*ctxl;
    cudaGetSymbolAddress((void**)&qa, g_qa);
    cudaGetSymbolAddress((void**)&ckv, g_ckv);
    cudaGetSymbolAddress((void**)&Xh, g_Xh);       cudaGetSymbolAddress((void**)&Xl, g_Xl);
    cudaGetSymbolAddress((void**)&wqa16, g_wqa16);
    cudaGetSymbolAddress((void**)&wqb16, g_wqb16);
    cudaGetSymbolAddress((void**)&wkva16, g_wkva16);
    cudaGetSymbolAddress((void**)&wkvb16, g_wkvb16);
    cudaGetSymbolAddress((void**)&wo16, g_wo16);
    cudaGetSymbolAddress((void**)&qanh, g_qan_h);  cudaGetSymbolAddress((void**)&qanl, g_qan_l);
    cudaGetSymbolAddress((void**)&ckvnh, g_ckvn_h); cudaGetSymbolAddress((void**)&ckvnl, g_ckvn_l);
    cudaGetSymbolAddress((void**)&q16h, g_q16h);   cudaGetSymbolAddress((void**)&q16l, g_q16l);
    cudaGetSymbolAddress((void**)&kv16, g_kv16);
    cudaGetSymbolAddress((void**)&kpe16, g_kpe16);
    cudaGetSymbolAddress((void**)&ctxh, g_ctxh);   cudaGetSymbolAddress((void**)&ctxl, g_ctxl);

    cudaFuncSetAttribute(fp_gemm_dual, cudaFuncAttributeMaxDynamicSharedMemorySize, GEMM_SMEM);
    cudaFuncSetAttribute(flash_mma, cudaFuncAttributeMaxDynamicSharedMemorySize, FL_SMEM);

    const dim3 blk(256);
    const int mt = T_TOK / 128;  // 32

    // merged input conversions: X hi/lo, weights single
    {
        Cvt6P P;
        P.x[0]=X;     P.h[0]=Xh;     P.l[0]=Xl;
        P.x[1]=wq_a;  P.h[1]=wqa16;  P.l[1]=nullptr;
        P.x[2]=wq_b;  P.h[2]=wqb16;  P.l[2]=nullptr;
        P.x[3]=wkv_a; P.h[3]=wkva16; P.l[3]=nullptr;
        P.x[4]=wkv_b; P.h[4]=wkvb16; P.l[4]=nullptr;
        P.x[5]=wo;    P.h[5]=wo16;   P.l[5]=nullptr;
        int lens[6] = { T_TOK*HIDDEN/4, QLORA*HIDDEN/4, NHEADS*QHD*QLORA/4,
                        KVW*HIDDEN/4, NHEADS*256*KVLORA/4, HIDDEN*NHEADS*VHD/4 };
        P.off[0] = 0;
        for (int i = 0; i < 6; ++i) P.off[i+1] = P.off[i] + lens[i];
        cvt6_kernel<<<(P.off[6] + 255) / 256, 256>>>(P);
    }

    // fused a-projections: wq_a + wkv_a -> fp32
    {
        GemmP p0 = { Xh, Xl, wqa16,  qa,  nullptr, nullptr, QLORA, HIDDEN };
        GemmP p1 = { Xh, Xl, wkva16, ckv, nullptr, nullptr, KVW,   HIDDEN };
        fp_gemm_dual<<<dim3(QLORA/128 + (KVW+127)/128, mt), blk, GEMM_SMEM>>>(p0, p1, QLORA/128);
    }

    // fused rmsnorms -> fp16 hi/lo
    {
        RmsP p0 = { qa, qln, qanh, qanl, QLORA, QLORA };
        RmsP p1 = { ckv, kvln, ckvnh, ckvnl, KVLORA, KVW };
        rmsnorm_dual<<<dim3(T_TOK, 2), 256>>>(p0, p1);
    }
    rope_k_kernel<<<T_TOK, 32>>>(ckv, pos, kpe16);

    // fused b-projections: q -> fp16 hi/lo ; kv -> fp16 single
    {
        GemmP p0 = { qanh, qanl, wqb16,  nullptr, q16h, q16l,   NHEADS*QHD, QLORA };
        GemmP p1 = { ckvnh, ckvnl, wkvb16, nullptr, kv16, nullptr, NHEADS*256, KVLORA };
        fp_gemm_dual<<<dim3((NHEADS*QHD)/128 + (NHEADS*256)/128, mt), blk, GEMM_SMEM>>>(
            p0, p1, (NHEADS*QHD)/128);
    }

    rope_q_kernel<<<T_TOK * NHEADS, 32>>>(q16h, q16l, pos);

    flash_mma<<<dim3(S_LEN / 128, NHEADS, BATCH), blk, FL_SMEM>>>(q16h, q16l, kv16, kpe16,
                                                                  ctxh, ctxl);

    // output projection: ctx (2-term) x wo (single) -> fp32 out
    {
        GemmP p0 = { ctxh, ctxl, wo16, out, nullptr, nullptr, HIDDEN, NHEADS*VHD };
        fp_gemm_dual<<<dim3(HIDDEN/128, mt), blk, GEMM_SMEM>>>(p0, p0, HIDDEN/128);
    }
}

// round 10
// speedup vs baseline: 3.2137x; 1.2965x over previous
#include <cuda_runtime.h>
#include <cuda_fp16.h>
#include <math.h>
#include <stdint.h>

// ---------------- problem constants ----------------
#define S_LEN   2048
#define BATCH   2
#define T_TOK   (BATCH * S_LEN)
#define HIDDEN  2048
#define QLORA   1536
#define KVLORA  512
#define NHEADS  16
#define NOPE    128
#define ROPE_D  64
#define QHD     192
#define VHD     128
#define KVW     576

// ---------------- scratch ----------------
__device__ float g_qa [T_TOK * QLORA];
__device__ float g_ckv[T_TOK * KVW];

__device__ __half g_X16[T_TOK * HIDDEN];
__device__ __half g_wqa16[QLORA * HIDDEN];
__device__ __half g_wqb16[NHEADS*QHD*QLORA];
__device__ __half g_wkva16[KVW * HIDDEN];
__device__ __half g_wkvb16[NHEADS*256*KVLORA];
__device__ __half g_wo16[HIDDEN*NHEADS*VHD];
__device__ __half g_qan16[T_TOK * QLORA];
__device__ __half g_ckvn16[T_TOK * KVLORA];
__device__ __half g_q16h[T_TOK * NHEADS * QHD], g_q16l[T_TOK * NHEADS * QHD];
__device__ __half g_kv16[T_TOK * NHEADS * 256];
__device__ __half g_kpe16[T_TOK * ROPE_D];
__device__ __half g_ctx16[T_TOK * NHEADS*VHD];

// ---------------- common helpers ----------------
__device__ __forceinline__ uint32_t smem_u32(const void* p) {
    uint32_t a;
    asm("{ .reg .u64 t; cvta.to.shared.u64 t, %1; cvt.u32.u64 %0, t; }" : "=r"(a) : "l"(p));
    return a;
}
__device__ __forceinline__ void ldm4(uint32_t* r, uint32_t addr) {
    asm volatile("ldmatrix.sync.aligned.m8n8.x4.shared.b16 {%0,%1,%2,%3}, [%4];"
                 : "=r"(r[0]), "=r"(r[1]), "=r"(r[2]), "=r"(r[3]) : "r"(addr));
}
__device__ __forceinline__ void ldm4t(uint32_t* r, uint32_t addr) {
    asm volatile("ldmatrix.sync.aligned.m8n8.x4.trans.shared.b16 {%0,%1,%2,%3}, [%4];"
                 : "=r"(r[0]), "=r"(r[1]), "=r"(r[2]), "=r"(r[3]) : "r"(addr));
}
__device__ __forceinline__ void mma16816h(float* d, const uint32_t* a, const uint32_t* b) {
    asm volatile("mma.sync.aligned.m16n8k16.row.col.f32.f16.f16.f32 "
                 "{%0,%1,%2,%3}, {%4,%5,%6,%7}, {%8,%9}, {%0,%1,%2,%3};"
                 : "+f"(d[0]), "+f"(d[1]), "+f"(d[2]), "+f"(d[3])
                 : "r"(a[0]), "r"(a[1]), "r"(a[2]), "r"(a[3]), "r"(b[0]), "r"(b[1]));
}
__device__ __forceinline__ void cpa16(uint32_t dst, const void* src, uint32_t sz) {
    asm volatile("cp.async.cg.shared.global [%0], [%1], 16, %2;"
                 :: "r"(dst), "l"(src), "r"(sz) : "memory");
}
__device__ __forceinline__ void split1h(float v, __half& h, __half& l) {
    h = __float2half_rn(v);
    l = __float2half_rn(v - __half2float(h));
}

// ---------------- merged convert fp32 -> fp16 single, 6 regions ----------------
struct Cvt6P {
    const float* x[6];
    __half* h[6];
    int off[7];
};
__global__ void cvt6_kernel(Cvt6P P) {
    int i = blockIdx.x * blockDim.x + threadIdx.x;
    if (i >= P.off[6]) return;
    int r = 0;
#pragma unroll
    for (int k = 1; k < 6; ++k) if (i >= P.off[k]) r = k;
    int j = i - P.off[r];
    float4 v = ((const float4*)P.x[r])[j];
    __half2 hp0 = __halves2half2(__float2half_rn(v.x), __float2half_rn(v.y));
    __half2 hp1 = __halves2half2(__float2half_rn(v.z), __float2half_rn(v.w));
    uint2 hh; hh.x = *(uint32_t*)&hp0; hh.y = *(uint32_t*)&hp1;
    ((uint2*)P.h[r])[j] = hh;
}

// ============================================================================
// fp16 GEMM: C = A * B^T, single precision operands. 128x128 CTA, 2 CTAs/SM.
// BK=16, 4-stage cp.async (2 tiles/stage), one sync per chunk, 8 warps.
// ============================================================================
#define SMSTR 48
#define TILEB (128 * SMSTR)           // 6144
#define STAGEB (2 * TILEB)            // 12288 (A, B)
#define NSTAGE 4
#define GEMM_SMEM (NSTAGE * STAGEB)   // 49152

struct GemmP {
    const __half *A, *B;
    float* C;
    __half *Hh, *Hl;      // fp16 hi/lo outputs (either nullable)
    int N, K;
};

__global__ __launch_bounds__(256, 2) void fp_gemm_dual(GemmP P0, GemmP P1, int xsplit) {
    extern __shared__ char sm[];
    const bool first = ((int)blockIdx.x < xsplit);
    const GemmP p = first ? P0 : P1;
    const int n0 = (first ? blockIdx.x : (blockIdx.x - xsplit)) * 128;
    const int K = p.K, N = p.N;

    const int tid = threadIdx.x;
    const int wid = tid >> 5;
    const int lane = tid & 31;
    const int m0 = blockIdx.y * 128;
    const int nvalid = (N - n0 < 128) ? (N - n0) : 128;

    const uint32_t sbase = smem_u32(sm);
    const int wr = wid >> 2, wc = wid & 3;
    const uint32_t a_row = wr * 64 + (lane & 15);
    const uint32_t a_colb = (lane >> 4) * 16;
    const uint32_t b_row = wc * 32 + (lane & 7) + ((lane >> 4) << 3);
    const uint32_t b_colb = ((lane >> 3) & 1) * 16;

    float acc[4][4][4];
#pragma unroll
    for (int i = 0; i < 4; ++i)
#pragma unroll
        for (int j = 0; j < 4; ++j)
#pragma unroll
            for (int e = 0; e < 4; ++e) acc[i][j][e] = 0.f;

    const int nch = K >> 4;

    // copy: 512 x 16B units per chunk, 2 per thread
    auto issue_chunk = [&](int c) {
        const int k0 = c << 4;
        const uint32_t stb = sbase + (c & (NSTAGE - 1)) * STAGEB;
#pragma unroll
        for (int i = 0; i < 2; ++i) {
            int u = tid + i * 256;
            int tile = u >> 8;              // 0=A 1=B
            int row = (u & 255) >> 1;
            int c16 = u & 1;
            uint32_t dst = stb + tile * TILEB + row * SMSTR + c16 * 16;
            const __half* src;
            uint32_t sz = 16;
            if (tile == 0) src = p.A + (size_t)(m0 + row) * K + k0 + c16 * 8;
            else {
                src = p.B + (size_t)(n0 + row) * K + k0 + c16 * 8;
                if (row >= nvalid) sz = 0;
            }
            cpa16(dst, src, sz);
        }
        asm volatile("cp.async.commit_group;" ::: "memory");
    };

    issue_chunk(0);
    if (nch > 1) issue_chunk(1); else asm volatile("cp.async.commit_group;" ::: "memory");
    if (nch > 2) issue_chunk(2); else asm volatile("cp.async.commit_group;" ::: "memory");

    for (int c = 0; c < nch; ++c) {
        asm volatile("cp.async.wait_group 2;" ::: "memory");
        __syncthreads();
        if (c + 3 < nch) issue_chunk(c + 3);
        else asm volatile("cp.async.commit_group;" ::: "memory");

        const uint32_t stb = sbase + (c & (NSTAGE - 1)) * STAGEB;
        uint32_t ah[4][4], bh[2][4];
#pragma unroll
        for (int i = 0; i < 4; ++i)
            ldm4(ah[i], stb + (a_row + i * 16) * SMSTR + a_colb);
#pragma unroll
        for (int jp = 0; jp < 2; ++jp)
            ldm4(bh[jp], stb + TILEB + (b_row + jp * 16) * SMSTR + b_colb);
#pragma unroll
        for (int i = 0; i < 4; ++i)
#pragma unroll
            for (int j = 0; j < 4; ++j)
                mma16816h(acc[i][j], ah[i], &bh[j >> 1][(j & 1) * 2]);
    }

    const int gid = lane >> 2, tig = lane & 3;
#pragma unroll
    for (int i = 0; i < 4; ++i) {
#pragma unroll
        for (int rr = 0; rr < 2; ++rr) {
            int row = m0 + wr * 64 + i * 16 + gid + rr * 8;
#pragma unroll
            for (int j = 0; j < 4; ++j) {
                int col = n0 + wc * 32 + j * 8 + tig * 2;
                if (col < N) {
                    float v0 = acc[i][j][rr * 2], v1 = acc[i][j][rr * 2 + 1];
                    if (p.C) *(float2*)(p.C + (size_t)row * N + col) = make_float2(v0, v1);
                    if (p.Hh) {
                        __half h0,l0,h1,l1;
                        split1h(v0,h0,l0); split1h(v1,h1,l1);
                        __half2 hp = __halves2half2(h0, h1);
                        *(uint32_t*)(p.Hh + (size_t)row * N + col) = *(uint32_t*)&hp;
                        if (p.Hl) {
                            __half2 lp = __halves2half2(l0, l1);
                            *(uint32_t*)(p.Hl + (size_t)row * N + col) = *(uint32_t*)&lp;
                        }
                    }
                }
            }
        }
    }
}

// ---------------- dual RMSNorm -> fp16 single ----------------
struct RmsP {
    const float* x; const float* w;
    __half *y;
    int D, in_stride;
};
__global__ void rmsnorm_dual(RmsP P0, RmsP P1) {
    const RmsP p = (blockIdx.y == 0) ? P0 : P1;
    const int row = blockIdx.x;
    const float* xr = p.x + (size_t)row * p.in_stride;
    float ss = 0.f;
    for (int d = threadIdx.x; d < p.D; d += blockDim.x) { float v = xr[d]; ss += v * v; }
    __shared__ float red[32];
#pragma unroll
    for (int o = 16; o; o >>= 1) ss += __shfl_xor_sync(0xffffffffu, ss, o);
    if ((threadIdx.x & 31) == 0) red[threadIdx.x >> 5] = ss;
    __syncthreads();
    if (threadIdx.x < 32) {
        float v = (threadIdx.x < (blockDim.x >> 5)) ? red[threadIdx.x] : 0.f;
#pragma unroll
        for (int o = 16; o; o >>= 1) v += __shfl_xor_sync(0xffffffffu, v, o);
        if (threadIdx.x == 0) red[0] = v;
    }
    __syncthreads();
    float scale = rsqrtf(red[0] / (float)p.D + 1e-6f);
    for (int d = threadIdx.x; d < p.D; d += blockDim.x) {
        float v = p.w[d] * xr[d] * scale;
        p.y[(size_t)row * p.D + d] = __float2half_rn(v);
    }
}

// ---------------- YaRN ----------------
__device__ __forceinline__ void yarn_cs(int pos, int j, float& c, float& s) {
    float ex   = __expf(-(float)(2 * j) * (9.210340371976184f / 64.f));
    float fi   = ex * 0.025f;
    float ramp = ((float)j - 10.f) * (1.f / 13.f);
    ramp = fminf(fmaxf(ramp, 0.f), 1.f);
    float invf = fi * ramp + ex * (1.f - ramp);
    float ang  = (float)pos * invf;
    c = cosf(ang); s = sinf(ang);
}

__global__ void rope_k_kernel(const float* __restrict__ ckv, const int* __restrict__ pos_ids,
                              __half* __restrict__ kpe) {
    const int t = blockIdx.x;
    const int j = threadIdx.x;
    const int pos = pos_ids[t];
    const float* x = ckv + (size_t)t * KVW + KVLORA;
    float c, s; yarn_cs(pos, j, c, s);
    float x0 = x[2 * j], x1 = x[2 * j + 1];
    kpe[t * ROPE_D + j]      = __float2half_rn(x0 * c - x1 * s);
    kpe[t * ROPE_D + 32 + j] = __float2half_rn(x1 * c + x0 * s);
}

__global__ void rope_q_kernel(__half* __restrict__ qh, __half* __restrict__ ql,
                              const int* __restrict__ pos_ids) {
    const int t = blockIdx.x >> 4;
    const int h = blockIdx.x & 15;
    const int j = threadIdx.x;
    const int pos = pos_ids[t];
    __half* xh = qh + (size_t)t * (NHEADS * QHD) + h * QHD + NOPE;
    __half* xl = ql + (size_t)t * (NHEADS * QHD) + h * QHD + NOPE;
    float c, s; yarn_cs(pos, j, c, s);
    float x0 = __half2float(xh[2*j])   + __half2float(xl[2*j]);
    float x1 = __half2float(xh[2*j+1]) + __half2float(xl[2*j+1]);
    float r0 = x0 * c - x1 * s, r1 = x1 * c + x0 * s;
    __syncwarp();
    __half hh, ll;
    split1h(r0, hh, ll); xh[j] = hh;      xl[j] = ll;
    split1h(r1, hh, ll); xh[32 + j] = hh; xl[32 + j] = ll;
}

// ============================================================================
// Flash attention, fp16 HMMA. BM=128, BN=64, 8 warps. (R9; ctx single out)
// ============================================================================
#define FL_KSTR 400
#define FL_VSTR 272
#define FL_PSTR 144
#define FL_KVSTG (64 * FL_KSTR + 64 * FL_VSTR)
#define FL_VOFF  (64 * FL_KSTR)
#define FL_QSTR 400
#define FL_PH  102400
#define FL_PL  (FL_PH + 128 * FL_PSTR)
#define FL_SMEM (FL_PL + 128 * FL_PSTR)

__global__ __launch_bounds__(256, 1) void flash_mma(
    const __half* __restrict__ qh, const __half* __restrict__ ql,
    const __half* __restrict__ kv,
    const __half* __restrict__ kpe,
    __half* __restrict__ ctx)
{
    extern __shared__ char sm[];
    const uint32_t sb = smem_u32(sm);
    const int qt = (int)gridDim.x - 1 - (int)blockIdx.x;
    const int hh = blockIdx.y, b = blockIdx.z;
    const int tid = threadIdx.x, wid = tid >> 5, lane = tid & 31;
    const int gid = lane >> 2, tig = lane & 3;
    const int t0 = b * S_LEN;

    const uint32_t a_row = wid * 16 + (lane & 15);
    const uint32_t a_colb = (lane >> 4) * 16;
    const uint32_t k_roff = (lane & 7) + ((lane >> 4) << 3);
    const uint32_t k_colb = ((lane >> 3) & 1) * 16;
    const uint32_t v_koff = (lane & 7) + ((lane >> 3) & 1) * 8;
    const uint32_t v_noff = (lane >> 4) * 8;

    for (int idx = tid; idx < 128 * 24; idx += 256) {
        int r = idx / 24, u = idx % 24;
        size_t g = (size_t)(t0 + qt * 128 + r) * (NHEADS * QHD) + hh * QHD + u * 8;
        *(uint4*)(sm + r * FL_QSTR + u * 16) = *(const uint4*)(qh + g);
        *(uint4*)(sm + 51200 + r * FL_QSTR + u * 16) = *(const uint4*)(ql + g);
    }
    __syncthreads();
    uint32_t qfh[12][4], qfl[12][4];
#pragma unroll
    for (int ks = 0; ks < 12; ++ks) {
        ldm4(qfh[ks], sb + a_row * FL_QSTR + a_colb + ks * 32);
        ldm4(qfl[ks], sb + 51200 + a_row * FL_QSTR + a_colb + ks * 32);
    }
    __syncthreads();

    auto issue_kv = [&](int kt) {
        const uint32_t stb = sb + (kt & 1) * FL_KVSTG;
        for (int idx = tid; idx < 64 * 24; idx += 256) {
            int r = idx / 24, u = idx % 24;
            int t = t0 + kt * 64 + r;
            const __half* src;
            if (u < 16) src = kv + (size_t)t * (NHEADS * 256) + hh * 256 + u * 8;
            else        src = kpe + (size_t)t * ROPE_D + (u - 16) * 8;
            cpa16(stb + r * FL_KSTR + u * 16, src, 16);
        }
        for (int idx = tid; idx < 64 * 16; idx += 256) {
            int r = idx >> 4, u = idx & 15;
            size_t g = (size_t)(t0 + kt * 64 + r) * (NHEADS * 256) + hh * 256 + 128 + u * 8;
            cpa16(stb + FL_VOFF + r * FL_VSTR + u * 16, kv + g, 16);
        }
        asm volatile("cp.async.commit_group;" ::: "memory");
    };

    float m_i[2], l_i[2], O[16][4];
    m_i[0] = m_i[1] = -1e30f; l_i[0] = l_i[1] = 0.f;
#pragma unroll
    for (int nf = 0; nf < 16; ++nf)
#pragma unroll
        for (int e = 0; e < 4; ++e) O[nf][e] = 0.f;

    const float mm = 0.1f * logf(40.f) + 1.f;
    const float sc = mm * mm * rsqrtf(192.f);

    const int nkt = 2 * qt + 2;
    issue_kv(0);

    for (int kt = 0; kt < nkt; ++kt) {
        if (kt + 1 < nkt) {
            issue_kv(kt + 1);
            asm volatile("cp.async.wait_group 1;" ::: "memory");
        } else {
            asm volatile("cp.async.wait_group 0;" ::: "memory");
        }
        __syncthreads();
        const uint32_t stb = sb + (kt & 1) * FL_KVSTG;

        float s[8][4];
#pragma unroll
        for (int nf = 0; nf < 8; ++nf)
#pragma unroll
            for (int e = 0; e < 4; ++e) s[nf][e] = 0.f;

#pragma unroll
        for (int ks = 0; ks < 12; ++ks) {
#pragma unroll
            for (int jb = 0; jb < 4; ++jb) {
                uint32_t bh4[4];
                uint32_t brow = jb * 16 + k_roff;
                ldm4(bh4, stb + brow * FL_KSTR + k_colb + ks * 32);
                mma16816h(s[2*jb],   qfh[ks], &bh4[0]);
                mma16816h(s[2*jb+1], qfh[ks], &bh4[2]);
                mma16816h(s[2*jb],   qfl[ks], &bh4[0]);
                mma16816h(s[2*jb+1], qfl[ks], &bh4[2]);
            }
        }

#pragma unroll
        for (int rr = 0; rr < 2; ++rr) {
            int grow = qt * 128 + wid * 16 + gid + rr * 8;
            float tmax = -1e30f;
#pragma unroll
            for (int nf = 0; nf < 8; ++nf) {
#pragma unroll
                for (int e = 0; e < 2; ++e) {
                    int gcol = kt * 64 + nf * 8 + tig * 2 + e;
                    float v = s[nf][rr * 2 + e] * sc;
                    if (gcol > grow) v = -1e30f;
                    s[nf][rr * 2 + e] = v;
                    tmax = fmaxf(tmax, v);
                }
            }
            tmax = fmaxf(tmax, __shfl_xor_sync(0xffffffffu, tmax, 1));
            tmax = fmaxf(tmax, __shfl_xor_sync(0xffffffffu, tmax, 2));
            float nm = fmaxf(m_i[rr], tmax);
            float fac = __expf(m_i[rr] - nm);
            float psum = 0.f;
#pragma unroll
            for (int nf = 0; nf < 8; ++nf) {
#pragma unroll
                for (int e = 0; e < 2; ++e) {
                    float p = __expf(s[nf][rr * 2 + e] - nm);
                    s[nf][rr * 2 + e] = p;
                    psum += p;
                }
            }
            psum += __shfl_xor_sync(0xffffffffu, psum, 1);
            psum += __shfl_xor_sync(0xffffffffu, psum, 2);
            l_i[rr] = l_i[rr] * fac + psum;
            m_i[rr] = nm;
#pragma unroll
            for (int nf = 0; nf < 16; ++nf) {
                O[nf][rr * 2] *= fac;
                O[nf][rr * 2 + 1] *= fac;
            }
        }

#pragma unroll
        for (int rr = 0; rr < 2; ++rr) {
            uint32_t prow = wid * 16 + gid + rr * 8;
#pragma unroll
            for (int nf = 0; nf < 8; ++nf) {
                __half h0,l0,h1,l1;
                split1h(s[nf][rr * 2], h0, l0);
                split1h(s[nf][rr * 2 + 1], h1, l1);
                __half2 hp = __halves2half2(h0, h1);
                __half2 lp = __halves2half2(l0, l1);
                uint32_t off = prow * FL_PSTR + (nf * 8 + tig * 2) * 2;
                *(uint32_t*)(sm + FL_PH + off) = *(uint32_t*)&hp;
                *(uint32_t*)(sm + FL_PL + off) = *(uint32_t*)&lp;
            }
        }
        __syncwarp();

#pragma unroll
        for (int ks = 0; ks < 4; ++ks) {
            uint32_t aph[4], apl[4];
            ldm4(aph, sb + FL_PH + a_row * FL_PSTR + a_colb + ks * 32);
            ldm4(apl, sb + FL_PL + a_row * FL_PSTR + a_colb + ks * 32);
            uint32_t vrow = ks * 16 + v_koff;
#pragma unroll
            for (int nb = 0; nb < 8; ++nb) {
                uint32_t bvh[4];
                uint32_t vcol = (nb * 16 + v_noff) * 2;
                ldm4t(bvh, stb + FL_VOFF + vrow * FL_VSTR + vcol);
                mma16816h(O[2*nb],   aph, &bvh[0]);
                mma16816h(O[2*nb+1], aph, &bvh[2]);
                mma16816h(O[2*nb],   apl, &bvh[0]);
                mma16816h(O[2*nb+1], apl, &bvh[2]);
            }
        }
        __syncthreads();
    }

#pragma unroll
    for (int rr = 0; rr < 2; ++rr) {
        float inv = 1.f / l_i[rr];
        int row = t0 + qt * 128 + wid * 16 + gid + rr * 8;
#pragma unroll
        for (int nf = 0; nf < 16; ++nf) {
            int col = nf * 8 + tig * 2;
            float v0 = O[nf][rr * 2] * inv, v1 = O[nf][rr * 2 + 1] * inv;
            __half2 hp = __halves2half2(__float2half_rn(v0), __float2half_rn(v1));
            size_t g = (size_t)row * (NHEADS * VHD) + hh * VHD + col;
            *(uint32_t*)(ctx + g) = *(uint32_t*)&hp;
        }
    }
}

// ---------------- launch ----------------
extern "C" void kernel_launch(void* const* d_in, const int* in_sizes, int n_in,
                              void* d_out, int out_size) {
    (void)in_sizes; (void)n_in; (void)out_size;
    const float* X     = (const float*)d_in[0];
    const int*   pos   = (const int*)  d_in[1];
    const float* wq_a  = (const float*)d_in[2];
    const float* qln   = (const float*)d_in[3];
    const float* wq_b  = (const float*)d_in[4];
    const float* wkv_a = (const float*)d_in[5];
    const float* kvln  = (const float*)d_in[6];
    const float* wkv_b = (const float*)d_in[7];
    const float* wo    = (const float*)d_in[8];
    float* out = (float*)d_out;

    float *qa, *ckv;
    __half *X16,*wqa16,*wqb16,*wkva16,*wkvb16,*wo16;
    __half *qan16,*ckvn16,*q16h,*q16l,*kv16,*kpe16,*ctx16;
    cudaGetSymbolAddress((void**)&qa, g_qa);
    cudaGetSymbolAddress((void**)&ckv, g_ckv);
    cudaGetSymbolAddress((void**)&X16, g_X16);
    cudaGetSymbolAddress((void**)&wqa16, g_wqa16);
    cudaGetSymbolAddress((void**)&wqb16, g_wqb16);
    cudaGetSymbolAddress((void**)&wkva16, g_wkva16);
    cudaGetSymbolAddress((void**)&wkvb16, g_wkvb16);
    cudaGetSymbolAddress((void**)&wo16, g_wo16);
    cudaGetSymbolAddress((void**)&qan16, g_qan16);
    cudaGetSymbolAddress((void**)&ckvn16, g_ckvn16);
    cudaGetSymbolAddress((void**)&q16h, g_q16h);
    cudaGetSymbolAddress((void**)&q16l, g_q16l);
    cudaGetSymbolAddress((void**)&kv16, g_kv16);
    cudaGetSymbolAddress((void**)&kpe16, g_kpe16);
    cudaGetSymbolAddress((void**)&ctx16, g_ctx16);

    cudaFuncSetAttribute(fp_gemm_dual, cudaFuncAttributeMaxDynamicSharedMemorySize, GEMM_SMEM);
    cudaFuncSetAttribute(flash_mma, cudaFuncAttributeMaxDynamicSharedMemorySize, FL_SMEM);

    const dim3 blk(256);
    const int mt = T_TOK / 128;  // 32

    // merged input conversions (all single fp16)
    {
        Cvt6P P;
        P.x[0]=X;     P.h[0]=X16;
        P.x[1]=wq_a;  P.h[1]=wqa16;
        P.x[2]=wq_b;  P.h[2]=wqb16;
        P.x[3]=wkv_a; P.h[3]=wkva16;
        P.x[4]=wkv_b; P.h[4]=wkvb16;
        P.x[5]=wo;    P.h[5]=wo16;
        int lens[6] = { T_TOK*HIDDEN/4, QLORA*HIDDEN/4, NHEADS*QHD*QLORA/4,
                        KVW*HIDDEN/4, NHEADS*256*KVLORA/4, HIDDEN*NHEADS*VHD/4 };
        P.off[0] = 0;
        for (int i = 0; i < 6; ++i) P.off[i+1] = P.off[i] + lens[i];
        cvt6_kernel<<<(P.off[6] + 255) / 256, 256>>>(P);
    }

    // fused a-projections -> fp32
    {
        GemmP p0 = { X16, wqa16,  qa,  nullptr, nullptr, QLORA, HIDDEN };
        GemmP p1 = { X16, wkva16, ckv, nullptr, nullptr, KVW,   HIDDEN };
        fp_gemm_dual<<<dim3(QLORA/128 + (KVW+127)/128, mt), blk, GEMM_SMEM>>>(p0, p1, QLORA/128);
    }

    // fused rmsnorms -> fp16
    {
        RmsP p0 = { qa, qln, qan16, QLORA, QLORA };
        RmsP p1 = { ckv, kvln, ckvn16, KVLORA, KVW };
        rmsnorm_dual<<<dim3(T_TOK, 2), 256>>>(p0, p1);
    }
    rope_k_kernel<<<T_TOK, 32>>>(ckv, pos, kpe16);

    // fused b-projections: q -> fp16 hi/lo ; kv -> fp16 single
    {
        GemmP p0 = { qan16,  wqb16,  nullptr, q16h, q16l,   NHEADS*QHD, QLORA };
        GemmP p1 = { ckvn16, wkvb16, nullptr, kv16, nullptr, NHEADS*256, KVLORA };
        fp_gemm_dual<<<dim3((NHEADS*QHD)/128 + (NHEADS*256)/128, mt), blk, GEMM_SMEM>>>(
            p0, p1, (NHEADS*QHD)/128);
    }

    rope_q_kernel<<<T_TOK * NHEADS, 32>>>(q16h, q16l, pos);

    flash_mma<<<dim3(S_LEN / 128, NHEADS, BATCH), blk, FL_SMEM>>>(q16h, q16l, kv16, kpe16,
                                                                  ctx16);

    // output projection -> fp32 out
    {
        GemmP p0 = { ctx16, wo16, out, nullptr, nullptr, HIDDEN, NHEADS*VHD };
        fp_gemm_dual<<<dim3(HIDDEN/128, mt), blk, GEMM_SMEM>>>(p0, p0, HIDDEN/128);
    }
}

// round 11
// speedup vs baseline: 3.3832x; 1.0527x over previous
#include <cuda_runtime.h>
#include <cuda_fp16.h>
#include <math.h>
#include <stdint.h>

// ---------------- problem constants ----------------
#define S_LEN   2048
#define BATCH   2
#define T_TOK   (BATCH * S_LEN)
#define HIDDEN  2048
#define QLORA   1536
#define KVLORA  512
#define NHEADS  16
#define NOPE    128
#define ROPE_D  64
#define QHD     192
#define VHD     128
#define KVW     576

// ---------------- scratch ----------------
__device__ float g_qa [T_TOK * QLORA];
__device__ float g_ckv[T_TOK * KVW];

__device__ __half g_X16[T_TOK * HIDDEN];
__device__ __half g_wqa16[QLORA * HIDDEN];
__device__ __half g_wqb16[NHEADS*QHD*QLORA];
__device__ __half g_wkva16[KVW * HIDDEN];
__device__ __half g_wkvb16[NHEADS*256*KVLORA];
__device__ __half g_wo16[HIDDEN*NHEADS*VHD];
__device__ __half g_qan16[T_TOK * QLORA];
__device__ __half g_ckvn16[T_TOK * KVLORA];
__device__ __half g_q16h[T_TOK * NHEADS * QHD], g_q16l[T_TOK * NHEADS * QHD];
__device__ __half g_kv16[T_TOK * NHEADS * 256];
__device__ __half g_kpe16[T_TOK * ROPE_D];
__device__ __half g_ctx16[T_TOK * NHEADS*VHD];

// ---------------- common helpers ----------------
__device__ __forceinline__ uint32_t smem_u32(const void* p) {
    uint32_t a;
    asm("{ .reg .u64 t; cvta.to.shared.u64 t, %1; cvt.u32.u64 %0, t; }" : "=r"(a) : "l"(p));
    return a;
}
__device__ __forceinline__ void ldm4(uint32_t* r, uint32_t addr) {
    asm volatile("ldmatrix.sync.aligned.m8n8.x4.shared.b16 {%0,%1,%2,%3}, [%4];"
                 : "=r"(r[0]), "=r"(r[1]), "=r"(r[2]), "=r"(r[3]) : "r"(addr));
}
__device__ __forceinline__ void ldm4t(uint32_t* r, uint32_t addr) {
    asm volatile("ldmatrix.sync.aligned.m8n8.x4.trans.shared.b16 {%0,%1,%2,%3}, [%4];"
                 : "=r"(r[0]), "=r"(r[1]), "=r"(r[2]), "=r"(r[3]) : "r"(addr));
}
__device__ __forceinline__ void mma16816h(float* d, const uint32_t* a, const uint32_t* b) {
    asm volatile("mma.sync.aligned.m16n8k16.row.col.f32.f16.f16.f32 "
                 "{%0,%1,%2,%3}, {%4,%5,%6,%7}, {%8,%9}, {%0,%1,%2,%3};"
                 : "+f"(d[0]), "+f"(d[1]), "+f"(d[2]), "+f"(d[3])
                 : "r"(a[0]), "r"(a[1]), "r"(a[2]), "r"(a[3]), "r"(b[0]), "r"(b[1]));
}
__device__ __forceinline__ void cpa16(uint32_t dst, const void* src, uint32_t sz) {
    asm volatile("cp.async.cg.shared.global [%0], [%1], 16, %2;"
                 :: "r"(dst), "l"(src), "r"(sz) : "memory");
}
__device__ __forceinline__ void split1h(float v, __half& h, __half& l) {
    h = __float2half_rn(v);
    l = __float2half_rn(v - __half2float(h));
}

// ---------------- merged convert fp32 -> fp16 single, 6 regions ----------------
struct Cvt6P {
    const float* x[6];
    __half* h[6];
    int off[7];
};
__global__ void cvt6_kernel(Cvt6P P) {
    int i = blockIdx.x * blockDim.x + threadIdx.x;
    if (i >= P.off[6]) return;
    int r = 0;
#pragma unroll
    for (int k = 1; k < 6; ++k) if (i >= P.off[k]) r = k;
    int j = i - P.off[r];
    float4 v = ((const float4*)P.x[r])[j];
    __half2 hp0 = __halves2half2(__float2half_rn(v.x), __float2half_rn(v.y));
    __half2 hp1 = __halves2half2(__float2half_rn(v.z), __float2half_rn(v.w));
    uint2 hh; hh.x = *(uint32_t*)&hp0; hh.y = *(uint32_t*)&hp1;
    ((uint2*)P.h[r])[j] = hh;
}

// ============================================================================
// fp16 GEMM: C = A * B^T, single operands. 128x128 CTA, 2 CTAs/SM.
// BK=32, 4-stage cp.async (2 tiles/stage), one sync per chunk, 8 warps.
// ============================================================================
#define SMSTR 80                      // 32 fp16 = 64B + 16B pad (conflict-free)
#define TILEB (128 * SMSTR)           // 10240
#define STAGEB (2 * TILEB)            // 20480 (A, B)
#define NSTAGE 4
#define GEMM_SMEM (NSTAGE * STAGEB)   // 81920

struct GemmP {
    const __half *A, *B;
    float* C;
    __half *Hh, *Hl;
    int N, K;
};

__global__ __launch_bounds__(256, 2) void fp_gemm_dual(GemmP P0, GemmP P1, int xsplit) {
    extern __shared__ char sm[];
    const bool first = ((int)blockIdx.x < xsplit);
    const GemmP p = first ? P0 : P1;
    const int n0 = (first ? blockIdx.x : (blockIdx.x - xsplit)) * 128;
    const int K = p.K, N = p.N;

    const int tid = threadIdx.x;
    const int wid = tid >> 5;
    const int lane = tid & 31;
    const int m0 = blockIdx.y * 128;
    const int nvalid = (N - n0 < 128) ? (N - n0) : 128;

    const uint32_t sbase = smem_u32(sm);
    const int wr = wid >> 2, wc = wid & 3;
    const uint32_t a_row = wr * 64 + (lane & 15);
    const uint32_t a_colb = (lane >> 4) * 16;
    const uint32_t b_row = wc * 32 + (lane & 7) + ((lane >> 4) << 3);
    const uint32_t b_colb = ((lane >> 3) & 1) * 16;

    float acc[4][4][4];
#pragma unroll
    for (int i = 0; i < 4; ++i)
#pragma unroll
        for (int j = 0; j < 4; ++j)
#pragma unroll
            for (int e = 0; e < 4; ++e) acc[i][j][e] = 0.f;

    const int nch = K >> 5;

    // copy: 1024 x 16B units per chunk, 4 per thread
    auto issue_chunk = [&](int c) {
        const int k0 = c << 5;
        const uint32_t stb = sbase + (c & (NSTAGE - 1)) * STAGEB;
#pragma unroll
        for (int i = 0; i < 4; ++i) {
            int u = tid + i * 256;
            int tile = u >> 9;              // 0=A 1=B
            int row = (u & 511) >> 2;
            int c16 = u & 3;
            uint32_t dst = stb + tile * TILEB + row * SMSTR + c16 * 16;
            const __half* src;
            uint32_t sz = 16;
            if (tile == 0) src = p.A + (size_t)(m0 + row) * K + k0 + c16 * 8;
            else {
                src = p.B + (size_t)(n0 + row) * K + k0 + c16 * 8;
                if (row >= nvalid) sz = 0;
            }
            cpa16(dst, src, sz);
        }
        asm volatile("cp.async.commit_group;" ::: "memory");
    };

    issue_chunk(0);
    if (nch > 1) issue_chunk(1); else asm volatile("cp.async.commit_group;" ::: "memory");
    if (nch > 2) issue_chunk(2); else asm volatile("cp.async.commit_group;" ::: "memory");

    for (int c = 0; c < nch; ++c) {
        asm volatile("cp.async.wait_group 2;" ::: "memory");
        __syncthreads();
        if (c + 3 < nch) issue_chunk(c + 3);
        else asm volatile("cp.async.commit_group;" ::: "memory");

        const uint32_t stb = sbase + (c & (NSTAGE - 1)) * STAGEB;
#pragma unroll
        for (int ks = 0; ks < 2; ++ks) {
            const uint32_t kb = ks * 32;
            uint32_t ah[4][4], bh[2][4];
#pragma unroll
            for (int i = 0; i < 4; ++i)
                ldm4(ah[i], stb + (a_row + i * 16) * SMSTR + a_colb + kb);
#pragma unroll
            for (int jp = 0; jp < 2; ++jp)
                ldm4(bh[jp], stb + TILEB + (b_row + jp * 16) * SMSTR + b_colb + kb);
#pragma unroll
            for (int i = 0; i < 4; ++i)
#pragma unroll
                for (int j = 0; j < 4; ++j)
                    mma16816h(acc[i][j], ah[i], &bh[j >> 1][(j & 1) * 2]);
        }
    }

    const int gid = lane >> 2, tig = lane & 3;
#pragma unroll
    for (int i = 0; i < 4; ++i) {
#pragma unroll
        for (int rr = 0; rr < 2; ++rr) {
            int row = m0 + wr * 64 + i * 16 + gid + rr * 8;
#pragma unroll
            for (int j = 0; j < 4; ++j) {
                int col = n0 + wc * 32 + j * 8 + tig * 2;
                if (col < N) {
                    float v0 = acc[i][j][rr * 2], v1 = acc[i][j][rr * 2 + 1];
                    if (p.C) *(float2*)(p.C + (size_t)row * N + col) = make_float2(v0, v1);
                    if (p.Hh) {
                        __half h0,l0,h1,l1;
                        split1h(v0,h0,l0); split1h(v1,h1,l1);
                        __half2 hp = __halves2half2(h0, h1);
                        *(uint32_t*)(p.Hh + (size_t)row * N + col) = *(uint32_t*)&hp;
                        if (p.Hl) {
                            __half2 lp = __halves2half2(l0, l1);
                            *(uint32_t*)(p.Hl + (size_t)row * N + col) = *(uint32_t*)&lp;
                        }
                    }
                }
            }
        }
    }
}

// ---------------- dual RMSNorm -> fp16 single ----------------
struct RmsP {
    const float* x; const float* w;
    __half *y;
    int D, in_stride;
};
__global__ void rmsnorm_dual(RmsP P0, RmsP P1) {
    const RmsP p = (blockIdx.y == 0) ? P0 : P1;
    const int row = blockIdx.x;
    const float* xr = p.x + (size_t)row * p.in_stride;
    float ss = 0.f;
    for (int d = threadIdx.x; d < p.D; d += blockDim.x) { float v = xr[d]; ss += v * v; }
    __shared__ float red[32];
#pragma unroll
    for (int o = 16; o; o >>= 1) ss += __shfl_xor_sync(0xffffffffu, ss, o);
    if ((threadIdx.x & 31) == 0) red[threadIdx.x >> 5] = ss;
    __syncthreads();
    if (threadIdx.x < 32) {
        float v = (threadIdx.x < (blockDim.x >> 5)) ? red[threadIdx.x] : 0.f;
#pragma unroll
        for (int o = 16; o; o >>= 1) v += __shfl_xor_sync(0xffffffffu, v, o);
        if (threadIdx.x == 0) red[0] = v;
    }
    __syncthreads();
    float scale = rsqrtf(red[0] / (float)p.D + 1e-6f);
    for (int d = threadIdx.x; d < p.D; d += blockDim.x) {
        float v = p.w[d] * xr[d] * scale;
        p.y[(size_t)row * p.D + d] = __float2half_rn(v);
    }
}

// ---------------- YaRN ----------------
__device__ __forceinline__ void yarn_cs(int pos, int j, float& c, float& s) {
    float ex   = __expf(-(float)(2 * j) * (9.210340371976184f / 64.f));
    float fi   = ex * 0.025f;
    float ramp = ((float)j - 10.f) * (1.f / 13.f);
    ramp = fminf(fmaxf(ramp, 0.f), 1.f);
    float invf = fi * ramp + ex * (1.f - ramp);
    float ang  = (float)pos * invf;
    c = cosf(ang); s = sinf(ang);
}

__global__ void rope_k_kernel(const float* __restrict__ ckv, const int* __restrict__ pos_ids,
                              __half* __restrict__ kpe) {
    const int t = blockIdx.x;
    const int j = threadIdx.x;
    const int pos = pos_ids[t];
    const float* x = ckv + (size_t)t * KVW + KVLORA;
    float c, s; yarn_cs(pos, j, c, s);
    float x0 = x[2 * j], x1 = x[2 * j + 1];
    kpe[t * ROPE_D + j]      = __float2half_rn(x0 * c - x1 * s);
    kpe[t * ROPE_D + 32 + j] = __float2half_rn(x1 * c + x0 * s);
}

__global__ void rope_q_kernel(__half* __restrict__ qh, __half* __restrict__ ql,
                              const int* __restrict__ pos_ids) {
    const int t = blockIdx.x >> 4;
    const int h = blockIdx.x & 15;
    const int j = threadIdx.x;
    const int pos = pos_ids[t];
    __half* xh = qh + (size_t)t * (NHEADS * QHD) + h * QHD + NOPE;
    __half* xl = ql + (size_t)t * (NHEADS * QHD) + h * QHD + NOPE;
    float c, s; yarn_cs(pos, j, c, s);
    float x0 = __half2float(xh[2*j])   + __half2float(xl[2*j]);
    float x1 = __half2float(xh[2*j+1]) + __half2float(xl[2*j+1]);
    float r0 = x0 * c - x1 * s, r1 = x1 * c + x0 * s;
    __syncwarp();
    __half hh, ll;
    split1h(r0, hh, ll); xh[j] = hh;      xl[j] = ll;
    split1h(r1, hh, ll); xh[32 + j] = hh; xl[32 + j] = ll;
}

// ============================================================================
// Flash attention, fp16 HMMA. BM=128, BN=64, 8 warps.
// P kept in registers (accumulator->A-operand layout identity). No P smem.
// ============================================================================
#define FL_KSTR 400
#define FL_VSTR 272
#define FL_KVSTG (64 * FL_KSTR + 64 * FL_VSTR)    // 43008
#define FL_VOFF  (64 * FL_KSTR)
#define FL_QSTR 400
#define FL_SMEM 102400                            // Q staging (prologue) ⊇ 2 KV stages

__global__ __launch_bounds__(256, 1) void flash_mma(
    const __half* __restrict__ qh, const __half* __restrict__ ql,
    const __half* __restrict__ kv,
    const __half* __restrict__ kpe,
    __half* __restrict__ ctx)
{
    extern __shared__ char sm[];
    const uint32_t sb = smem_u32(sm);
    const int qt = (int)gridDim.x - 1 - (int)blockIdx.x;
    const int hh = blockIdx.y, b = blockIdx.z;
    const int tid = threadIdx.x, wid = tid >> 5, lane = tid & 31;
    const int gid = lane >> 2, tig = lane & 3;
    const int t0 = b * S_LEN;

    const uint32_t a_row = wid * 16 + (lane & 15);
    const uint32_t a_colb = (lane >> 4) * 16;
    const uint32_t k_roff = (lane & 7) + ((lane >> 4) << 3);
    const uint32_t k_colb = ((lane >> 3) & 1) * 16;
    const uint32_t v_koff = (lane & 7) + ((lane >> 3) & 1) * 8;
    const uint32_t v_noff = (lane >> 4) * 8;

    for (int idx = tid; idx < 128 * 24; idx += 256) {
        int r = idx / 24, u = idx % 24;
        size_t g = (size_t)(t0 + qt * 128 + r) * (NHEADS * QHD) + hh * QHD + u * 8;
        *(uint4*)(sm + r * FL_QSTR + u * 16) = *(const uint4*)(qh + g);
        *(uint4*)(sm + 51200 + r * FL_QSTR + u * 16) = *(const uint4*)(ql + g);
    }
    __syncthreads();
    uint32_t qfh[12][4], qfl[12][4];
#pragma unroll
    for (int ks = 0; ks < 12; ++ks) {
        ldm4(qfh[ks], sb + a_row * FL_QSTR + a_colb + ks * 32);
        ldm4(qfl[ks], sb + 51200 + a_row * FL_QSTR + a_colb + ks * 32);
    }
    __syncthreads();

    auto issue_kv = [&](int kt) {
        const uint32_t stb = sb + (kt & 1) * FL_KVSTG;
        for (int idx = tid; idx < 64 * 24; idx += 256) {
            int r = idx / 24, u = idx % 24;
            int t = t0 + kt * 64 + r;
            const __half* src;
            if (u < 16) src = kv + (size_t)t * (NHEADS * 256) + hh * 256 + u * 8;
            else        src = kpe + (size_t)t * ROPE_D + (u - 16) * 8;
            cpa16(stb + r * FL_KSTR + u * 16, src, 16);
        }
        for (int idx = tid; idx < 64 * 16; idx += 256) {
            int r = idx >> 4, u = idx & 15;
            size_t g = (size_t)(t0 + kt * 64 + r) * (NHEADS * 256) + hh * 256 + 128 + u * 8;
            cpa16(stb + FL_VOFF + r * FL_VSTR + u * 16, kv + g, 16);
        }
        asm volatile("cp.async.commit_group;" ::: "memory");
    };

    float m_i[2], l_i[2], O[16][4];
    m_i[0] = m_i[1] = -1e30f; l_i[0] = l_i[1] = 0.f;
#pragma unroll
    for (int nf = 0; nf < 16; ++nf)
#pragma unroll
        for (int e = 0; e < 4; ++e) O[nf][e] = 0.f;

    const float mm = 0.1f * logf(40.f) + 1.f;
    const float sc = mm * mm * rsqrtf(192.f);

    const int nkt = 2 * qt + 2;
    issue_kv(0);

    for (int kt = 0; kt < nkt; ++kt) {
        if (kt + 1 < nkt) {
            issue_kv(kt + 1);
            asm volatile("cp.async.wait_group 1;" ::: "memory");
        } else {
            asm volatile("cp.async.wait_group 0;" ::: "memory");
        }
        __syncthreads();
        const uint32_t stb = sb + (kt & 1) * FL_KVSTG;

        // ---- QK: S = (Qh + Ql) * K ----
        float s[8][4];
#pragma unroll
        for (int nf = 0; nf < 8; ++nf)
#pragma unroll
            for (int e = 0; e < 4; ++e) s[nf][e] = 0.f;

#pragma unroll
        for (int ks = 0; ks < 12; ++ks) {
#pragma unroll
            for (int jb = 0; jb < 4; ++jb) {
                uint32_t bh4[4];
                uint32_t brow = jb * 16 + k_roff;
                ldm4(bh4, stb + brow * FL_KSTR + k_colb + ks * 32);
                mma16816h(s[2*jb],   qfh[ks], &bh4[0]);
                mma16816h(s[2*jb+1], qfh[ks], &bh4[2]);
                mma16816h(s[2*jb],   qfl[ks], &bh4[0]);
                mma16816h(s[2*jb+1], qfl[ks], &bh4[2]);
            }
        }

        // ---- softmax ----
#pragma unroll
        for (int rr = 0; rr < 2; ++rr) {
            int grow = qt * 128 + wid * 16 + gid + rr * 8;
            float tmax = -1e30f;
#pragma unroll
            for (int nf = 0; nf < 8; ++nf) {
#pragma unroll
                for (int e = 0; e < 2; ++e) {
                    int gcol = kt * 64 + nf * 8 + tig * 2 + e;
                    float v = s[nf][rr * 2 + e] * sc;
                    if (gcol > grow) v = -1e30f;
                    s[nf][rr * 2 + e] = v;
                    tmax = fmaxf(tmax, v);
                }
            }
            tmax = fmaxf(tmax, __shfl_xor_sync(0xffffffffu, tmax, 1));
            tmax = fmaxf(tmax, __shfl_xor_sync(0xffffffffu, tmax, 2));
            float nm = fmaxf(m_i[rr], tmax);
            float fac = __expf(m_i[rr] - nm);
            float psum = 0.f;
#pragma unroll
            for (int nf = 0; nf < 8; ++nf) {
#pragma unroll
                for (int e = 0; e < 2; ++e) {
                    float pv = __expf(s[nf][rr * 2 + e] - nm);
                    s[nf][rr * 2 + e] = pv;
                    psum += pv;
                }
            }
            psum += __shfl_xor_sync(0xffffffffu, psum, 1);
            psum += __shfl_xor_sync(0xffffffffu, psum, 2);
            l_i[rr] = l_i[rr] * fac + psum;
            m_i[rr] = nm;
#pragma unroll
            for (int nf = 0; nf < 16; ++nf) {
                O[nf][rr * 2] *= fac;
                O[nf][rr * 2 + 1] *= fac;
            }
        }

        // ---- P -> A-operand fragments in registers (hi/lo) ----
        uint32_t aph[4][4], apl[4][4];
#pragma unroll
        for (int ks = 0; ks < 4; ++ks) {
#pragma unroll
            for (int q = 0; q < 2; ++q) {
                int nf = 2 * ks + q;
                __half h0,l0,h1,l1,h2,l2,h3,l3;
                split1h(s[nf][0], h0, l0); split1h(s[nf][1], h1, l1);
                split1h(s[nf][2], h2, l2); split1h(s[nf][3], h3, l3);
                __half2 ph01 = __halves2half2(h0, h1);
                __half2 ph23 = __halves2half2(h2, h3);
                __half2 pl01 = __halves2half2(l0, l1);
                __half2 pl23 = __halves2half2(l2, l3);
                aph[ks][2*q]   = *(uint32_t*)&ph01;
                aph[ks][2*q+1] = *(uint32_t*)&ph23;
                apl[ks][2*q]   = *(uint32_t*)&pl01;
                apl[ks][2*q+1] = *(uint32_t*)&pl23;
            }
        }

        // ---- AV: O += (Ph + Pl) * V ----
#pragma unroll
        for (int ks = 0; ks < 4; ++ks) {
            uint32_t vrow = ks * 16 + v_koff;
#pragma unroll
            for (int nb = 0; nb < 8; ++nb) {
                uint32_t bvh[4];
                uint32_t vcol = (nb * 16 + v_noff) * 2;
                ldm4t(bvh, stb + FL_VOFF + vrow * FL_VSTR + vcol);
                mma16816h(O[2*nb],   aph[ks], &bvh[0]);
                mma16816h(O[2*nb+1], aph[ks], &bvh[2]);
                mma16816h(O[2*nb],   apl[ks], &bvh[0]);
                mma16816h(O[2*nb+1], apl[ks], &bvh[2]);
            }
        }
        __syncthreads();
    }

#pragma unroll
    for (int rr = 0; rr < 2; ++rr) {
        float inv = 1.f / l_i[rr];
        int row = t0 + qt * 128 + wid * 16 + gid + rr * 8;
#pragma unroll
        for (int nf = 0; nf < 16; ++nf) {
            int col = nf * 8 + tig * 2;
            float v0 = O[nf][rr * 2] * inv, v1 = O[nf][rr * 2 + 1] * inv;
            __half2 hp = __halves2half2(__float2half_rn(v0), __float2half_rn(v1));
            size_t g = (size_t)row * (NHEADS * VHD) + hh * VHD + col;
            *(uint32_t*)(ctx + g) = *(uint32_t*)&hp;
        }
    }
}

// ---------------- launch ----------------
extern "C" void kernel_launch(void* const* d_in, const int* in_sizes, int n_in,
                              void* d_out, int out_size) {
    (void)in_sizes; (void)n_in; (void)out_size;
    const float* X     = (const float*)d_in[0];
    const int*   pos   = (const int*)  d_in[1];
    const float* wq_a  = (const float*)d_in[2];
    const float* qln   = (const float*)d_in[3];
    const float* wq_b  = (const float*)d_in[4];
    const float* wkv_a = (const float*)d_in[5];
    const float* kvln  = (const float*)d_in[6];
    const float* wkv_b = (const float*)d_in[7];
    const float* wo    = (const float*)d_in[8];
    float* out = (float*)d_out;

    float *qa, *ckv;
    __half *X16,*wqa16,*wqb16,*wkva16,*wkvb16,*wo16;
    __half *qan16,*ckvn16,*q16h,*q16l,*kv16,*kpe16,*ctx16;
    cudaGetSymbolAddress((void**)&qa, g_qa);
    cudaGetSymbolAddress((void**)&ckv, g_ckv);
    cudaGetSymbolAddress((void**)&X16, g_X16);
    cudaGetSymbolAddress((void**)&wqa16, g_wqa16);
    cudaGetSymbolAddress((void**)&wqb16, g_wqb16);
    cudaGetSymbolAddress((void**)&wkva16, g_wkva16);
    cudaGetSymbolAddress((void**)&wkvb16, g_wkvb16);
    cudaGetSymbolAddress((void**)&wo16, g_wo16);
    cudaGetSymbolAddress((void**)&qan16, g_qan16);
    cudaGetSymbolAddress((void**)&ckvn16, g_ckvn16);
    cudaGetSymbolAddress((void**)&q16h, g_q16h);
    cudaGetSymbolAddress((void**)&q16l, g_q16l);
    cudaGetSymbolAddress((void**)&kv16, g_kv16);
    cudaGetSymbolAddress((void**)&kpe16, g_kpe16);
    cudaGetSymbolAddress((void**)&ctx16, g_ctx16);

    cudaFuncSetAttribute(fp_gemm_dual, cudaFuncAttributeMaxDynamicSharedMemorySize, GEMM_SMEM);
    cudaFuncSetAttribute(flash_mma, cudaFuncAttributeMaxDynamicSharedMemorySize, FL_SMEM);

    const dim3 blk(256);
    const int mt = T_TOK / 128;  // 32

    // merged input conversions (all single fp16)
    {
        Cvt6P P;
        P.x[0]=X;     P.h[0]=X16;
        P.x[1]=wq_a;  P.h[1]=wqa16;
        P.x[2]=wq_b;  P.h[2]=wqb16;
        P.x[3]=wkv_a; P.h[3]=wkva16;
        P.x[4]=wkv_b; P.h[4]=wkvb16;
        P.x[5]=wo;    P.h[5]=wo16;
        int lens[6] = { T_TOK*HIDDEN/4, QLORA*HIDDEN/4, NHEADS*QHD*QLORA/4,
                        KVW*HIDDEN/4, NHEADS*256*KVLORA/4, HIDDEN*NHEADS*VHD/4 };
        P.off[0] = 0;
        for (int i = 0; i < 6; ++i) P.off[i+1] = P.off[i] + lens[i];
        cvt6_kernel<<<(P.off[6] + 255) / 256, 256>>>(P);
    }

    // fused a-projections -> fp32
    {
        GemmP p0 = { X16, wqa16,  qa,  nullptr, nullptr, QLORA, HIDDEN };
        GemmP p1 = { X16, wkva16, ckv, nullptr, nullptr, KVW,   HIDDEN };
        fp_gemm_dual<<<dim3(QLORA/128 + (KVW+127)/128, mt), blk, GEMM_SMEM>>>(p0, p1, QLORA/128);
    }

    // fused rmsnorms -> fp16
    {
        RmsP p0 = { qa, qln, qan16, QLORA, QLORA };
        RmsP p1 = { ckv, kvln, ckvn16, KVLORA, KVW };
        rmsnorm_dual<<<dim3(T_TOK, 2), 256>>>(p0, p1);
    }
    rope_k_kernel<<<T_TOK, 32>>>(ckv, pos, kpe16);

    // fused b-projections: q -> fp16 hi/lo ; kv -> fp16 single
    {
        GemmP p0 = { qan16,  wqb16,  nullptr, q16h, q16l,   NHEADS*QHD, QLORA };
        GemmP p1 = { ckvn16, wkvb16, nullptr, kv16, nullptr, NHEADS*256, KVLORA };
        fp_gemm_dual<<<dim3((NHEADS*QHD)/128 + (NHEADS*256)/128, mt), blk, GEMM_SMEM>>>(
            p0, p1, (NHEADS*QHD)/128);
    }

    rope_q_kernel<<<T_TOK * NHEADS, 32>>>(q16h, q16l, pos);

    flash_mma<<<dim3(S_LEN / 128, NHEADS, BATCH), blk, FL_SMEM>>>(q16h, q16l, kv16, kpe16,
                                                                  ctx16);

    // output projection -> fp32 out
    {
        GemmP p0 = { ctx16, wo16, out, nullptr, nullptr, HIDDEN, NHEADS*VHD };
        fp_gemm_dual<<<dim3(HIDDEN/128, mt), blk, GEMM_SMEM>>>(p0, p0, HIDDEN/128);
    }
}

// round 13
// speedup vs baseline: 3.4032x; 1.0059x over previous
#include <cuda_runtime.h>
#include <cuda_fp16.h>
#include <math.h>
#include <stdint.h>

// ---------------- problem constants ----------------
#define S_LEN   2048
#define BATCH   2
#define T_TOK   (BATCH * S_LEN)
#define HIDDEN  2048
#define QLORA   1536
#define KVLORA  512
#define NHEADS  16
#define NOPE    128
#define ROPE_D  64
#define QHD     192
#define VHD     128
#define KVW     576

// ---------------- scratch ----------------
__device__ float g_qa [T_TOK * QLORA];
__device__ float g_ckv[T_TOK * KVW];

__device__ __half g_X16[T_TOK * HIDDEN];
__device__ __half g_wqa16[QLORA * HIDDEN];
__device__ __half g_wqb16[NHEADS*QHD*QLORA];
__device__ __half g_wkva16[KVW * HIDDEN];
__device__ __half g_wkvb16[NHEADS*256*KVLORA];
__device__ __half g_wo16[HIDDEN*NHEADS*VHD];
__device__ __half g_qan16[T_TOK * QLORA];
__device__ __half g_ckvn16[T_TOK * KVLORA];
__device__ __half g_q16h[T_TOK * NHEADS * QHD], g_q16l[T_TOK * NHEADS * QHD];
__device__ __half g_kv16[T_TOK * NHEADS * 256];
__device__ __half g_kpe16[T_TOK * ROPE_D];
__device__ __half g_ctx16[T_TOK * NHEADS*VHD];

// ---------------- common helpers ----------------
__device__ __forceinline__ uint32_t smem_u32(const void* p) {
    uint32_t a;
    asm("{ .reg .u64 t; cvta.to.shared.u64 t, %1; cvt.u32.u64 %0, t; }" : "=r"(a) : "l"(p));
    return a;
}
__device__ __forceinline__ void ldm4(uint32_t* r, uint32_t addr) {
    asm volatile("ldmatrix.sync.aligned.m8n8.x4.shared.b16 {%0,%1,%2,%3}, [%4];"
                 : "=r"(r[0]), "=r"(r[1]), "=r"(r[2]), "=r"(r[3]) : "r"(addr));
}
__device__ __forceinline__ void ldm4t(uint32_t* r, uint32_t addr) {
    asm volatile("ldmatrix.sync.aligned.m8n8.x4.trans.shared.b16 {%0,%1,%2,%3}, [%4];"
                 : "=r"(r[0]), "=r"(r[1]), "=r"(r[2]), "=r"(r[3]) : "r"(addr));
}
__device__ __forceinline__ void mma16816h(float* d, const uint32_t* a, const uint32_t* b) {
    asm volatile("mma.sync.aligned.m16n8k16.row.col.f32.f16.f16.f32 "
                 "{%0,%1,%2,%3}, {%4,%5,%6,%7}, {%8,%9}, {%0,%1,%2,%3};"
                 : "+f"(d[0]), "+f"(d[1]), "+f"(d[2]), "+f"(d[3])
                 : "r"(a[0]), "r"(a[1]), "r"(a[2]), "r"(a[3]), "r"(b[0]), "r"(b[1]));
}
__device__ __forceinline__ void cpa16(uint32_t dst, const void* src, uint32_t sz) {
    asm volatile("cp.async.cg.shared.global [%0], [%1], 16, %2;"
                 :: "r"(dst), "l"(src), "r"(sz) : "memory");
}
__device__ __forceinline__ void split1h(float v, __half& h, __half& l) {
    h = __float2half_rn(v);
    l = __float2half_rn(v - __half2float(h));
}

// ---------------- merged convert fp32 -> fp16 single, 6 regions ----------------
struct Cvt6P {
    const float* x[6];
    __half* h[6];
    int off[7];
};
__global__ void cvt6_kernel(Cvt6P P) {
    int i = blockIdx.x * blockDim.x + threadIdx.x;
    if (i >= P.off[6]) return;
    int r = 0;
#pragma unroll
    for (int k = 1; k < 6; ++k) if (i >= P.off[k]) r = k;
    int j = i - P.off[r];
    float4 v = ((const float4*)P.x[r])[j];
    __half2 hp0 = __halves2half2(__float2half_rn(v.x), __float2half_rn(v.y));
    __half2 hp1 = __halves2half2(__float2half_rn(v.z), __float2half_rn(v.w));
    uint2 hh; hh.x = *(uint32_t*)&hp0; hh.y = *(uint32_t*)&hp1;
    ((uint2*)P.h[r])[j] = hh;
}

// ============================================================================
// fp16 GEMM: C = A * B^T, single operands. 128x128 CTA, 2 CTAs/SM.
// BK=32, 4-stage cp.async, one sync per chunk, 8 warps. (R11, unchanged)
// ============================================================================
#define SMSTR 80
#define TILEB (128 * SMSTR)
#define STAGEB (2 * TILEB)
#define NSTAGE 4
#define GEMM_SMEM (NSTAGE * STAGEB)

struct GemmP {
    const __half *A, *B;
    float* C;
    __half *Hh, *Hl;
    int N, K;
};

__global__ __launch_bounds__(256, 2) void fp_gemm_dual(GemmP P0, GemmP P1, int xsplit) {
    extern __shared__ char sm[];
    const bool first = ((int)blockIdx.x < xsplit);
    const GemmP p = first ? P0 : P1;
    const int n0 = (first ? blockIdx.x : (blockIdx.x - xsplit)) * 128;
    const int K = p.K, N = p.N;

    const int tid = threadIdx.x;
    const int wid = tid >> 5;
    const int lane = tid & 31;
    const int m0 = blockIdx.y * 128;
    const int nvalid = (N - n0 < 128) ? (N - n0) : 128;

    const uint32_t sbase = smem_u32(sm);
    const int wr = wid >> 2, wc = wid & 3;
    const uint32_t a_row = wr * 64 + (lane & 15);
    const uint32_t a_colb = (lane >> 4) * 16;
    const uint32_t b_row = wc * 32 + (lane & 7) + ((lane >> 4) << 3);
    const uint32_t b_colb = ((lane >> 3) & 1) * 16;

    float acc[4][4][4];
#pragma unroll
    for (int i = 0; i < 4; ++i)
#pragma unroll
        for (int j = 0; j < 4; ++j)
#pragma unroll
            for (int e = 0; e < 4; ++e) acc[i][j][e] = 0.f;

    const int nch = K >> 5;

    auto issue_chunk = [&](int c) {
        const int k0 = c << 5;
        const uint32_t stb = sbase + (c & (NSTAGE - 1)) * STAGEB;
#pragma unroll
        for (int i = 0; i < 4; ++i) {
            int u = tid + i * 256;
            int tile = u >> 9;
            int row = (u & 511) >> 2;
            int c16 = u & 3;
            uint32_t dst = stb + tile * TILEB + row * SMSTR + c16 * 16;
            const __half* src;
            uint32_t sz = 16;
            if (tile == 0) src = p.A + (size_t)(m0 + row) * K + k0 + c16 * 8;
            else {
                src = p.B + (size_t)(n0 + row) * K + k0 + c16 * 8;
                if (row >= nvalid) sz = 0;
            }
            cpa16(dst, src, sz);
        }
        asm volatile("cp.async.commit_group;" ::: "memory");
    };

    issue_chunk(0);
    if (nch > 1) issue_chunk(1); else asm volatile("cp.async.commit_group;" ::: "memory");
    if (nch > 2) issue_chunk(2); else asm volatile("cp.async.commit_group;" ::: "memory");

    for (int c = 0; c < nch; ++c) {
        asm volatile("cp.async.wait_group 2;" ::: "memory");
        __syncthreads();
        if (c + 3 < nch) issue_chunk(c + 3);
        else asm volatile("cp.async.commit_group;" ::: "memory");

        const uint32_t stb = sbase + (c & (NSTAGE - 1)) * STAGEB;
#pragma unroll
        for (int ks = 0; ks < 2; ++ks) {
            const uint32_t kb = ks * 32;
            uint32_t ah[4][4], bh[2][4];
#pragma unroll
            for (int i = 0; i < 4; ++i)
                ldm4(ah[i], stb + (a_row + i * 16) * SMSTR + a_colb + kb);
#pragma unroll
            for (int jp = 0; jp < 2; ++jp)
                ldm4(bh[jp], stb + TILEB + (b_row + jp * 16) * SMSTR + b_colb + kb);
#pragma unroll
            for (int i = 0; i < 4; ++i)
#pragma unroll
                for (int j = 0; j < 4; ++j)
                    mma16816h(acc[i][j], ah[i], &bh[j >> 1][(j & 1) * 2]);
        }
    }

    const int gid = lane >> 2, tig = lane & 3;
#pragma unroll
    for (int i = 0; i < 4; ++i) {
#pragma unroll
        for (int rr = 0; rr < 2; ++rr) {
            int row = m0 + wr * 64 + i * 16 + gid + rr * 8;
#pragma unroll
            for (int j = 0; j < 4; ++j) {
                int col = n0 + wc * 32 + j * 8 + tig * 2;
                if (col < N) {
                    float v0 = acc[i][j][rr * 2], v1 = acc[i][j][rr * 2 + 1];
                    if (p.C) *(float2*)(p.C + (size_t)row * N + col) = make_float2(v0, v1);
                    if (p.Hh) {
                        __half h0,l0,h1,l1;
                        split1h(v0,h0,l0); split1h(v1,h1,l1);
                        __half2 hp = __halves2half2(h0, h1);
                        *(uint32_t*)(p.Hh + (size_t)row * N + col) = *(uint32_t*)&hp;
                        if (p.Hl) {
                            __half2 lp = __halves2half2(l0, l1);
                            *(uint32_t*)(p.Hl + (size_t)row * N + col) = *(uint32_t*)&lp;
                        }
                    }
                }
            }
        }
    }
}

// ---------------- dual RMSNorm -> fp16 single ----------------
struct RmsP {
    const float* x; const float* w;
    __half *y;
    int D, in_stride;
};
__global__ void rmsnorm_dual(RmsP P0, RmsP P1) {
    const RmsP p = (blockIdx.y == 0) ? P0 : P1;
    const int row = blockIdx.x;
    const float* xr = p.x + (size_t)row * p.in_stride;
    float ss = 0.f;
    for (int d = threadIdx.x; d < p.D; d += blockDim.x) { float v = xr[d]; ss += v * v; }
    __shared__ float red[32];
#pragma unroll
    for (int o = 16; o; o >>= 1) ss += __shfl_xor_sync(0xffffffffu, ss, o);
    if ((threadIdx.x & 31) == 0) red[threadIdx.x >> 5] = ss;
    __syncthreads();
    if (threadIdx.x < 32) {
        float v = (threadIdx.x < (blockDim.x >> 5)) ? red[threadIdx.x] : 0.f;
#pragma unroll
        for (int o = 16; o; o >>= 1) v += __shfl_xor_sync(0xffffffffu, v, o);
        if (threadIdx.x == 0) red[0] = v;
    }
    __syncthreads();
    float scale = rsqrtf(red[0] / (float)p.D + 1e-6f);
    for (int d = threadIdx.x; d < p.D; d += blockDim.x) {
        float v = p.w[d] * xr[d] * scale;
        p.y[(size_t)row * p.D + d] = __float2half_rn(v);
    }
}

// ---------------- YaRN ----------------
__device__ __forceinline__ void yarn_cs(int pos, int j, float& c, float& s) {
    float ex   = __expf(-(float)(2 * j) * (9.210340371976184f / 64.f));
    float fi   = ex * 0.025f;
    float ramp = ((float)j - 10.f) * (1.f / 13.f);
    ramp = fminf(fmaxf(ramp, 0.f), 1.f);
    float invf = fi * ramp + ex * (1.f - ramp);
    float ang  = (float)pos * invf;
    c = cosf(ang); s = sinf(ang);
}

__global__ void rope_k_kernel(const float* __restrict__ ckv, const int* __restrict__ pos_ids,
                              __half* __restrict__ kpe) {
    const int t = blockIdx.x;
    const int j = threadIdx.x;
    const int pos = pos_ids[t];
    const float* x = ckv + (size_t)t * KVW + KVLORA;
    float c, s; yarn_cs(pos, j, c, s);
    float x0 = x[2 * j], x1 = x[2 * j + 1];
    kpe[t * ROPE_D + j]      = __float2half_rn(x0 * c - x1 * s);
    kpe[t * ROPE_D + 32 + j] = __float2half_rn(x1 * c + x0 * s);
}

__global__ void rope_q_kernel(__half* __restrict__ qh, __half* __restrict__ ql,
                              const int* __restrict__ pos_ids) {
    const int t = blockIdx.x >> 4;
    const int h = blockIdx.x & 15;
    const int j = threadIdx.x;
    const int pos = pos_ids[t];
    __half* xh = qh + (size_t)t * (NHEADS * QHD) + h * QHD + NOPE;
    __half* xl = ql + (size_t)t * (NHEADS * QHD) + h * QHD + NOPE;
    float c, s; yarn_cs(pos, j, c, s);
    float x0 = __half2float(xh[2*j])   + __half2float(xl[2*j]);
    float x1 = __half2float(xh[2*j+1]) + __half2float(xl[2*j+1]);
    float r0 = x0 * c - x1 * s, r1 = x1 * c + x0 * s;
    __syncwarp();
    __half hh, ll;
    split1h(r0, hh, ll); xh[j] = hh;      xl[j] = ll;
    split1h(r1, hh, ll); xh[32 + j] = hh; xl[32 + j] = ll;
}

// ============================================================================
// Flash attention, fp16 HMMA. BM=128, BN=64, 8 warps.
// 3-stage KV ring, ONE sync per kt, 2-deep cp.async prefetch. P in registers.
// ============================================================================
#define FL_KSTR 400
#define FL_VSTR 272
#define FL_KVSTG (64 * FL_KSTR + 64 * FL_VSTR)    // 43008
#define FL_VOFF  (64 * FL_KSTR)
#define FL_QSTR 400
#define FL_SMEM (3 * FL_KVSTG)                    // 129024 (Q staging 102400 overlaps)

__global__ __launch_bounds__(256, 1) void flash_mma(
    const __half* __restrict__ qh, const __half* __restrict__ ql,
    const __half* __restrict__ kv,
    const __half* __restrict__ kpe,
    __half* __restrict__ ctx)
{
    extern __shared__ char sm[];
    const uint32_t sb = smem_u32(sm);
    const int qt = (int)gridDim.x - 1 - (int)blockIdx.x;
    const int hh = blockIdx.y, b = blockIdx.z;
    const int tid = threadIdx.x, wid = tid >> 5, lane = tid & 31;
    const int gid = lane >> 2, tig = lane & 3;
    const int t0 = b * S_LEN;

    const uint32_t a_row = wid * 16 + (lane & 15);
    const uint32_t a_colb = (lane >> 4) * 16;
    const uint32_t k_roff = (lane & 7) + ((lane >> 4) << 3);
    const uint32_t k_colb = ((lane >> 3) & 1) * 16;
    const uint32_t v_koff = (lane & 7) + ((lane >> 3) & 1) * 8;
    const uint32_t v_noff = (lane >> 4) * 8;

    // ---- prologue: stage Q, pull fragments, free the smem ----
    for (int idx = tid; idx < 128 * 24; idx += 256) {
        int r = idx / 24, u = idx % 24;
        size_t g = (size_t)(t0 + qt * 128 + r) * (NHEADS * QHD) + hh * QHD + u * 8;
        *(uint4*)(sm + r * FL_QSTR + u * 16) = *(const uint4*)(qh + g);
        *(uint4*)(sm + 51200 + r * FL_QSTR + u * 16) = *(const uint4*)(ql + g);
    }
    __syncthreads();
    uint32_t qfh[12][4], qfl[12][4];
#pragma unroll
    for (int ks = 0; ks < 12; ++ks) {
        ldm4(qfh[ks], sb + a_row * FL_QSTR + a_colb + ks * 32);
        ldm4(qfl[ks], sb + 51200 + a_row * FL_QSTR + a_colb + ks * 32);
    }
    __syncthreads();

    auto issue_kv = [&](int kt, int stage) {
        const uint32_t stb = sb + stage * FL_KVSTG;
        for (int idx = tid; idx < 64 * 24; idx += 256) {
            int r = idx / 24, u = idx % 24;
            int t = t0 + kt * 64 + r;
            const __half* src;
            if (u < 16) src = kv + (size_t)t * (NHEADS * 256) + hh * 256 + u * 8;
            else        src = kpe + (size_t)t * ROPE_D + (u - 16) * 8;
            cpa16(stb + r * FL_KSTR + u * 16, src, 16);
        }
        for (int idx = tid; idx < 64 * 16; idx += 256) {
            int r = idx >> 4, u = idx & 15;
            size_t g = (size_t)(t0 + kt * 64 + r) * (NHEADS * 256) + hh * 256 + 128 + u * 8;
            cpa16(stb + FL_VOFF + r * FL_VSTR + u * 16, kv + g, 16);
        }
        asm volatile("cp.async.commit_group;" ::: "memory");
    };

    float m_i[2], l_i[2], O[16][4];
    m_i[0] = m_i[1] = -1e30f; l_i[0] = l_i[1] = 0.f;
#pragma unroll
    for (int nf = 0; nf < 16; ++nf)
#pragma unroll
        for (int e = 0; e < 4; ++e) O[nf][e] = 0.f;

    const float mm = 0.1f * logf(40.f) + 1.f;
    const float sc = mm * mm * rsqrtf(192.f);

    const int nkt = 2 * qt + 2;
    issue_kv(0, 0);
    if (nkt > 1) issue_kv(1, 1); else asm volatile("cp.async.commit_group;" ::: "memory");

    int stage = 0, nstage = 2 % 3;   // stage of kt; stage of kt+2
    for (int kt = 0; kt < nkt; ++kt) {
        asm volatile("cp.async.wait_group 1;" ::: "memory");
        __syncthreads();
        // issue kt+2 into the stage last read at kt-1 (protected by the sync above)
        if (kt + 2 < nkt) issue_kv(kt + 2, nstage);
        else asm volatile("cp.async.commit_group;" ::: "memory");

        const uint32_t stb = sb + stage * FL_KVSTG;
        stage = (stage + 1 == 3) ? 0 : stage + 1;
        nstage = (nstage + 1 == 3) ? 0 : nstage + 1;

        // ---- QK: S = (Qh + Ql) * K ----
        float s[8][4];
#pragma unroll
        for (int nf = 0; nf < 8; ++nf)
#pragma unroll
            for (int e = 0; e < 4; ++e) s[nf][e] = 0.f;

#pragma unroll
        for (int ks = 0; ks < 12; ++ks) {
#pragma unroll
            for (int jb = 0; jb < 4; ++jb) {
                uint32_t bh4[4];
                uint32_t brow = jb * 16 + k_roff;
                ldm4(bh4, stb + brow * FL_KSTR + k_colb + ks * 32);
                mma16816h(s[2*jb],   qfh[ks], &bh4[0]);
                mma16816h(s[2*jb+1], qfh[ks], &bh4[2]);
                mma16816h(s[2*jb],   qfl[ks], &bh4[0]);
                mma16816h(s[2*jb+1], qfl[ks], &bh4[2]);
            }
        }

        // ---- softmax ----
#pragma unroll
        for (int rr = 0; rr < 2; ++rr) {
            int grow = qt * 128 + wid * 16 + gid + rr * 8;
            float tmax = -1e30f;
#pragma unroll
            for (int nf = 0; nf < 8; ++nf) {
#pragma unroll
                for (int e = 0; e < 2; ++e) {
                    int gcol = kt * 64 + nf * 8 + tig * 2 + e;
                    float v = s[nf][rr * 2 + e] * sc;
                    if (gcol > grow) v = -1e30f;
                    s[nf][rr * 2 + e] = v;
                    tmax = fmaxf(tmax, v);
                }
            }
            tmax = fmaxf(tmax, __shfl_xor_sync(0xffffffffu, tmax, 1));
            tmax = fmaxf(tmax, __shfl_xor_sync(0xffffffffu, tmax, 2));
            float nm = fmaxf(m_i[rr], tmax);
            float fac = __expf(m_i[rr] - nm);
            float psum = 0.f;
#pragma unroll
            for (int nf = 0; nf < 8; ++nf) {
#pragma unroll
                for (int e = 0; e < 2; ++e) {
                    float pv = __expf(s[nf][rr * 2 + e] - nm);
                    s[nf][rr * 2 + e] = pv;
                    psum += pv;
                }
            }
            psum += __shfl_xor_sync(0xffffffffu, psum, 1);
            psum += __shfl_xor_sync(0xffffffffu, psum, 2);
            l_i[rr] = l_i[rr] * fac + psum;
            m_i[rr] = nm;
#pragma unroll
            for (int nf = 0; nf < 16; ++nf) {
                O[nf][rr * 2] *= fac;
                O[nf][rr * 2 + 1] *= fac;
            }
        }

        // ---- P -> A-operand fragments in registers (hi/lo) ----
        uint32_t aph[4][4], apl[4][4];
#pragma unroll
        for (int ks = 0; ks < 4; ++ks) {
#pragma unroll
            for (int q = 0; q < 2; ++q) {
                int nf = 2 * ks + q;
                __half h0,l0,h1,l1,h2,l2,h3,l3;
                split1h(s[nf][0], h0, l0); split1h(s[nf][1], h1, l1);
                split1h(s[nf][2], h2, l2); split1h(s[nf][3], h3, l3);
                __half2 ph01 = __halves2half2(h0, h1);
                __half2 ph23 = __halves2half2(h2, h3);
                __half2 pl01 = __halves2half2(l0, l1);
                __half2 pl23 = __halves2half2(l2, l3);
                aph[ks][2*q]   = *(uint32_t*)&ph01;
                aph[ks][2*q+1] = *(uint32_t*)&ph23;
                apl[ks][2*q]   = *(uint32_t*)&pl01;
                apl[ks][2*q+1] = *(uint32_t*)&pl23;
            }
        }

        // ---- AV: O += (Ph + Pl) * V ----
#pragma unroll
        for (int ks = 0; ks < 4; ++ks) {
            uint32_t vrow = ks * 16 + v_koff;
#pragma unroll
            for (int nb = 0; nb < 8; ++nb) {
                uint32_t bvh[4];
                uint32_t vcol = (nb * 16 + v_noff) * 2;
                ldm4t(bvh, stb + FL_VOFF + vrow * FL_VSTR + vcol);
                mma16816h(O[2*nb],   aph[ks], &bvh[0]);
                mma16816h(O[2*nb+1], aph[ks], &bvh[2]);
                mma16816h(O[2*nb],   apl[ks], &bvh[0]);
                mma16816h(O[2*nb+1], apl[ks], &bvh[2]);
            }
        }
    }

#pragma unroll
    for (int rr = 0; rr < 2; ++rr) {
        float inv = 1.f / l_i[rr];
        int row = t0 + qt * 128 + wid * 16 + gid + rr * 8;
#pragma unroll
        for (int nf = 0; nf < 16; ++nf) {
            int col = nf * 8 + tig * 2;
            float v0 = O[nf][rr * 2] * inv, v1 = O[nf][rr * 2 + 1] * inv;
            __half2 hp = __halves2half2(__float2half_rn(v0), __float2half_rn(v1));
            size_t g = (size_t)row * (NHEADS * VHD) + hh * VHD + col;
            *(uint32_t*)(ctx + g) = *(uint32_t*)&hp;
        }
    }
}

// ---------------- launch ----------------
extern "C" void kernel_launch(void* const* d_in, const int* in_sizes, int n_in,
                              void* d_out, int out_size) {
    (void)in_sizes; (void)n_in; (void)out_size;
    const float* X     = (const float*)d_in[0];
    const int*   pos   = (const int*)  d_in[1];
    const float* wq_a  = (const float*)d_in[2];
    const float* qln   = (const float*)d_in[3];
    const float* wq_b  = (const float*)d_in[4];
    const float* wkv_a = (const float*)d_in[5];
    const float* kvln  = (const float*)d_in[6];
    const float* wkv_b = (const float*)d_in[7];
    const float* wo    = (const float*)d_in[8];
    float* out = (float*)d_out;

    float *qa, *ckv;
    __half *X16,*wqa16,*wqb16,*wkva16,*wkvb16,*wo16;
    __half *qan16,*ckvn16,*q16h,*q16l,*kv16,*kpe16,*ctx16;
    cudaGetSymbolAddress((void**)&qa, g_qa);
    cudaGetSymbolAddress((void**)&ckv, g_ckv);
    cudaGetSymbolAddress((void**)&X16, g_X16);
    cudaGetSymbolAddress((void**)&wqa16, g_wqa16);
    cudaGetSymbolAddress((void**)&wqb16, g_wqb16);
    cudaGetSymbolAddress((void**)&wkva16, g_wkva16);
    cudaGetSymbolAddress((void**)&wkvb16, g_wkvb16);
    cudaGetSymbolAddress((void**)&wo16, g_wo16);
    cudaGetSymbolAddress((void**)&qan16, g_qan16);
    cudaGetSymbolAddress((void**)&ckvn16, g_ckvn16);
    cudaGetSymbolAddress((void**)&q16h, g_q16h);
    cudaGetSymbolAddress((void**)&q16l, g_q16l);
    cudaGetSymbolAddress((void**)&kv16, g_kv16);
    cudaGetSymbolAddress((void**)&kpe16, g_kpe16);
    cudaGetSymbolAddress((void**)&ctx16, g_ctx16);

    cudaFuncSetAttribute(fp_gemm_dual, cudaFuncAttributeMaxDynamicSharedMemorySize, GEMM_SMEM);
    cudaFuncSetAttribute(flash_mma, cudaFuncAttributeMaxDynamicSharedMemorySize, FL_SMEM);

    const dim3 blk(256);
    const int mt = T_TOK / 128;  // 32

    // merged input conversions (all single fp16)
    {
        Cvt6P P;
        P.x[0]=X;     P.h[0]=X16;
        P.x[1]=wq_a;  P.h[1]=wqa16;
        P.x[2]=wq_b;  P.h[2]=wqb16;
        P.x[3]=wkv_a; P.h[3]=wkva16;
        P.x[4]=wkv_b; P.h[4]=wkvb16;
        P.x[5]=wo;    P.h[5]=wo16;
        int lens[6] = { T_TOK*HIDDEN/4, QLORA*HIDDEN/4, NHEADS*QHD*QLORA/4,
                        KVW*HIDDEN/4, NHEADS*256*KVLORA/4, HIDDEN*NHEADS*VHD/4 };
        P.off[0] = 0;
        for (int i = 0; i < 6; ++i) P.off[i+1] = P.off[i] + lens[i];
        cvt6_kernel<<<(P.off[6] + 255) / 256, 256>>>(P);
    }

    // fused a-projections -> fp32
    {
        GemmP p0 = { X16, wqa16,  qa,  nullptr, nullptr, QLORA, HIDDEN };
        GemmP p1 = { X16, wkva16, ckv, nullptr, nullptr, KVW,   HIDDEN };
        fp_gemm_dual<<<dim3(QLORA/128 + (KVW+127)/128, mt), blk, GEMM_SMEM>>>(p0, p1, QLORA/128);
    }

    // fused rmsnorms -> fp16
    {
        RmsP p0 = { qa, qln, qan16, QLORA, QLORA };
        RmsP p1 = { ckv, kvln, ckvn16, KVLORA, KVW };
        rmsnorm_dual<<<dim3(T_TOK, 2), 256>>>(p0, p1);
    }
    rope_k_kernel<<<T_TOK, 32>>>(ckv, pos, kpe16);

    // fused b-projections: q -> fp16 hi/lo ; kv -> fp16 single
    {
        GemmP p0 = { qan16,  wqb16,  nullptr, q16h, q16l,   NHEADS*QHD, QLORA };
        GemmP p1 = { ckvn16, wkvb16, nullptr, kv16, nullptr, NHEADS*256, KVLORA };
        fp_gemm_dual<<<dim3((NHEADS*QHD)/128 + (NHEADS*256)/128, mt), blk, GEMM_SMEM>>>(
            p0, p1, (NHEADS*QHD)/128);
    }

    rope_q_kernel<<<T_TOK * NHEADS, 32>>>(q16h, q16l, pos);

    flash_mma<<<dim3(S_LEN / 128, NHEADS, BATCH), blk, FL_SMEM>>>(q16h, q16l, kv16, kpe16,
                                                                  ctx16);

    // output projection -> fp32 out
    {
        GemmP p0 = { ctx16, wo16, out, nullptr, nullptr, HIDDEN, NHEADS*VHD };
        fp_gemm_dual<<<dim3(HIDDEN/128, mt), blk, GEMM_SMEM>>>(p0, p0, HIDDEN/128);
    }
}

// round 14
// speedup vs baseline: 3.5047x; 1.0298x over previous
#include <cuda_runtime.h>
#include <cuda_fp16.h>
#include <math.h>
#include <stdint.h>

// ---------------- problem constants ----------------
#define S_LEN   2048
#define BATCH   2
#define T_TOK   (BATCH * S_LEN)
#define HIDDEN  2048
#define QLORA   1536
#define KVLORA  512
#define NHEADS  16
#define NOPE    128
#define ROPE_D  64
#define QHD     192
#define VHD     128
#define KVW     576

// ---------------- scratch ----------------
__device__ float g_qa [T_TOK * QLORA];
__device__ float g_ckv[T_TOK * KVW];

__device__ __half g_X16[T_TOK * HIDDEN];
__device__ __half g_wqa16[QLORA * HIDDEN];
__device__ __half g_wqb16[NHEADS*QHD*QLORA];
__device__ __half g_wkva16[KVW * HIDDEN];
__device__ __half g_wkvb16[NHEADS*256*KVLORA];
__device__ __half g_wo16[HIDDEN*NHEADS*VHD];
__device__ __half g_qan16[T_TOK * QLORA];
__device__ __half g_ckvn16[T_TOK * KVLORA];
__device__ __half g_q16h[T_TOK * NHEADS * QHD], g_q16l[T_TOK * NHEADS * QHD];
__device__ __half g_kv16[T_TOK * NHEADS * 256];
__device__ __half g_kpe16[T_TOK * ROPE_D];
__device__ __half g_ctx16[T_TOK * NHEADS*VHD];

// ---------------- common helpers ----------------
__device__ __forceinline__ uint32_t smem_u32(const void* p) {
    uint32_t a;
    asm("{ .reg .u64 t; cvta.to.shared.u64 t, %1; cvt.u32.u64 %0, t; }" : "=r"(a) : "l"(p));
    return a;
}
__device__ __forceinline__ void ldm4(uint32_t* r, uint32_t addr) {
    asm volatile("ldmatrix.sync.aligned.m8n8.x4.shared.b16 {%0,%1,%2,%3}, [%4];"
                 : "=r"(r[0]), "=r"(r[1]), "=r"(r[2]), "=r"(r[3]) : "r"(addr));
}
__device__ __forceinline__ void ldm4t(uint32_t* r, uint32_t addr) {
    asm volatile("ldmatrix.sync.aligned.m8n8.x4.trans.shared.b16 {%0,%1,%2,%3}, [%4];"
                 : "=r"(r[0]), "=r"(r[1]), "=r"(r[2]), "=r"(r[3]) : "r"(addr));
}
__device__ __forceinline__ void mma16816h(float* d, const uint32_t* a, const uint32_t* b) {
    asm volatile("mma.sync.aligned.m16n8k16.row.col.f32.f16.f16.f32 "
                 "{%0,%1,%2,%3}, {%4,%5,%6,%7}, {%8,%9}, {%0,%1,%2,%3};"
                 : "+f"(d[0]), "+f"(d[1]), "+f"(d[2]), "+f"(d[3])
                 : "r"(a[0]), "r"(a[1]), "r"(a[2]), "r"(a[3]), "r"(b[0]), "r"(b[1]));
}
__device__ __forceinline__ void cpa16(uint32_t dst, const void* src, uint32_t sz) {
    asm volatile("cp.async.cg.shared.global [%0], [%1], 16, %2;"
                 :: "r"(dst), "l"(src), "r"(sz) : "memory");
}
__device__ __forceinline__ void split1h(float v, __half& h, __half& l) {
    h = __float2half_rn(v);
    l = __float2half_rn(v - __half2float(h));
}

// ---------------- merged convert fp32 -> fp16 single, 6 regions ----------------
struct Cvt6P {
    const float* x[6];
    __half* h[6];
    int off[7];
};
__global__ void cvt6_kernel(Cvt6P P) {
    int i = blockIdx.x * blockDim.x + threadIdx.x;
    if (i >= P.off[6]) return;
    int r = 0;
#pragma unroll
    for (int k = 1; k < 6; ++k) if (i >= P.off[k]) r = k;
    int j = i - P.off[r];
    float4 v = ((const float4*)P.x[r])[j];
    __half2 hp0 = __halves2half2(__float2half_rn(v.x), __float2half_rn(v.y));
    __half2 hp1 = __halves2half2(__float2half_rn(v.z), __float2half_rn(v.w));
    uint2 hh; hh.x = *(uint32_t*)&hp0; hh.y = *(uint32_t*)&hp1;
    ((uint2*)P.h[r])[j] = hh;
}

// ============================================================================
// fp16 GEMM: C = A * B^T, single operands. 128x128 CTA, 2 CTAs/SM.
// BK=32, 4-stage cp.async, one sync per chunk, 8 warps. (R11, unchanged)
// ============================================================================
#define SMSTR 80
#define TILEB (128 * SMSTR)
#define STAGEB (2 * TILEB)
#define NSTAGE 4
#define GEMM_SMEM (NSTAGE * STAGEB)

struct GemmP {
    const __half *A, *B;
    float* C;
    __half *Hh, *Hl;
    int N, K;
};

__global__ __launch_bounds__(256, 2) void fp_gemm_dual(GemmP P0, GemmP P1, int xsplit) {
    extern __shared__ char sm[];
    const bool first = ((int)blockIdx.x < xsplit);
    const GemmP p = first ? P0 : P1;
    const int n0 = (first ? blockIdx.x : (blockIdx.x - xsplit)) * 128;
    const int K = p.K, N = p.N;

    const int tid = threadIdx.x;
    const int wid = tid >> 5;
    const int lane = tid & 31;
    const int m0 = blockIdx.y * 128;
    const int nvalid = (N - n0 < 128) ? (N - n0) : 128;

    const uint32_t sbase = smem_u32(sm);
    const int wr = wid >> 2, wc = wid & 3;
    const uint32_t a_row = wr * 64 + (lane & 15);
    const uint32_t a_colb = (lane >> 4) * 16;
    const uint32_t b_row = wc * 32 + (lane & 7) + ((lane >> 4) << 3);
    const uint32_t b_colb = ((lane >> 3) & 1) * 16;

    float acc[4][4][4];
#pragma unroll
    for (int i = 0; i < 4; ++i)
#pragma unroll
        for (int j = 0; j < 4; ++j)
#pragma unroll
            for (int e = 0; e < 4; ++e) acc[i][j][e] = 0.f;

    const int nch = K >> 5;

    auto issue_chunk = [&](int c) {
        const int k0 = c << 5;
        const uint32_t stb = sbase + (c & (NSTAGE - 1)) * STAGEB;
#pragma unroll
        for (int i = 0; i < 4; ++i) {
            int u = tid + i * 256;
            int tile = u >> 9;
            int row = (u & 511) >> 2;
            int c16 = u & 3;
            uint32_t dst = stb + tile * TILEB + row * SMSTR + c16 * 16;
            const __half* src;
            uint32_t sz = 16;
            if (tile == 0) src = p.A + (size_t)(m0 + row) * K + k0 + c16 * 8;
            else {
                src = p.B + (size_t)(n0 + row) * K + k0 + c16 * 8;
                if (row >= nvalid) sz = 0;
            }
            cpa16(dst, src, sz);
        }
        asm volatile("cp.async.commit_group;" ::: "memory");
    };

    issue_chunk(0);
    if (nch > 1) issue_chunk(1); else asm volatile("cp.async.commit_group;" ::: "memory");
    if (nch > 2) issue_chunk(2); else asm volatile("cp.async.commit_group;" ::: "memory");

    for (int c = 0; c < nch; ++c) {
        asm volatile("cp.async.wait_group 2;" ::: "memory");
        __syncthreads();
        if (c + 3 < nch) issue_chunk(c + 3);
        else asm volatile("cp.async.commit_group;" ::: "memory");

        const uint32_t stb = sbase + (c & (NSTAGE - 1)) * STAGEB;
#pragma unroll
        for (int ks = 0; ks < 2; ++ks) {
            const uint32_t kb = ks * 32;
            uint32_t ah[4][4], bh[2][4];
#pragma unroll
            for (int i = 0; i < 4; ++i)
                ldm4(ah[i], stb + (a_row + i * 16) * SMSTR + a_colb + kb);
#pragma unroll
            for (int jp = 0; jp < 2; ++jp)
                ldm4(bh[jp], stb + TILEB + (b_row + jp * 16) * SMSTR + b_colb + kb);
#pragma unroll
            for (int i = 0; i < 4; ++i)
#pragma unroll
                for (int j = 0; j < 4; ++j)
                    mma16816h(acc[i][j], ah[i], &bh[j >> 1][(j & 1) * 2]);
        }
    }

    const int gid = lane >> 2, tig = lane & 3;
#pragma unroll
    for (int i = 0; i < 4; ++i) {
#pragma unroll
        for (int rr = 0; rr < 2; ++rr) {
            int row = m0 + wr * 64 + i * 16 + gid + rr * 8;
#pragma unroll
            for (int j = 0; j < 4; ++j) {
                int col = n0 + wc * 32 + j * 8 + tig * 2;
                if (col < N) {
                    float v0 = acc[i][j][rr * 2], v1 = acc[i][j][rr * 2 + 1];
                    if (p.C) *(float2*)(p.C + (size_t)row * N + col) = make_float2(v0, v1);
                    if (p.Hh) {
                        __half h0,l0,h1,l1;
                        split1h(v0,h0,l0); split1h(v1,h1,l1);
                        __half2 hp = __halves2half2(h0, h1);
                        *(uint32_t*)(p.Hh + (size_t)row * N + col) = *(uint32_t*)&hp;
                        if (p.Hl) {
                            __half2 lp = __halves2half2(l0, l1);
                            *(uint32_t*)(p.Hl + (size_t)row * N + col) = *(uint32_t*)&lp;
                        }
                    }
                }
            }
        }
    }
}

// ---------------- dual RMSNorm -> fp16 single ----------------
struct RmsP {
    const float* x; const float* w;
    __half *y;
    int D, in_stride;
};
__global__ void rmsnorm_dual(RmsP P0, RmsP P1) {
    const RmsP p = (blockIdx.y == 0) ? P0 : P1;
    const int row = blockIdx.x;
    const float* xr = p.x + (size_t)row * p.in_stride;
    float ss = 0.f;
    for (int d = threadIdx.x; d < p.D; d += blockDim.x) { float v = xr[d]; ss += v * v; }
    __shared__ float red[32];
#pragma unroll
    for (int o = 16; o; o >>= 1) ss += __shfl_xor_sync(0xffffffffu, ss, o);
    if ((threadIdx.x & 31) == 0) red[threadIdx.x >> 5] = ss;
    __syncthreads();
    if (threadIdx.x < 32) {
        float v = (threadIdx.x < (blockDim.x >> 5)) ? red[threadIdx.x] : 0.f;
#pragma unroll
        for (int o = 16; o; o >>= 1) v += __shfl_xor_sync(0xffffffffu, v, o);
        if (threadIdx.x == 0) red[0] = v;
    }
    __syncthreads();
    float scale = rsqrtf(red[0] / (float)p.D + 1e-6f);
    for (int d = threadIdx.x; d < p.D; d += blockDim.x) {
        float v = p.w[d] * xr[d] * scale;
        p.y[(size_t)row * p.D + d] = __float2half_rn(v);
    }
}

// ---------------- YaRN ----------------
__device__ __forceinline__ void yarn_cs(int pos, int j, float& c, float& s) {
    float ex   = __expf(-(float)(2 * j) * (9.210340371976184f / 64.f));
    float fi   = ex * 0.025f;
    float ramp = ((float)j - 10.f) * (1.f / 13.f);
    ramp = fminf(fmaxf(ramp, 0.f), 1.f);
    float invf = fi * ramp + ex * (1.f - ramp);
    float ang  = (float)pos * invf;
    c = cosf(ang); s = sinf(ang);
}

__global__ void rope_k_kernel(const float* __restrict__ ckv, const int* __restrict__ pos_ids,
                              __half* __restrict__ kpe) {
    const int t = blockIdx.x;
    const int j = threadIdx.x;
    const int pos = pos_ids[t];
    const float* x = ckv + (size_t)t * KVW + KVLORA;
    float c, s; yarn_cs(pos, j, c, s);
    float x0 = x[2 * j], x1 = x[2 * j + 1];
    kpe[t * ROPE_D + j]      = __float2half_rn(x0 * c - x1 * s);
    kpe[t * ROPE_D + 32 + j] = __float2half_rn(x1 * c + x0 * s);
}

__global__ void rope_q_kernel(__half* __restrict__ qh, __half* __restrict__ ql,
                              const int* __restrict__ pos_ids) {
    const int t = blockIdx.x >> 4;
    const int h = blockIdx.x & 15;
    const int j = threadIdx.x;
    const int pos = pos_ids[t];
    __half* xh = qh + (size_t)t * (NHEADS * QHD) + h * QHD + NOPE;
    __half* xl = ql + (size_t)t * (NHEADS * QHD) + h * QHD + NOPE;
    float c, s; yarn_cs(pos, j, c, s);
    float x0 = __half2float(xh[2*j])   + __half2float(xl[2*j]);
    float x1 = __half2float(xh[2*j+1]) + __half2float(xl[2*j+1]);
    float r0 = x0 * c - x1 * s, r1 = x1 * c + x0 * s;
    __syncwarp();
    __half hh, ll;
    split1h(r0, hh, ll); xh[j] = hh;      xl[j] = ll;
    split1h(r1, hh, ll); xh[32 + j] = hh; xl[32 + j] = ll;
}

// ============================================================================
// Flash attention, fp16 HMMA. BM=64, BN=64, 4 warps, 2 CTAs/SM.
// 2-stage KV ring, P in registers. Math per q-row identical to R13.
// ============================================================================
#define FL_KSTR 400
#define FL_VSTR 272
#define FL_KVSTG (64 * FL_KSTR + 64 * FL_VSTR)    // 43008
#define FL_VOFF  (64 * FL_KSTR)
#define FL_QSTR 400
#define FL_QLO   25600                            // Q lo staging offset (64 rows)
#define FL_SMEM (2 * FL_KVSTG)                    // 86016 per CTA

__global__ __launch_bounds__(128, 2) void flash_mma(
    const __half* __restrict__ qh, const __half* __restrict__ ql,
    const __half* __restrict__ kv,
    const __half* __restrict__ kpe,
    __half* __restrict__ ctx)
{
    extern __shared__ char sm[];
    const uint32_t sb = smem_u32(sm);
    const int qt = (int)gridDim.x - 1 - (int)blockIdx.x;   // heavy tiles first
    const int hh = blockIdx.y, b = blockIdx.z;
    const int tid = threadIdx.x, wid = tid >> 5, lane = tid & 31;
    const int gid = lane >> 2, tig = lane & 3;
    const int t0 = b * S_LEN;

    const uint32_t a_row = wid * 16 + (lane & 15);
    const uint32_t a_colb = (lane >> 4) * 16;
    const uint32_t k_roff = (lane & 7) + ((lane >> 4) << 3);
    const uint32_t k_colb = ((lane >> 3) & 1) * 16;
    const uint32_t v_koff = (lane & 7) + ((lane >> 3) & 1) * 8;
    const uint32_t v_noff = (lane >> 4) * 8;

    // ---- prologue: stage Q (64 x 192 hi+lo), pull fragments ----
    for (int idx = tid; idx < 64 * 24; idx += 128) {
        int r = idx / 24, u = idx % 24;
        size_t g = (size_t)(t0 + qt * 64 + r) * (NHEADS * QHD) + hh * QHD + u * 8;
        *(uint4*)(sm + r * FL_QSTR + u * 16) = *(const uint4*)(qh + g);
        *(uint4*)(sm + FL_QLO + r * FL_QSTR + u * 16) = *(const uint4*)(ql + g);
    }
    __syncthreads();
    uint32_t qfh[12][4], qfl[12][4];
#pragma unroll
    for (int ks = 0; ks < 12; ++ks) {
        ldm4(qfh[ks], sb + a_row * FL_QSTR + a_colb + ks * 32);
        ldm4(qfl[ks], sb + FL_QLO + a_row * FL_QSTR + a_colb + ks * 32);
    }
    __syncthreads();

    auto issue_kv = [&](int kt) {
        const uint32_t stb = sb + (kt & 1) * FL_KVSTG;
        for (int idx = tid; idx < 64 * 24; idx += 128) {
            int r = idx / 24, u = idx % 24;
            int t = t0 + kt * 64 + r;
            const __half* src;
            if (u < 16) src = kv + (size_t)t * (NHEADS * 256) + hh * 256 + u * 8;
            else        src = kpe + (size_t)t * ROPE_D + (u - 16) * 8;
            cpa16(stb + r * FL_KSTR + u * 16, src, 16);
        }
        for (int idx = tid; idx < 64 * 16; idx += 128) {
            int r = idx >> 4, u = idx & 15;
            size_t g = (size_t)(t0 + kt * 64 + r) * (NHEADS * 256) + hh * 256 + 128 + u * 8;
            cpa16(stb + FL_VOFF + r * FL_VSTR + u * 16, kv + g, 16);
        }
        asm volatile("cp.async.commit_group;" ::: "memory");
    };

    float m_i[2], l_i[2], O[16][4];
    m_i[0] = m_i[1] = -1e30f; l_i[0] = l_i[1] = 0.f;
#pragma unroll
    for (int nf = 0; nf < 16; ++nf)
#pragma unroll
        for (int e = 0; e < 4; ++e) O[nf][e] = 0.f;

    const float mm = 0.1f * logf(40.f) + 1.f;
    const float sc = mm * mm * rsqrtf(192.f);

    const int nkt = qt + 1;
    issue_kv(0);

    for (int kt = 0; kt < nkt; ++kt) {
        if (kt + 1 < nkt) {
            issue_kv(kt + 1);
            asm volatile("cp.async.wait_group 1;" ::: "memory");
        } else {
            asm volatile("cp.async.wait_group 0;" ::: "memory");
        }
        __syncthreads();
        const uint32_t stb = sb + (kt & 1) * FL_KVSTG;

        // ---- QK: S = (Qh + Ql) * K ----
        float s[8][4];
#pragma unroll
        for (int nf = 0; nf < 8; ++nf)
#pragma unroll
            for (int e = 0; e < 4; ++e) s[nf][e] = 0.f;

#pragma unroll
        for (int ks = 0; ks < 12; ++ks) {
#pragma unroll
            for (int jb = 0; jb < 4; ++jb) {
                uint32_t bh4[4];
                uint32_t brow = jb * 16 + k_roff;
                ldm4(bh4, stb + brow * FL_KSTR + k_colb + ks * 32);
                mma16816h(s[2*jb],   qfh[ks], &bh4[0]);
                mma16816h(s[2*jb+1], qfh[ks], &bh4[2]);
                mma16816h(s[2*jb],   qfl[ks], &bh4[0]);
                mma16816h(s[2*jb+1], qfl[ks], &bh4[2]);
            }
        }

        // ---- softmax ----
#pragma unroll
        for (int rr = 0; rr < 2; ++rr) {
            int grow = qt * 64 + wid * 16 + gid + rr * 8;
            float tmax = -1e30f;
#pragma unroll
            for (int nf = 0; nf < 8; ++nf) {
#pragma unroll
                for (int e = 0; e < 2; ++e) {
                    int gcol = kt * 64 + nf * 8 + tig * 2 + e;
                    float v = s[nf][rr * 2 + e] * sc;
                    if (gcol > grow) v = -1e30f;
                    s[nf][rr * 2 + e] = v;
                    tmax = fmaxf(tmax, v);
                }
            }
            tmax = fmaxf(tmax, __shfl_xor_sync(0xffffffffu, tmax, 1));
            tmax = fmaxf(tmax, __shfl_xor_sync(0xffffffffu, tmax, 2));
            float nm = fmaxf(m_i[rr], tmax);
            float fac = __expf(m_i[rr] - nm);
            float psum = 0.f;
#pragma unroll
            for (int nf = 0; nf < 8; ++nf) {
#pragma unroll
                for (int e = 0; e < 2; ++e) {
                    float pv = __expf(s[nf][rr * 2 + e] - nm);
                    s[nf][rr * 2 + e] = pv;
                    psum += pv;
                }
            }
            psum += __shfl_xor_sync(0xffffffffu, psum, 1);
            psum += __shfl_xor_sync(0xffffffffu, psum, 2);
            l_i[rr] = l_i[rr] * fac + psum;
            m_i[rr] = nm;
#pragma unroll
            for (int nf = 0; nf < 16; ++nf) {
                O[nf][rr * 2] *= fac;
                O[nf][rr * 2 + 1] *= fac;
            }
        }

        // ---- P -> A-operand fragments in registers (hi/lo) ----
        uint32_t aph[4][4], apl[4][4];
#pragma unroll
        for (int ks = 0; ks < 4; ++ks) {
#pragma unroll
            for (int q = 0; q < 2; ++q) {
                int nf = 2 * ks + q;
                __half h0,l0,h1,l1,h2,l2,h3,l3;
                split1h(s[nf][0], h0, l0); split1h(s[nf][1], h1, l1);
                split1h(s[nf][2], h2, l2); split1h(s[nf][3], h3, l3);
                __half2 ph01 = __halves2half2(h0, h1);
                __half2 ph23 = __halves2half2(h2, h3);
                __half2 pl01 = __halves2half2(l0, l1);
                __half2 pl23 = __halves2half2(l2, l3);
                aph[ks][2*q]   = *(uint32_t*)&ph01;
                aph[ks][2*q+1] = *(uint32_t*)&ph23;
                apl[ks][2*q]   = *(uint32_t*)&pl01;
                apl[ks][2*q+1] = *(uint32_t*)&pl23;
            }
        }

        // ---- AV: O += (Ph + Pl) * V ----
#pragma unroll
        for (int ks = 0; ks < 4; ++ks) {
            uint32_t vrow = ks * 16 + v_koff;
#pragma unroll
            for (int nb = 0; nb < 8; ++nb) {
                uint32_t bvh[4];
                uint32_t vcol = (nb * 16 + v_noff) * 2;
                ldm4t(bvh, stb + FL_VOFF + vrow * FL_VSTR + vcol);
                mma16816h(O[2*nb],   aph[ks], &bvh[0]);
                mma16816h(O[2*nb+1], aph[ks], &bvh[2]);
                mma16816h(O[2*nb],   apl[ks], &bvh[0]);
                mma16816h(O[2*nb+1], apl[ks], &bvh[2]);
            }
        }
        __syncthreads();   // WAR guard: stage (kt+1)&1 reads done before issue(kt+2)
    }

#pragma unroll
    for (int rr = 0; rr < 2; ++rr) {
        float inv = 1.f / l_i[rr];
        int row = t0 + qt * 64 + wid * 16 + gid + rr * 8;
#pragma unroll
        for (int nf = 0; nf < 16; ++nf) {
            int col = nf * 8 + tig * 2;
            float v0 = O[nf][rr * 2] * inv, v1 = O[nf][rr * 2 + 1] * inv;
            __half2 hp = __halves2half2(__float2half_rn(v0), __float2half_rn(v1));
            size_t g = (size_t)row * (NHEADS * VHD) + hh * VHD + col;
            *(uint32_t*)(ctx + g) = *(uint32_t*)&hp;
        }
    }
}

// ---------------- launch ----------------
extern "C" void kernel_launch(void* const* d_in, const int* in_sizes, int n_in,
                              void* d_out, int out_size) {
    (void)in_sizes; (void)n_in; (void)out_size;
    const float* X     = (const float*)d_in[0];
    const int*   pos   = (const int*)  d_in[1];
    const float* wq_a  = (const float*)d_in[2];
    const float* qln   = (const float*)d_in[3];
    const float* wq_b  = (const float*)d_in[4];
    const float* wkv_a = (const float*)d_in[5];
    const float* kvln  = (const float*)d_in[6];
    const float* wkv_b = (const float*)d_in[7];
    const float* wo    = (const float*)d_in[8];
    float* out = (float*)d_out;

    float *qa, *ckv;
    __half *X16,*wqa16,*wqb16,*wkva16,*wkvb16,*wo16;
    __half *qan16,*ckvn16,*q16h,*q16l,*kv16,*kpe16,*ctx16;
    cudaGetSymbolAddress((void**)&qa, g_qa);
    cudaGetSymbolAddress((void**)&ckv, g_ckv);
    cudaGetSymbolAddress((void**)&X16, g_X16);
    cudaGetSymbolAddress((void**)&wqa16, g_wqa16);
    cudaGetSymbolAddress((void**)&wqb16, g_wqb16);
    cudaGetSymbolAddress((void**)&wkva16, g_wkva16);
    cudaGetSymbolAddress((void**)&wkvb16, g_wkvb16);
    cudaGetSymbolAddress((void**)&wo16, g_wo16);
    cudaGetSymbolAddress((void**)&qan16, g_qan16);
    cudaGetSymbolAddress((void**)&ckvn16, g_ckvn16);
    cudaGetSymbolAddress((void**)&q16h, g_q16h);
    cudaGetSymbolAddress((void**)&q16l, g_q16l);
    cudaGetSymbolAddress((void**)&kv16, g_kv16);
    cudaGetSymbolAddress((void**)&kpe16, g_kpe16);
    cudaGetSymbolAddress((void**)&ctx16, g_ctx16);

    cudaFuncSetAttribute(fp_gemm_dual, cudaFuncAttributeMaxDynamicSharedMemorySize, GEMM_SMEM);
    cudaFuncSetAttribute(flash_mma, cudaFuncAttributeMaxDynamicSharedMemorySize, FL_SMEM);

    const dim3 blk(256);
    const int mt = T_TOK / 128;  // 32

    // merged input conversions (all single fp16)
    {
        Cvt6P P;
        P.x[0]=X;     P.h[0]=X16;
        P.x[1]=wq_a;  P.h[1]=wqa16;
        P.x[2]=wq_b;  P.h[2]=wqb16;
        P.x[3]=wkv_a; P.h[3]=wkva16;
        P.x[4]=wkv_b; P.h[4]=wkvb16;
        P.x[5]=wo;    P.h[5]=wo16;
        int lens[6] = { T_TOK*HIDDEN/4, QLORA*HIDDEN/4, NHEADS*QHD*QLORA/4,
                        KVW*HIDDEN/4, NHEADS*256*KVLORA/4, HIDDEN*NHEADS*VHD/4 };
        P.off[0] = 0;
        for (int i = 0; i < 6; ++i) P.off[i+1] = P.off[i] + lens[i];
        cvt6_kernel<<<(P.off[6] + 255) / 256, 256>>>(P);
    }

    // fused a-projections -> fp32
    {
        GemmP p0 = { X16, wqa16,  qa,  nullptr, nullptr, QLORA, HIDDEN };
        GemmP p1 = { X16, wkva16, ckv, nullptr, nullptr, KVW,   HIDDEN };
        fp_gemm_dual<<<dim3(QLORA/128 + (KVW+127)/128, mt), blk, GEMM_SMEM>>>(p0, p1, QLORA/128);
    }

    // fused rmsnorms -> fp16
    {
        RmsP p0 = { qa, qln, qan16, QLORA, QLORA };
        RmsP p1 = { ckv, kvln, ckvn16, KVLORA, KVW };
        rmsnorm_dual<<<dim3(T_TOK, 2), 256>>>(p0, p1);
    }
    rope_k_kernel<<<T_TOK, 32>>>(ckv, pos, kpe16);

    // fused b-projections: q -> fp16 hi/lo ; kv -> fp16 single
    {
        GemmP p0 = { qan16,  wqb16,  nullptr, q16h, q16l,   NHEADS*QHD, QLORA };
        GemmP p1 = { ckvn16, wkvb16, nullptr, kv16, nullptr, NHEADS*256, KVLORA };
        fp_gemm_dual<<<dim3((NHEADS*QHD)/128 + (NHEADS*256)/128, mt), blk, GEMM_SMEM>>>(
            p0, p1, (NHEADS*QHD)/128);
    }

    rope_q_kernel<<<T_TOK * NHEADS, 32>>>(q16h, q16l, pos);

    flash_mma<<<dim3(S_LEN / 64, NHEADS, BATCH), dim3(128), FL_SMEM>>>(q16h, q16l, kv16, kpe16,
                                                                       ctx16);

    // output projection -> fp32 out
    {
        GemmP p0 = { ctx16, wo16, out, nullptr, nullptr, HIDDEN, NHEADS*VHD };
        fp_gemm_dual<<<dim3(HIDDEN/128, mt), blk, GEMM_SMEM>>>(p0, p0, HIDDEN/128);
    }
}

// round 15
// speedup vs baseline: 3.7721x; 1.0763x over previous
#include <cuda_runtime.h>
#include <cuda_fp16.h>
#include <math.h>
#include <stdint.h>

// ---------------- problem constants ----------------
#define S_LEN   2048
#define BATCH   2
#define T_TOK   (BATCH * S_LEN)
#define HIDDEN  2048
#define QLORA   1536
#define KVLORA  512
#define NHEADS  16
#define NOPE    128
#define ROPE_D  64
#define QHD     192
#define VHD     128
#define KVW     576

// ---------------- scratch ----------------
__device__ float g_qa [T_TOK * QLORA];
__device__ float g_ckv[T_TOK * KVW];

__device__ __half g_X16[T_TOK * HIDDEN];
__device__ __half g_wqa16[QLORA * HIDDEN];
__device__ __half g_wqb16[NHEADS*QHD*QLORA];
__device__ __half g_wkva16[KVW * HIDDEN];
__device__ __half g_wkvb16[NHEADS*256*KVLORA];
__device__ __half g_wo16[HIDDEN*NHEADS*VHD];
__device__ __half g_qan16[T_TOK * QLORA];
__device__ __half g_ckvn16[T_TOK * KVLORA];
__device__ __half g_q16[T_TOK * NHEADS * QHD];
__device__ __half g_kv16[T_TOK * NHEADS * 256];
__device__ __half g_kpe16[T_TOK * ROPE_D];
__device__ __half g_ctx16[T_TOK * NHEADS*VHD];

// ---------------- common helpers ----------------
__device__ __forceinline__ uint32_t smem_u32(const void* p) {
    uint32_t a;
    asm("{ .reg .u64 t; cvta.to.shared.u64 t, %1; cvt.u32.u64 %0, t; }" : "=r"(a) : "l"(p));
    return a;
}
__device__ __forceinline__ void ldm4(uint32_t* r, uint32_t addr) {
    asm volatile("ldmatrix.sync.aligned.m8n8.x4.shared.b16 {%0,%1,%2,%3}, [%4];"
                 : "=r"(r[0]), "=r"(r[1]), "=r"(r[2]), "=r"(r[3]) : "r"(addr));
}
__device__ __forceinline__ void ldm4t(uint32_t* r, uint32_t addr) {
    asm volatile("ldmatrix.sync.aligned.m8n8.x4.trans.shared.b16 {%0,%1,%2,%3}, [%4];"
                 : "=r"(r[0]), "=r"(r[1]), "=r"(r[2]), "=r"(r[3]) : "r"(addr));
}
__device__ __forceinline__ void mma16816h(float* d, const uint32_t* a, const uint32_t* b) {
    asm volatile("mma.sync.aligned.m16n8k16.row.col.f32.f16.f16.f32 "
                 "{%0,%1,%2,%3}, {%4,%5,%6,%7}, {%8,%9}, {%0,%1,%2,%3};"
                 : "+f"(d[0]), "+f"(d[1]), "+f"(d[2]), "+f"(d[3])
                 : "r"(a[0]), "r"(a[1]), "r"(a[2]), "r"(a[3]), "r"(b[0]), "r"(b[1]));
}
__device__ __forceinline__ void cpa16(uint32_t dst, const void* src, uint32_t sz) {
    asm volatile("cp.async.cg.shared.global [%0], [%1], 16, %2;"
                 :: "r"(dst), "l"(src), "r"(sz) : "memory");
}
__device__ __forceinline__ void split1h(float v, __half& h, __half& l) {
    h = __float2half_rn(v);
    l = __float2half_rn(v - __half2float(h));
}

// ---------------- merged convert fp32 -> fp16 single, 6 regions ----------------
struct Cvt6P {
    const float* x[6];
    __half* h[6];
    int off[7];
};
__global__ void cvt6_kernel(Cvt6P P) {
    int i = blockIdx.x * blockDim.x + threadIdx.x;
    if (i >= P.off[6]) return;
    int r = 0;
#pragma unroll
    for (int k = 1; k < 6; ++k) if (i >= P.off[k]) r = k;
    int j = i - P.off[r];
    float4 v = ((const float4*)P.x[r])[j];
    __half2 hp0 = __halves2half2(__float2half_rn(v.x), __float2half_rn(v.y));
    __half2 hp1 = __halves2half2(__float2half_rn(v.z), __float2half_rn(v.w));
    uint2 hh; hh.x = *(uint32_t*)&hp0; hh.y = *(uint32_t*)&hp1;
    ((uint2*)P.h[r])[j] = hh;
}

// ============================================================================
// fp16 GEMM: C = A * B^T, single operands. 128x128 CTA, 2 CTAs/SM.
// BK=32, 4-stage cp.async, one sync per chunk, 8 warps. (unchanged)
// ============================================================================
#define SMSTR 80
#define TILEB (128 * SMSTR)
#define STAGEB (2 * TILEB)
#define NSTAGE 4
#define GEMM_SMEM (NSTAGE * STAGEB)

struct GemmP {
    const __half *A, *B;
    float* C;
    __half *Hh;
    int N, K;
};

__global__ __launch_bounds__(256, 2) void fp_gemm_dual(GemmP P0, GemmP P1, int xsplit) {
    extern __shared__ char sm[];
    const bool first = ((int)blockIdx.x < xsplit);
    const GemmP p = first ? P0 : P1;
    const int n0 = (first ? blockIdx.x : (blockIdx.x - xsplit)) * 128;
    const int K = p.K, N = p.N;

    const int tid = threadIdx.x;
    const int wid = tid >> 5;
    const int lane = tid & 31;
    const int m0 = blockIdx.y * 128;
    const int nvalid = (N - n0 < 128) ? (N - n0) : 128;

    const uint32_t sbase = smem_u32(sm);
    const int wr = wid >> 2, wc = wid & 3;
    const uint32_t a_row = wr * 64 + (lane & 15);
    const uint32_t a_colb = (lane >> 4) * 16;
    const uint32_t b_row = wc * 32 + (lane & 7) + ((lane >> 4) << 3);
    const uint32_t b_colb = ((lane >> 3) & 1) * 16;

    float acc[4][4][4];
#pragma unroll
    for (int i = 0; i < 4; ++i)
#pragma unroll
        for (int j = 0; j < 4; ++j)
#pragma unroll
            for (int e = 0; e < 4; ++e) acc[i][j][e] = 0.f;

    const int nch = K >> 5;

    auto issue_chunk = [&](int c) {
        const int k0 = c << 5;
        const uint32_t stb = sbase + (c & (NSTAGE - 1)) * STAGEB;
#pragma unroll
        for (int i = 0; i < 4; ++i) {
            int u = tid + i * 256;
            int tile = u >> 9;
            int row = (u & 511) >> 2;
            int c16 = u & 3;
            uint32_t dst = stb + tile * TILEB + row * SMSTR + c16 * 16;
            const __half* src;
            uint32_t sz = 16;
            if (tile == 0) src = p.A + (size_t)(m0 + row) * K + k0 + c16 * 8;
            else {
                src = p.B + (size_t)(n0 + row) * K + k0 + c16 * 8;
                if (row >= nvalid) sz = 0;
            }
            cpa16(dst, src, sz);
        }
        asm volatile("cp.async.commit_group;" ::: "memory");
    };

    issue_chunk(0);
    if (nch > 1) issue_chunk(1); else asm volatile("cp.async.commit_group;" ::: "memory");
    if (nch > 2) issue_chunk(2); else asm volatile("cp.async.commit_group;" ::: "memory");

    for (int c = 0; c < nch; ++c) {
        asm volatile("cp.async.wait_group 2;" ::: "memory");
        __syncthreads();
        if (c + 3 < nch) issue_chunk(c + 3);
        else asm volatile("cp.async.commit_group;" ::: "memory");

        const uint32_t stb = sbase + (c & (NSTAGE - 1)) * STAGEB;
#pragma unroll
        for (int ks = 0; ks < 2; ++ks) {
            const uint32_t kb = ks * 32;
            uint32_t ah[4][4], bh[2][4];
#pragma unroll
            for (int i = 0; i < 4; ++i)
                ldm4(ah[i], stb + (a_row + i * 16) * SMSTR + a_colb + kb);
#pragma unroll
            for (int jp = 0; jp < 2; ++jp)
                ldm4(bh[jp], stb + TILEB + (b_row + jp * 16) * SMSTR + b_colb + kb);
#pragma unroll
            for (int i = 0; i < 4; ++i)
#pragma unroll
                for (int j = 0; j < 4; ++j)
                    mma16816h(acc[i][j], ah[i], &bh[j >> 1][(j & 1) * 2]);
        }
    }

    const int gid = lane >> 2, tig = lane & 3;
#pragma unroll
    for (int i = 0; i < 4; ++i) {
#pragma unroll
        for (int rr = 0; rr < 2; ++rr) {
            int row = m0 + wr * 64 + i * 16 + gid + rr * 8;
#pragma unroll
            for (int j = 0; j < 4; ++j) {
                int col = n0 + wc * 32 + j * 8 + tig * 2;
                if (col < N) {
                    float v0 = acc[i][j][rr * 2], v1 = acc[i][j][rr * 2 + 1];
                    if (p.C) *(float2*)(p.C + (size_t)row * N + col) = make_float2(v0, v1);
                    if (p.Hh) {
                        __half2 hp = __halves2half2(__float2half_rn(v0), __float2half_rn(v1));
                        *(uint32_t*)(p.Hh + (size_t)row * N + col) = *(uint32_t*)&hp;
                    }
                }
            }
        }
    }
}

// ---------------- dual RMSNorm -> fp16 single ----------------
struct RmsP {
    const float* x; const float* w;
    __half *y;
    int D, in_stride;
};
__global__ void rmsnorm_dual(RmsP P0, RmsP P1) {
    const RmsP p = (blockIdx.y == 0) ? P0 : P1;
    const int row = blockIdx.x;
    const float* xr = p.x + (size_t)row * p.in_stride;
    float ss = 0.f;
    for (int d = threadIdx.x; d < p.D; d += blockDim.x) { float v = xr[d]; ss += v * v; }
    __shared__ float red[32];
#pragma unroll
    for (int o = 16; o; o >>= 1) ss += __shfl_xor_sync(0xffffffffu, ss, o);
    if ((threadIdx.x & 31) == 0) red[threadIdx.x >> 5] = ss;
    __syncthreads();
    if (threadIdx.x < 32) {
        float v = (threadIdx.x < (blockDim.x >> 5)) ? red[threadIdx.x] : 0.f;
#pragma unroll
        for (int o = 16; o; o >>= 1) v += __shfl_xor_sync(0xffffffffu, v, o);
        if (threadIdx.x == 0) red[0] = v;
    }
    __syncthreads();
    float scale = rsqrtf(red[0] / (float)p.D + 1e-6f);
    for (int d = threadIdx.x; d < p.D; d += blockDim.x) {
        float v = p.w[d] * xr[d] * scale;
        p.y[(size_t)row * p.D + d] = __float2half_rn(v);
    }
}

// ---------------- YaRN ----------------
__device__ __forceinline__ void yarn_cs(int pos, int j, float& c, float& s) {
    float ex   = __expf(-(float)(2 * j) * (9.210340371976184f / 64.f));
    float fi   = ex * 0.025f;
    float ramp = ((float)j - 10.f) * (1.f / 13.f);
    ramp = fminf(fmaxf(ramp, 0.f), 1.f);
    float invf = fi * ramp + ex * (1.f - ramp);
    float ang  = (float)pos * invf;
    c = cosf(ang); s = sinf(ang);
}

__global__ void rope_k_kernel(const float* __restrict__ ckv, const int* __restrict__ pos_ids,
                              __half* __restrict__ kpe) {
    const int t = blockIdx.x;
    const int j = threadIdx.x;
    const int pos = pos_ids[t];
    const float* x = ckv + (size_t)t * KVW + KVLORA;
    float c, s; yarn_cs(pos, j, c, s);
    float x0 = x[2 * j], x1 = x[2 * j + 1];
    kpe[t * ROPE_D + j]      = __float2half_rn(x0 * c - x1 * s);
    kpe[t * ROPE_D + 32 + j] = __float2half_rn(x1 * c + x0 * s);
}

__global__ void rope_q_kernel(__half* __restrict__ q, const int* __restrict__ pos_ids) {
    const int t = blockIdx.x >> 4;
    const int h = blockIdx.x & 15;
    const int j = threadIdx.x;
    const int pos = pos_ids[t];
    __half* x = q + (size_t)t * (NHEADS * QHD) + h * QHD + NOPE;
    float c, s; yarn_cs(pos, j, c, s);
    float x0 = __half2float(x[2*j]);
    float x1 = __half2float(x[2*j+1]);
    float r0 = x0 * c - x1 * s, r1 = x1 * c + x0 * s;
    __syncwarp();
    x[j]      = __float2half_rn(r0);
    x[32 + j] = __float2half_rn(r1);
}

// ============================================================================
// Flash attention, fp16 HMMA. BM=64, BN=64, 4 warps, 2 CTAs/SM.
// Q single fp16 (1-term QK), P 2-term AV, P in registers.
// ============================================================================
#define FL_KSTR 400
#define FL_VSTR 272
#define FL_KVSTG (64 * FL_KSTR + 64 * FL_VSTR)    // 43008
#define FL_VOFF  (64 * FL_KSTR)
#define FL_QSTR 400
#define FL_SMEM (2 * FL_KVSTG)                    // 86016 per CTA

__global__ __launch_bounds__(128, 2) void flash_mma(
    const __half* __restrict__ q,
    const __half* __restrict__ kv,
    const __half* __restrict__ kpe,
    __half* __restrict__ ctx)
{
    extern __shared__ char sm[];
    const uint32_t sb = smem_u32(sm);
    const int qt = (int)gridDim.x - 1 - (int)blockIdx.x;   // heavy tiles first
    const int hh = blockIdx.y, b = blockIdx.z;
    const int tid = threadIdx.x, wid = tid >> 5, lane = tid & 31;
    const int gid = lane >> 2, tig = lane & 3;
    const int t0 = b * S_LEN;

    const uint32_t a_row = wid * 16 + (lane & 15);
    const uint32_t a_colb = (lane >> 4) * 16;
    const uint32_t k_roff = (lane & 7) + ((lane >> 4) << 3);
    const uint32_t k_colb = ((lane >> 3) & 1) * 16;
    const uint32_t v_koff = (lane & 7) + ((lane >> 3) & 1) * 8;
    const uint32_t v_noff = (lane >> 4) * 8;

    // ---- prologue: stage Q (64 x 192), pull fragments ----
    for (int idx = tid; idx < 64 * 24; idx += 128) {
        int r = idx / 24, u = idx % 24;
        size_t g = (size_t)(t0 + qt * 64 + r) * (NHEADS * QHD) + hh * QHD + u * 8;
        *(uint4*)(sm + r * FL_QSTR + u * 16) = *(const uint4*)(q + g);
    }
    __syncthreads();
    uint32_t qf[12][4];
#pragma unroll
    for (int ks = 0; ks < 12; ++ks)
        ldm4(qf[ks], sb + a_row * FL_QSTR + a_colb + ks * 32);
    __syncthreads();

    auto issue_kv = [&](int kt) {
        const uint32_t stb = sb + (kt & 1) * FL_KVSTG;
        for (int idx = tid; idx < 64 * 24; idx += 128) {
            int r = idx / 24, u = idx % 24;
            int t = t0 + kt * 64 + r;
            const __half* src;
            if (u < 16) src = kv + (size_t)t * (NHEADS * 256) + hh * 256 + u * 8;
            else        src = kpe + (size_t)t * ROPE_D + (u - 16) * 8;
            cpa16(stb + r * FL_KSTR + u * 16, src, 16);
        }
        for (int idx = tid; idx < 64 * 16; idx += 128) {
            int r = idx >> 4, u = idx & 15;
            size_t g = (size_t)(t0 + kt * 64 + r) * (NHEADS * 256) + hh * 256 + 128 + u * 8;
            cpa16(stb + FL_VOFF + r * FL_VSTR + u * 16, kv + g, 16);
        }
        asm volatile("cp.async.commit_group;" ::: "memory");
    };

    float m_i[2], l_i[2], O[16][4];
    m_i[0] = m_i[1] = -1e30f; l_i[0] = l_i[1] = 0.f;
#pragma unroll
    for (int nf = 0; nf < 16; ++nf)
#pragma unroll
        for (int e = 0; e < 4; ++e) O[nf][e] = 0.f;

    const float mm = 0.1f * logf(40.f) + 1.f;
    const float sc = mm * mm * rsqrtf(192.f);

    const int nkt = qt + 1;
    issue_kv(0);

    for (int kt = 0; kt < nkt; ++kt) {
        if (kt + 1 < nkt) {
            issue_kv(kt + 1);
            asm volatile("cp.async.wait_group 1;" ::: "memory");
        } else {
            asm volatile("cp.async.wait_group 0;" ::: "memory");
        }
        __syncthreads();
        const uint32_t stb = sb + (kt & 1) * FL_KVSTG;

        // ---- QK: S = Q * K ----
        float s[8][4];
#pragma unroll
        for (int nf = 0; nf < 8; ++nf)
#pragma unroll
            for (int e = 0; e < 4; ++e) s[nf][e] = 0.f;

#pragma unroll
        for (int ks = 0; ks < 12; ++ks) {
#pragma unroll
            for (int jb = 0; jb < 4; ++jb) {
                uint32_t bh4[4];
                uint32_t brow = jb * 16 + k_roff;
                ldm4(bh4, stb + brow * FL_KSTR + k_colb + ks * 32);
                mma16816h(s[2*jb],   qf[ks], &bh4[0]);
                mma16816h(s[2*jb+1], qf[ks], &bh4[2]);
            }
        }

        // ---- softmax ----
#pragma unroll
        for (int rr = 0; rr < 2; ++rr) {
            int grow = qt * 64 + wid * 16 + gid + rr * 8;
            float tmax = -1e30f;
#pragma unroll
            for (int nf = 0; nf < 8; ++nf) {
#pragma unroll
                for (int e = 0; e < 2; ++e) {
                    int gcol = kt * 64 + nf * 8 + tig * 2 + e;
                    float v = s[nf][rr * 2 + e] * sc;
                    if (gcol > grow) v = -1e30f;
                    s[nf][rr * 2 + e] = v;
                    tmax = fmaxf(tmax, v);
                }
            }
            tmax = fmaxf(tmax, __shfl_xor_sync(0xffffffffu, tmax, 1));
            tmax = fmaxf(tmax, __shfl_xor_sync(0xffffffffu, tmax, 2));
            float nm = fmaxf(m_i[rr], tmax);
            float fac = __expf(m_i[rr] - nm);
            float psum = 0.f;
#pragma unroll
            for (int nf = 0; nf < 8; ++nf) {
#pragma unroll
                for (int e = 0; e < 2; ++e) {
                    float pv = __expf(s[nf][rr * 2 + e] - nm);
                    s[nf][rr * 2 + e] = pv;
                    psum += pv;
                }
            }
            psum += __shfl_xor_sync(0xffffffffu, psum, 1);
            psum += __shfl_xor_sync(0xffffffffu, psum, 2);
            l_i[rr] = l_i[rr] * fac + psum;
            m_i[rr] = nm;
#pragma unroll
            for (int nf = 0; nf < 16; ++nf) {
                O[nf][rr * 2] *= fac;
                O[nf][rr * 2 + 1] *= fac;
            }
        }

        // ---- P -> A-operand fragments in registers (hi/lo) ----
        uint32_t aph[4][4], apl[4][4];
#pragma unroll
        for (int ks = 0; ks < 4; ++ks) {
#pragma unroll
            for (int q2 = 0; q2 < 2; ++q2) {
                int nf = 2 * ks + q2;
                __half h0,l0,h1,l1,h2,l2,h3,l3;
                split1h(s[nf][0], h0, l0); split1h(s[nf][1], h1, l1);
                split1h(s[nf][2], h2, l2); split1h(s[nf][3], h3, l3);
                __half2 ph01 = __halves2half2(h0, h1);
                __half2 ph23 = __halves2half2(h2, h3);
                __half2 pl01 = __halves2half2(l0, l1);
                __half2 pl23 = __halves2half2(l2, l3);
                aph[ks][2*q2]   = *(uint32_t*)&ph01;
                aph[ks][2*q2+1] = *(uint32_t*)&ph23;
                apl[ks][2*q2]   = *(uint32_t*)&pl01;
                apl[ks][2*q2+1] = *(uint32_t*)&pl23;
            }
        }

        // ---- AV: O += (Ph + Pl) * V ----
#pragma unroll
        for (int ks = 0; ks < 4; ++ks) {
            uint32_t vrow = ks * 16 + v_koff;
#pragma unroll
            for (int nb = 0; nb < 8; ++nb) {
                uint32_t bvh[4];
                uint32_t vcol = (nb * 16 + v_noff) * 2;
                ldm4t(bvh, stb + FL_VOFF + vrow * FL_VSTR + vcol);
                mma16816h(O[2*nb],   aph[ks], &bvh[0]);
                mma16816h(O[2*nb+1], aph[ks], &bvh[2]);
                mma16816h(O[2*nb],   apl[ks], &bvh[0]);
                mma16816h(O[2*nb+1], apl[ks], &bvh[2]);
            }
        }
        __syncthreads();   // WAR guard before overwrite of this stage
    }

#pragma unroll
    for (int rr = 0; rr < 2; ++rr) {
        float inv = 1.f / l_i[rr];
        int row = t0 + qt * 64 + wid * 16 + gid + rr * 8;
#pragma unroll
        for (int nf = 0; nf < 16; ++nf) {
            int col = nf * 8 + tig * 2;
            float v0 = O[nf][rr * 2] * inv, v1 = O[nf][rr * 2 + 1] * inv;
            __half2 hp = __halves2half2(__float2half_rn(v0), __float2half_rn(v1));
            size_t g = (size_t)row * (NHEADS * VHD) + hh * VHD + col;
            *(uint32_t*)(ctx + g) = *(uint32_t*)&hp;
        }
    }
}

// ---------------- launch ----------------
extern "C" void kernel_launch(void* const* d_in, const int* in_sizes, int n_in,
                              void* d_out, int out_size) {
    (void)in_sizes; (void)n_in; (void)out_size;
    const float* X     = (const float*)d_in[0];
    const int*   pos   = (const int*)  d_in[1];
    const float* wq_a  = (const float*)d_in[2];
    const float* qln   = (const float*)d_in[3];
    const float* wq_b  = (const float*)d_in[4];
    const float* wkv_a = (const float*)d_in[5];
    const float* kvln  = (const float*)d_in[6];
    const float* wkv_b = (const float*)d_in[7];
    const float* wo    = (const float*)d_in[8];
    float* out = (float*)d_out;

    float *qa, *ckv;
    __half *X16,*wqa16,*wqb16,*wkva16,*wkvb16,*wo16;
    __half *qan16,*ckvn16,*q16,*kv16,*kpe16,*ctx16;
    cudaGetSymbolAddress((void**)&qa, g_qa);
    cudaGetSymbolAddress((void**)&ckv, g_ckv);
    cudaGetSymbolAddress((void**)&X16, g_X16);
    cudaGetSymbolAddress((void**)&wqa16, g_wqa16);
    cudaGetSymbolAddress((void**)&wqb16, g_wqb16);
    cudaGetSymbolAddress((void**)&wkva16, g_wkva16);
    cudaGetSymbolAddress((void**)&wkvb16, g_wkvb16);
    cudaGetSymbolAddress((void**)&wo16, g_wo16);
    cudaGetSymbolAddress((void**)&qan16, g_qan16);
    cudaGetSymbolAddress((void**)&ckvn16, g_ckvn16);
    cudaGetSymbolAddress((void**)&q16, g_q16);
    cudaGetSymbolAddress((void**)&kv16, g_kv16);
    cudaGetSymbolAddress((void**)&kpe16, g_kpe16);
    cudaGetSymbolAddress((void**)&ctx16, g_ctx16);

    cudaFuncSetAttribute(fp_gemm_dual, cudaFuncAttributeMaxDynamicSharedMemorySize, GEMM_SMEM);
    cudaFuncSetAttribute(flash_mma, cudaFuncAttributeMaxDynamicSharedMemorySize, FL_SMEM);

    const dim3 blk(256);
    const int mt = T_TOK / 128;  // 32

    // merged input conversions (all single fp16)
    {
        Cvt6P P;
        P.x[0]=X;     P.h[0]=X16;
        P.x[1]=wq_a;  P.h[1]=wqa16;
        P.x[2]=wq_b;  P.h[2]=wqb16;
        P.x[3]=wkv_a; P.h[3]=wkva16;
        P.x[4]=wkv_b; P.h[4]=wkvb16;
        P.x[5]=wo;    P.h[5]=wo16;
        int lens[6] = { T_TOK*HIDDEN/4, QLORA*HIDDEN/4, NHEADS*QHD*QLORA/4,
                        KVW*HIDDEN/4, NHEADS*256*KVLORA/4, HIDDEN*NHEADS*VHD/4 };
        P.off[0] = 0;
        for (int i = 0; i < 6; ++i) P.off[i+1] = P.off[i] + lens[i];
        cvt6_kernel<<<(P.off[6] + 255) / 256, 256>>>(P);
    }

    // fused a-projections -> fp32
    {
        GemmP p0 = { X16, wqa16,  qa,  nullptr, QLORA, HIDDEN };
        GemmP p1 = { X16, wkva16, ckv, nullptr, KVW,   HIDDEN };
        fp_gemm_dual<<<dim3(QLORA/128 + (KVW+127)/128, mt), blk, GEMM_SMEM>>>(p0, p1, QLORA/128);
    }

    // fused rmsnorms -> fp16
    {
        RmsP p0 = { qa, qln, qan16, QLORA, QLORA };
        RmsP p1 = { ckv, kvln, ckvn16, KVLORA, KVW };
        rmsnorm_dual<<<dim3(T_TOK, 2), 256>>>(p0, p1);
    }
    rope_k_kernel<<<T_TOK, 32>>>(ckv, pos, kpe16);

    // fused b-projections: q -> fp16 single ; kv -> fp16 single
    {
        GemmP p0 = { qan16,  wqb16,  nullptr, q16,  NHEADS*QHD, QLORA };
        GemmP p1 = { ckvn16, wkvb16, nullptr, kv16, NHEADS*256, KVLORA };
        fp_gemm_dual<<<dim3((NHEADS*QHD)/128 + (NHEADS*256)/128, mt), blk, GEMM_SMEM>>>(
            p0, p1, (NHEADS*QHD)/128);
    }

    rope_q_kernel<<<T_TOK * NHEADS, 32>>>(q16, pos);

    flash_mma<<<dim3(S_LEN / 64, NHEADS, BATCH), dim3(128), FL_SMEM>>>(q16, kv16, kpe16, ctx16);

    // output projection -> fp32 out
    {
        GemmP p0 = { ctx16, wo16, out, nullptr, HIDDEN, NHEADS*VHD };
        fp_gemm_dual<<<dim3(HIDDEN/128, mt), blk, GEMM_SMEM>>>(p0, p0, HIDDEN/128);
    }
}

// round 16
// speedup vs baseline: 4.1096x; 1.0895x over previous
#include <cuda_runtime.h>
#include <cuda_fp16.h>
#include <math.h>
#include <stdint.h>

// ---------------- problem constants ----------------
#define S_LEN   2048
#define BATCH   2
#define T_TOK   (BATCH * S_LEN)
#define HIDDEN  2048
#define QLORA   1536
#define KVLORA  512
#define NHEADS  16
#define NOPE    128
#define ROPE_D  64
#define QHD     192
#define VHD     128
#define KVW     576

// ---------------- scratch ----------------
__device__ float g_qa [T_TOK * QLORA];
__device__ float g_ckv[T_TOK * KVW];

__device__ __half g_X16[T_TOK * HIDDEN];
__device__ __half g_wqa16[QLORA * HIDDEN];
__device__ __half g_wqb16[NHEADS*QHD*QLORA];
__device__ __half g_wkva16[KVW * HIDDEN];
__device__ __half g_wkvb16[NHEADS*256*KVLORA];
__device__ __half g_wo16[HIDDEN*NHEADS*VHD];
__device__ __half g_qan16[T_TOK * QLORA];
__device__ __half g_ckvn16[T_TOK * KVLORA];
__device__ __half g_q16[T_TOK * NHEADS * QHD];
__device__ __half g_kv16[T_TOK * NHEADS * 256];
__device__ __half g_kpe16[T_TOK * ROPE_D];
__device__ __half g_ctx16[T_TOK * NHEADS*VHD];

// ---------------- common helpers ----------------
__device__ __forceinline__ uint32_t smem_u32(const void* p) {
    uint32_t a;
    asm("{ .reg .u64 t; cvta.to.shared.u64 t, %1; cvt.u32.u64 %0, t; }" : "=r"(a) : "l"(p));
    return a;
}
__device__ __forceinline__ void ldm4(uint32_t* r, uint32_t addr) {
    asm volatile("ldmatrix.sync.aligned.m8n8.x4.shared.b16 {%0,%1,%2,%3}, [%4];"
                 : "=r"(r[0]), "=r"(r[1]), "=r"(r[2]), "=r"(r[3]) : "r"(addr));
}
__device__ __forceinline__ void ldm4t(uint32_t* r, uint32_t addr) {
    asm volatile("ldmatrix.sync.aligned.m8n8.x4.trans.shared.b16 {%0,%1,%2,%3}, [%4];"
                 : "=r"(r[0]), "=r"(r[1]), "=r"(r[2]), "=r"(r[3]) : "r"(addr));
}
__device__ __forceinline__ void mma16816h(float* d, const uint32_t* a, const uint32_t* b) {
    asm volatile("mma.sync.aligned.m16n8k16.row.col.f32.f16.f16.f32 "
                 "{%0,%1,%2,%3}, {%4,%5,%6,%7}, {%8,%9}, {%0,%1,%2,%3};"
                 : "+f"(d[0]), "+f"(d[1]), "+f"(d[2]), "+f"(d[3])
                 : "r"(a[0]), "r"(a[1]), "r"(a[2]), "r"(a[3]), "r"(b[0]), "r"(b[1]));
}
__device__ __forceinline__ void cpa16(uint32_t dst, const void* src, uint32_t sz) {
    asm volatile("cp.async.cg.shared.global [%0], [%1], 16, %2;"
                 :: "r"(dst), "l"(src), "r"(sz) : "memory");
}
__device__ __forceinline__ void split1h(float v, __half& h, __half& l) {
    h = __float2half_rn(v);
    l = __float2half_rn(v - __half2float(h));
}

// ---------------- merged convert fp32 -> fp16 single, 6 regions ----------------
struct Cvt6P {
    const float* x[6];
    __half* h[6];
    int off[7];
};
__global__ void cvt6_kernel(Cvt6P P) {
    int i = blockIdx.x * blockDim.x + threadIdx.x;
    if (i >= P.off[6]) return;
    int r = 0;
#pragma unroll
    for (int k = 1; k < 6; ++k) if (i >= P.off[k]) r = k;
    int j = i - P.off[r];
    float4 v = ((const float4*)P.x[r])[j];
    __half2 hp0 = __halves2half2(__float2half_rn(v.x), __float2half_rn(v.y));
    __half2 hp1 = __halves2half2(__float2half_rn(v.z), __float2half_rn(v.w));
    uint2 hh; hh.x = *(uint32_t*)&hp0; hh.y = *(uint32_t*)&hp1;
    ((uint2*)P.h[r])[j] = hh;
}

// ============================================================================
// fp16 GEMM: C = A * B^T, single operands. 128x128 CTA tile, 128 threads
// (4 warps, 64x64 warp tile), 2 CTAs/SM. BK=32, 4-stage cp.async.
// ============================================================================
#define SMSTR 80
#define TILEB (128 * SMSTR)
#define STAGEB (2 * TILEB)
#define NSTAGE 4
#define GEMM_SMEM (NSTAGE * STAGEB)

struct GemmP {
    const __half *A, *B;
    float* C;
    __half *Hh;
    int N, K;
};

__global__ __launch_bounds__(128, 2) void fp_gemm_dual(GemmP P0, GemmP P1, int xsplit) {
    extern __shared__ char sm[];
    const bool first = ((int)blockIdx.x < xsplit);
    const GemmP p = first ? P0 : P1;
    const int n0 = (first ? blockIdx.x : (blockIdx.x - xsplit)) * 128;
    const int K = p.K, N = p.N;

    const int tid = threadIdx.x;
    const int wid = tid >> 5;
    const int lane = tid & 31;
    const int m0 = blockIdx.y * 128;
    const int nvalid = (N - n0 < 128) ? (N - n0) : 128;

    const uint32_t sbase = smem_u32(sm);
    const int wr = wid >> 1, wc = wid & 1;               // 2x2 warps, 64x64 each
    const uint32_t a_row = wr * 64 + (lane & 15);
    const uint32_t a_colb = (lane >> 4) * 16;
    const uint32_t b_row = wc * 64 + (lane & 7) + ((lane >> 4) << 3);
    const uint32_t b_colb = ((lane >> 3) & 1) * 16;

    float acc[4][8][4];
#pragma unroll
    for (int i = 0; i < 4; ++i)
#pragma unroll
        for (int j = 0; j < 8; ++j)
#pragma unroll
            for (int e = 0; e < 4; ++e) acc[i][j][e] = 0.f;

    const int nch = K >> 5;

    // copy: 1024 x 16B units per chunk, 8 per thread
    auto issue_chunk = [&](int c) {
        const int k0 = c << 5;
        const uint32_t stb = sbase + (c & (NSTAGE - 1)) * STAGEB;
#pragma unroll
        for (int i = 0; i < 8; ++i) {
            int u = tid + i * 128;
            int tile = u >> 9;              // 0=A 1=B
            int row = (u & 511) >> 2;
            int c16 = u & 3;
            uint32_t dst = stb + tile * TILEB + row * SMSTR + c16 * 16;
            const __half* src;
            uint32_t sz = 16;
            if (tile == 0) src = p.A + (size_t)(m0 + row) * K + k0 + c16 * 8;
            else {
                src = p.B + (size_t)(n0 + row) * K + k0 + c16 * 8;
                if (row >= nvalid) sz = 0;
            }
            cpa16(dst, src, sz);
        }
        asm volatile("cp.async.commit_group;" ::: "memory");
    };

    issue_chunk(0);
    if (nch > 1) issue_chunk(1); else asm volatile("cp.async.commit_group;" ::: "memory");
    if (nch > 2) issue_chunk(2); else asm volatile("cp.async.commit_group;" ::: "memory");

    for (int c = 0; c < nch; ++c) {
        asm volatile("cp.async.wait_group 2;" ::: "memory");
        __syncthreads();
        if (c + 3 < nch) issue_chunk(c + 3);
        else asm volatile("cp.async.commit_group;" ::: "memory");

        const uint32_t stb = sbase + (c & (NSTAGE - 1)) * STAGEB;
#pragma unroll
        for (int ks = 0; ks < 2; ++ks) {
            const uint32_t kb = ks * 32;
            uint32_t ah[4][4], bh[4][4];
#pragma unroll
            for (int i = 0; i < 4; ++i)
                ldm4(ah[i], stb + (a_row + i * 16) * SMSTR + a_colb + kb);
#pragma unroll
            for (int jp = 0; jp < 4; ++jp)
                ldm4(bh[jp], stb + TILEB + (b_row + jp * 16) * SMSTR + b_colb + kb);
#pragma unroll
            for (int i = 0; i < 4; ++i)
#pragma unroll
                for (int j = 0; j < 8; ++j)
                    mma16816h(acc[i][j], ah[i], &bh[j >> 1][(j & 1) * 2]);
        }
    }

    const int gid = lane >> 2, tig = lane & 3;
#pragma unroll
    for (int i = 0; i < 4; ++i) {
#pragma unroll
        for (int rr = 0; rr < 2; ++rr) {
            int row = m0 + wr * 64 + i * 16 + gid + rr * 8;
#pragma unroll
            for (int j = 0; j < 8; ++j) {
                int col = n0 + wc * 64 + j * 8 + tig * 2;
                if (col < N) {
                    float v0 = acc[i][j][rr * 2], v1 = acc[i][j][rr * 2 + 1];
                    if (p.C) *(float2*)(p.C + (size_t)row * N + col) = make_float2(v0, v1);
                    if (p.Hh) {
                        __half2 hp = __halves2half2(__float2half_rn(v0), __float2half_rn(v1));
                        *(uint32_t*)(p.Hh + (size_t)row * N + col) = *(uint32_t*)&hp;
                    }
                }
            }
        }
    }
}

// ---------------- dual RMSNorm -> fp16 single ----------------
struct RmsP {
    const float* x; const float* w;
    __half *y;
    int D, in_stride;
};
__global__ void rmsnorm_dual(RmsP P0, RmsP P1) {
    const RmsP p = (blockIdx.y == 0) ? P0 : P1;
    const int row = blockIdx.x;
    const float* xr = p.x + (size_t)row * p.in_stride;
    float ss = 0.f;
    for (int d = threadIdx.x; d < p.D; d += blockDim.x) { float v = xr[d]; ss += v * v; }
    __shared__ float red[32];
#pragma unroll
    for (int o = 16; o; o >>= 1) ss += __shfl_xor_sync(0xffffffffu, ss, o);
    if ((threadIdx.x & 31) == 0) red[threadIdx.x >> 5] = ss;
    __syncthreads();
    if (threadIdx.x < 32) {
        float v = (threadIdx.x < (blockDim.x >> 5)) ? red[threadIdx.x] : 0.f;
#pragma unroll
        for (int o = 16; o; o >>= 1) v += __shfl_xor_sync(0xffffffffu, v, o);
        if (threadIdx.x == 0) red[0] = v;
    }
    __syncthreads();
    float scale = rsqrtf(red[0] / (float)p.D + 1e-6f);
    for (int d = threadIdx.x; d < p.D; d += blockDim.x) {
        float v = p.w[d] * xr[d] * scale;
        p.y[(size_t)row * p.D + d] = __float2half_rn(v);
    }
}

// ---------------- YaRN ----------------
__device__ __forceinline__ void yarn_cs(int pos, int j, float& c, float& s) {
    float ex   = __expf(-(float)(2 * j) * (9.210340371976184f / 64.f));
    float fi   = ex * 0.025f;
    float ramp = ((float)j - 10.f) * (1.f / 13.f);
    ramp = fminf(fmaxf(ramp, 0.f), 1.f);
    float invf = fi * ramp + ex * (1.f - ramp);
    float ang  = (float)pos * invf;
    c = cosf(ang); s = sinf(ang);
}

__global__ void rope_k_kernel(const float* __restrict__ ckv, const int* __restrict__ pos_ids,
                              __half* __restrict__ kpe) {
    const int t = blockIdx.x;
    const int j = threadIdx.x;
    const int pos = pos_ids[t];
    const float* x = ckv + (size_t)t * KVW + KVLORA;
    float c, s; yarn_cs(pos, j, c, s);
    float x0 = x[2 * j], x1 = x[2 * j + 1];
    kpe[t * ROPE_D + j]      = __float2half_rn(x0 * c - x1 * s);
    kpe[t * ROPE_D + 32 + j] = __float2half_rn(x1 * c + x0 * s);
}

__global__ void rope_q_kernel(__half* __restrict__ q, const int* __restrict__ pos_ids) {
    const int t = blockIdx.x >> 4;
    const int h = blockIdx.x & 15;
    const int j = threadIdx.x;
    const int pos = pos_ids[t];
    __half* x = q + (size_t)t * (NHEADS * QHD) + h * QHD + NOPE;
    float c, s; yarn_cs(pos, j, c, s);
    float x0 = __half2float(x[2*j]);
    float x1 = __half2float(x[2*j+1]);
    float r0 = x0 * c - x1 * s, r1 = x1 * c + x0 * s;
    __syncwarp();
    x[j]      = __float2half_rn(r0);
    x[32 + j] = __float2half_rn(r1);
}

// ============================================================================
// Flash attention, fp16 HMMA. BM=64, BN=64, 4 warps, 2 CTAs/SM. (R15)
// ============================================================================
#define FL_KSTR 400
#define FL_VSTR 272
#define FL_KVSTG (64 * FL_KSTR + 64 * FL_VSTR)
#define FL_VOFF  (64 * FL_KSTR)
#define FL_QSTR 400
#define FL_SMEM (2 * FL_KVSTG)

__global__ __launch_bounds__(128, 2) void flash_mma(
    const __half* __restrict__ q,
    const __half* __restrict__ kv,
    const __half* __restrict__ kpe,
    __half* __restrict__ ctx)
{
    extern __shared__ char sm[];
    const uint32_t sb = smem_u32(sm);
    const int qt = (int)gridDim.x - 1 - (int)blockIdx.x;
    const int hh = blockIdx.y, b = blockIdx.z;
    const int tid = threadIdx.x, wid = tid >> 5, lane = tid & 31;
    const int gid = lane >> 2, tig = lane & 3;
    const int t0 = b * S_LEN;

    const uint32_t a_row = wid * 16 + (lane & 15);
    const uint32_t a_colb = (lane >> 4) * 16;
    const uint32_t k_roff = (lane & 7) + ((lane >> 4) << 3);
    const uint32_t k_colb = ((lane >> 3) & 1) * 16;
    const uint32_t v_koff = (lane & 7) + ((lane >> 3) & 1) * 8;
    const uint32_t v_noff = (lane >> 4) * 8;

    for (int idx = tid; idx < 64 * 24; idx += 128) {
        int r = idx / 24, u = idx % 24;
        size_t g = (size_t)(t0 + qt * 64 + r) * (NHEADS * QHD) + hh * QHD + u * 8;
        *(uint4*)(sm + r * FL_QSTR + u * 16) = *(const uint4*)(q + g);
    }
    __syncthreads();
    uint32_t qf[12][4];
#pragma unroll
    for (int ks = 0; ks < 12; ++ks)
        ldm4(qf[ks], sb + a_row * FL_QSTR + a_colb + ks * 32);
    __syncthreads();

    auto issue_kv = [&](int kt) {
        const uint32_t stb = sb + (kt & 1) * FL_KVSTG;
        for (int idx = tid; idx < 64 * 24; idx += 128) {
            int r = idx / 24, u = idx % 24;
            int t = t0 + kt * 64 + r;
            const __half* src;
            if (u < 16) src = kv + (size_t)t * (NHEADS * 256) + hh * 256 + u * 8;
            else        src = kpe + (size_t)t * ROPE_D + (u - 16) * 8;
            cpa16(stb + r * FL_KSTR + u * 16, src, 16);
        }
        for (int idx = tid; idx < 64 * 16; idx += 128) {
            int r = idx >> 4, u = idx & 15;
            size_t g = (size_t)(t0 + kt * 64 + r) * (NHEADS * 256) + hh * 256 + 128 + u * 8;
            cpa16(stb + FL_VOFF + r * FL_VSTR + u * 16, kv + g, 16);
        }
        asm volatile("cp.async.commit_group;" ::: "memory");
    };

    float m_i[2], l_i[2], O[16][4];
    m_i[0] = m_i[1] = -1e30f; l_i[0] = l_i[1] = 0.f;
#pragma unroll
    for (int nf = 0; nf < 16; ++nf)
#pragma unroll
        for (int e = 0; e < 4; ++e) O[nf][e] = 0.f;

    const float mm = 0.1f * logf(40.f) + 1.f;
    const float sc = mm * mm * rsqrtf(192.f);

    const int nkt = qt + 1;
    issue_kv(0);

    for (int kt = 0; kt < nkt; ++kt) {
        if (kt + 1 < nkt) {
            issue_kv(kt + 1);
            asm volatile("cp.async.wait_group 1;" ::: "memory");
        } else {
            asm volatile("cp.async.wait_group 0;" ::: "memory");
        }
        __syncthreads();
        const uint32_t stb = sb + (kt & 1) * FL_KVSTG;

        float s[8][4];
#pragma unroll
        for (int nf = 0; nf < 8; ++nf)
#pragma unroll
            for (int e = 0; e < 4; ++e) s[nf][e] = 0.f;

#pragma unroll
        for (int ks = 0; ks < 12; ++ks) {
#pragma unroll
            for (int jb = 0; jb < 4; ++jb) {
                uint32_t bh4[4];
                uint32_t brow = jb * 16 + k_roff;
                ldm4(bh4, stb + brow * FL_KSTR + k_colb + ks * 32);
                mma16816h(s[2*jb],   qf[ks], &bh4[0]);
                mma16816h(s[2*jb+1], qf[ks], &bh4[2]);
            }
        }

#pragma unroll
        for (int rr = 0; rr < 2; ++rr) {
            int grow = qt * 64 + wid * 16 + gid + rr * 8;
            float tmax = -1e30f;
#pragma unroll
            for (int nf = 0; nf < 8; ++nf) {
#pragma unroll
                for (int e = 0; e < 2; ++e) {
                    int gcol = kt * 64 + nf * 8 + tig * 2 + e;
                    float v = s[nf][rr * 2 + e] * sc;
                    if (gcol > grow) v = -1e30f;
                    s[nf][rr * 2 + e] = v;
                    tmax = fmaxf(tmax, v);
                }
            }
            tmax = fmaxf(tmax, __shfl_xor_sync(0xffffffffu, tmax, 1));
            tmax = fmaxf(tmax, __shfl_xor_sync(0xffffffffu, tmax, 2));
            float nm = fmaxf(m_i[rr], tmax);
            float fac = __expf(m_i[rr] - nm);
            float psum = 0.f;
#pragma unroll
            for (int nf = 0; nf < 8; ++nf) {
#pragma unroll
                for (int e = 0; e < 2; ++e) {
                    float pv = __expf(s[nf][rr * 2 + e] - nm);
                    s[nf][rr * 2 + e] = pv;
                    psum += pv;
                }
            }
            psum += __shfl_xor_sync(0xffffffffu, psum, 1);
            psum += __shfl_xor_sync(0xffffffffu, psum, 2);
            l_i[rr] = l_i[rr] * fac + psum;
            m_i[rr] = nm;
#pragma unroll
            for (int nf = 0; nf < 16; ++nf) {
                O[nf][rr * 2] *= fac;
                O[nf][rr * 2 + 1] *= fac;
            }
        }

        uint32_t aph[4][4], apl[4][4];
#pragma unroll
        for (int ks = 0; ks < 4; ++ks) {
#pragma unroll
            for (int q2 = 0; q2 < 2; ++q2) {
                int nf = 2 * ks + q2;
                __half h0,l0,h1,l1,h2,l2,h3,l3;
                split1h(s[nf][0], h0, l0); split1h(s[nf][1], h1, l1);
                split1h(s[nf][2], h2, l2); split1h(s[nf][3], h3, l3);
                __half2 ph01 = __halves2half2(h0, h1);
                __half2 ph23 = __halves2half2(h2, h3);
                __half2 pl01 = __halves2half2(l0, l1);
                __half2 pl23 = __halves2half2(l2, l3);
                aph[ks][2*q2]   = *(uint32_t*)&ph01;
                aph[ks][2*q2+1] = *(uint32_t*)&ph23;
                apl[ks][2*q2]   = *(uint32_t*)&pl01;
                apl[ks][2*q2+1] = *(uint32_t*)&pl23;
            }
        }

#pragma unroll
        for (int ks = 0; ks < 4; ++ks) {
            uint32_t vrow = ks * 16 + v_koff;
#pragma unroll
            for (int nb = 0; nb < 8; ++nb) {
                uint32_t bvh[4];
                uint32_t vcol = (nb * 16 + v_noff) * 2;
                ldm4t(bvh, stb + FL_VOFF + vrow * FL_VSTR + vcol);
                mma16816h(O[2*nb],   aph[ks], &bvh[0]);
                mma16816h(O[2*nb+1], aph[ks], &bvh[2]);
                mma16816h(O[2*nb],   apl[ks], &bvh[0]);
                mma16816h(O[2*nb+1], apl[ks], &bvh[2]);
            }
        }
        __syncthreads();
    }

#pragma unroll
    for (int rr = 0; rr < 2; ++rr) {
        float inv = 1.f / l_i[rr];
        int row = t0 + qt * 64 + wid * 16 + gid + rr * 8;
#pragma unroll
        for (int nf = 0; nf < 16; ++nf) {
            int col = nf * 8 + tig * 2;
            float v0 = O[nf][rr * 2] * inv, v1 = O[nf][rr * 2 + 1] * inv;
            __half2 hp = __halves2half2(__float2half_rn(v0), __float2half_rn(v1));
            size_t g = (size_t)row * (NHEADS * VHD) + hh * VHD + col;
            *(uint32_t*)(ctx + g) = *(uint32_t*)&hp;
        }
    }
}

// ---------------- launch ----------------
extern "C" void kernel_launch(void* const* d_in, const int* in_sizes, int n_in,
                              void* d_out, int out_size) {
    (void)in_sizes; (void)n_in; (void)out_size;
    const float* X     = (const float*)d_in[0];
    const int*   pos   = (const int*)  d_in[1];
    const float* wq_a  = (const float*)d_in[2];
    const float* qln   = (const float*)d_in[3];
    const float* wq_b  = (const float*)d_in[4];
    const float* wkv_a = (const float*)d_in[5];
    const float* kvln  = (const float*)d_in[6];
    const float* wkv_b = (const float*)d_in[7];
    const float* wo    = (const float*)d_in[8];
    float* out = (float*)d_out;

    float *qa, *ckv;
    __half *X16,*wqa16,*wqb16,*wkva16,*wkvb16,*wo16;
    __half *qan16,*ckvn16,*q16,*kv16,*kpe16,*ctx16;
    cudaGetSymbolAddress((void**)&qa, g_qa);
    cudaGetSymbolAddress((void**)&ckv, g_ckv);
    cudaGetSymbolAddress((void**)&X16, g_X16);
    cudaGetSymbolAddress((void**)&wqa16, g_wqa16);
    cudaGetSymbolAddress((void**)&wqb16, g_wqb16);
    cudaGetSymbolAddress((void**)&wkva16, g_wkva16);
    cudaGetSymbolAddress((void**)&wkvb16, g_wkvb16);
    cudaGetSymbolAddress((void**)&wo16, g_wo16);
    cudaGetSymbolAddress((void**)&qan16, g_qan16);
    cudaGetSymbolAddress((void**)&ckvn16, g_ckvn16);
    cudaGetSymbolAddress((void**)&q16, g_q16);
    cudaGetSymbolAddress((void**)&kv16, g_kv16);
    cudaGetSymbolAddress((void**)&kpe16, g_kpe16);
    cudaGetSymbolAddress((void**)&ctx16, g_ctx16);

    cudaFuncSetAttribute(fp_gemm_dual, cudaFuncAttributeMaxDynamicSharedMemorySize, GEMM_SMEM);
    cudaFuncSetAttribute(flash_mma, cudaFuncAttributeMaxDynamicSharedMemorySize, FL_SMEM);

    const dim3 blk(128);
    const int mt = T_TOK / 128;  // 32

    // merged input conversions (all single fp16)
    {
        Cvt6P P;
        P.x[0]=X;     P.h[0]=X16;
        P.x[1]=wq_a;  P.h[1]=wqa16;
        P.x[2]=wq_b;  P.h[2]=wqb16;
        P.x[3]=wkv_a; P.h[3]=wkva16;
        P.x[4]=wkv_b; P.h[4]=wkvb16;
        P.x[5]=wo;    P.h[5]=wo16;
        int lens[6] = { T_TOK*HIDDEN/4, QLORA*HIDDEN/4, NHEADS*QHD*QLORA/4,
                        KVW*HIDDEN/4, NHEADS*256*KVLORA/4, HIDDEN*NHEADS*VHD/4 };
        P.off[0] = 0;
        for (int i = 0; i < 6; ++i) P.off[i+1] = P.off[i] + lens[i];
        cvt6_kernel<<<(P.off[6] + 255) / 256, 256>>>(P);
    }

    // fused a-projections -> fp32
    {
        GemmP p0 = { X16, wqa16,  qa,  nullptr, QLORA, HIDDEN };
        GemmP p1 = { X16, wkva16, ckv, nullptr, KVW,   HIDDEN };
        fp_gemm_dual<<<dim3(QLORA/128 + (KVW+127)/128, mt), blk, GEMM_SMEM>>>(p0, p1, QLORA/128);
    }

    // fused rmsnorms -> fp16
    {
        RmsP p0 = { qa, qln, qan16, QLORA, QLORA };
        RmsP p1 = { ckv, kvln, ckvn16, KVLORA, KVW };
        rmsnorm_dual<<<dim3(T_TOK, 2), 256>>>(p0, p1);
    }
    rope_k_kernel<<<T_TOK, 32>>>(ckv, pos, kpe16);

    // fused b-projections: q -> fp16 single ; kv -> fp16 single
    {
        GemmP p0 = { qan16,  wqb16,  nullptr, q16,  NHEADS*QHD, QLORA };
        GemmP p1 = { ckvn16, wkvb16, nullptr, kv16, NHEADS*256, KVLORA };
        fp_gemm_dual<<<dim3((NHEADS*QHD)/128 + (NHEADS*256)/128, mt), blk, GEMM_SMEM>>>(
            p0, p1, (NHEADS*QHD)/128);
    }

    rope_q_kernel<<<T_TOK * NHEADS, 32>>>(q16, pos);

    flash_mma<<<dim3(S_LEN / 64, NHEADS, BATCH), dim3(128), FL_SMEM>>>(q16, kv16, kpe16, ctx16);

    // output projection -> fp32 out
    {
        GemmP p0 = { ctx16, wo16, out, nullptr, HIDDEN, NHEADS*VHD };
        fp_gemm_dual<<<dim3(HIDDEN/128, mt), blk, GEMM_SMEM>>>(p0, p0, HIDDEN/128);
    }
}